// round 1
// baseline (speedup 1.0000x reference)
#include <cuda_runtime.h>
#include <math.h>

#define Bn      64
#define Cn      256
#define Ln      4096
#define HEADSn  8
#define Qn      16
#define Dn      32
#define NHQ     128          // HEADS*Q
#define FHn     512
#define NT1     32           // K1: L / 128
#define LT1     128
#define NSPLIT  8
#define LSP     512          // L per split
#define KT      32           // K3 l-tile

// ---------------- scratch (device globals: no allocs allowed) ----------------
__device__ float  g_logits[(size_t)Bn*NHQ*Ln];            // 134 MB
__device__ float2 g_stats [Bn*Ln];                         // mean,rstd per (b,l)
__device__ float2 g_part  [Bn*NT1*NHQ];                    // per-tile (max, sumexp)
__device__ float2 g_ms    [Bn*NHQ];                        // (max, 1/sum)
__device__ float  g_Ppart [(size_t)NSPLIT*Bn*NHQ*Cn];      // 67 MB partial P
__device__ float  g_A     [Bn*NHQ*Dn];                     // Aflat [B,4096]

// ---------------- fast exp (no MUFU; pure FMA/ALU) ----------------
// x <= 0 always (post max-subtraction). exp(x) = 2^(x*log2e), split int/frac.
__device__ __forceinline__ float fexp(float x) {
    float y = x * 1.4426950408889634f;
    y = fmaxf(y, -120.0f);
    float fl = floorf(y);
    float f  = y - fl;                 // [0,1)
    float p = 1.5252733e-5f;
    p = fmaf(p, f, 1.5403530e-4f);
    p = fmaf(p, f, 1.3333558e-3f);
    p = fmaf(p, f, 9.6181291e-3f);
    p = fmaf(p, f, 5.5504109e-2f);
    p = fmaf(p, f, 2.4022651e-1f);
    p = fmaf(p, f, 6.9314718e-1f);
    p = fmaf(p, f, 1.0f);
    int i = (int)fl;
    return p * __int_as_float((i + 127) << 23);
}

// ---------------- K1: LN stats + logits + per-tile softmax partials ----------------
__global__ __launch_bounds__(256) void k1(const float* __restrict__ x,
                                          const float* __restrict__ gamma,
                                          const float* __restrict__ beta,
                                          const float* __restrict__ attw)
{
    extern __shared__ float logit_s[];              // [128][129]
    __shared__ float  w_s[HEADSn*Qn*Dn];            // 16 KB
    __shared__ float  rsum[256], rsq[256];
    __shared__ float2 stats_s[LT1];

    const int b = blockIdx.y, tile = blockIdx.x;
    const int tid  = threadIdx.x;
    const int lt   = tid & 127;
    const int half = tid >> 7;
    const int l    = tile*LT1 + lt;

    for (int i = tid; i < HEADSn*Qn*Dn; i += 256) w_s[i] = attw[i];

    const float* xb = x + (size_t)b*Cn*Ln;

    // phase A: LN stats (each half sums 128 channels)
    float s = 0.f, ss = 0.f;
    const int c0 = half*128;
    #pragma unroll 4
    for (int c = c0; c < c0+128; c++) {
        float v = xb[(size_t)c*Ln + l];
        s += v; ss += v*v;
    }
    rsum[tid] = s; rsq[tid] = ss;
    __syncthreads();
    if (half == 0) {
        float sum = rsum[lt] + rsum[lt+128];
        float sq  = rsq [lt] + rsq [lt+128];
        float mu  = sum * (1.f/Cn);
        float var = sq * (1.f/Cn) - mu*mu;
        float rstd = rsqrtf(var + 1e-6f);
        stats_s[lt] = make_float2(mu, rstd);
        g_stats[b*Ln + l] = make_float2(mu, rstd);
    }
    __syncthreads();
    const float mu = stats_s[lt].x, rstd = stats_s[lt].y;

    // phase B: 4 heads per half (x re-reads hit L1)
    for (int hh = 0; hh < 4; hh++) {
        const int h = half*4 + hh;
        float acc[Qn];
        #pragma unroll
        for (int q = 0; q < Qn; q++) acc[q] = 0.f;
        #pragma unroll 4
        for (int cc = 0; cc < Dn; cc++) {
            const int c = h*Dn + cc;
            float xv = xb[(size_t)c*Ln + l];
            float xn = (xv - mu) * rstd * gamma[c] + beta[c];
            const float* wp = &w_s[(h*Qn)*Dn + cc];
            #pragma unroll
            for (int q = 0; q < Qn; q++)
                acc[q] = fmaf(wp[q*Dn], xn, acc[q]);
        }
        #pragma unroll
        for (int q = 0; q < Qn; q++) {
            const int hq = h*Qn + q;
            logit_s[hq*129 + lt] = acc[q];
            g_logits[((size_t)(b*NHQ + hq))*Ln + l] = acc[q];
        }
    }
    __syncthreads();

    // phase C: per-hq tile max / sumexp
    if (tid < NHQ) {
        const int hq = tid;
        float m = -1e30f;
        for (int k = 0; k < LT1; k++) m = fmaxf(m, logit_s[hq*129 + k]);
        float se = 0.f;
        for (int k = 0; k < LT1; k++) se += fexp(logit_s[hq*129 + k] - m);
        g_part[(b*NT1 + tile)*NHQ + hq] = make_float2(m, se);
    }
}

// ---------------- K2: merge softmax partials ----------------
__global__ void k2()
{
    const int idx = blockIdx.x*256 + threadIdx.x;   // B*NHQ = 8192
    if (idx >= Bn*NHQ) return;
    const int b = idx >> 7, hq = idx & 127;
    float m = -1e30f;
    for (int t = 0; t < NT1; t++) m = fmaxf(m, g_part[(b*NT1 + t)*NHQ + hq].x);
    float s = 0.f;
    for (int t = 0; t < NT1; t++) {
        float2 p = g_part[(b*NT1 + t)*NHQ + hq];
        s += p.y * fexp(p.x - m);
    }
    g_ms[idx] = make_float2(m, 1.f/s);
}

// ---------------- K3: P = Aw @ xn^T  (dominant GEMM, 8x8 register tiles) ----------------
__global__ __launch_bounds__(512, 1) void k3(const float* __restrict__ x,
                                             const float* __restrict__ gamma,
                                             const float* __restrict__ beta)
{
    extern __shared__ float sm[];
    float* aw_s = sm;                 // [KT][132]
    float* xn_s = sm + KT*132;        // [KT][260]
    __shared__ float  gm[Cn], bt[Cn];
    __shared__ float2 ms_s[NHQ];

    const int split = blockIdx.x, b = blockIdx.y;
    const int tid = threadIdx.x;
    const int ty = tid >> 5, tx = tid & 31;

    for (int i = tid; i < Cn;  i += 512) { gm[i] = gamma[i]; bt[i] = beta[i]; }
    for (int i = tid; i < NHQ; i += 512) ms_s[i] = g_ms[b*NHQ + i];

    float acc[8][8];
    #pragma unroll
    for (int i = 0; i < 8; i++)
        #pragma unroll
        for (int j = 0; j < 8; j++) acc[i][j] = 0.f;

    const float*  xb  = x        + (size_t)b*Cn*Ln;
    const float*  lg  = g_logits + (size_t)b*NHQ*Ln;
    const float2* stp = g_stats  + b*Ln;

    const int hqA = tid >> 2, k0A = (tid & 3) * 8;   // Aw loader mapping
    const int cB  = tid >> 1, k0B = (tid & 1) * 16;  // xn loader mapping

    __syncthreads();

    for (int t = 0; t < LSP/KT; t++) {
        const int lb = split*LSP + t*KT;

        // stage Aw tile (exp applied inline)
        {
            const float2 ms = ms_s[hqA];
            const float* gp = lg + (size_t)hqA*Ln + lb + k0A;
            float4 v0 = *(const float4*)gp;
            float4 v1 = *(const float4*)(gp + 4);
            float vv[8] = {v0.x,v0.y,v0.z,v0.w,v1.x,v1.y,v1.z,v1.w};
            #pragma unroll
            for (int j = 0; j < 8; j++)
                aw_s[(k0A + j)*132 + hqA] = fexp(vv[j] - ms.x) * ms.y;
        }
        // stage xn tile (LN applied inline from stats)
        {
            const float* xp = xb + (size_t)cB*Ln + lb + k0B;
            const float gg = gm[cB], bb2 = bt[cB];
            #pragma unroll
            for (int jj = 0; jj < 16; jj += 4) {
                float4 v = *(const float4*)(xp + jj);
                float vv[4] = {v.x, v.y, v.z, v.w};
                #pragma unroll
                for (int e = 0; e < 4; e++) {
                    float2 st = stp[lb + k0B + jj + e];
                    xn_s[(k0B + jj + e)*260 + cB] = (vv[e] - st.x)*st.y*gg + bb2;
                }
            }
        }
        __syncthreads();

        #pragma unroll 4
        for (int k = 0; k < KT; k++) {
            float4 a0 = *(const float4*)&aw_s[k*132 + ty*8];
            float4 a1 = *(const float4*)&aw_s[k*132 + ty*8 + 4];
            float4 b0 = *(const float4*)&xn_s[k*260 + tx*8];
            float4 b1 = *(const float4*)&xn_s[k*260 + tx*8 + 4];
            float av[8] = {a0.x,a0.y,a0.z,a0.w,a1.x,a1.y,a1.z,a1.w};
            float bv[8] = {b0.x,b0.y,b0.z,b0.w,b1.x,b1.y,b1.z,b1.w};
            #pragma unroll
            for (int i = 0; i < 8; i++)
                #pragma unroll
                for (int j = 0; j < 8; j++)
                    acc[i][j] = fmaf(av[i], bv[j], acc[i][j]);
        }
        __syncthreads();
    }

    float* pp = g_Ppart + (((size_t)split*Bn + b)*NHQ)*Cn;
    #pragma unroll
    for (int i = 0; i < 8; i++) {
        float* row = pp + (size_t)(ty*8 + i)*Cn + tx*8;
        *(float4*)(row)     = make_float4(acc[i][0], acc[i][1], acc[i][2], acc[i][3]);
        *(float4*)(row + 4) = make_float4(acc[i][4], acc[i][5], acc[i][6], acc[i][7]);
    }
}

// ---------------- K4a: reduce P partials, A = P @ val_w^T (per head) + val_b ----------------
__global__ void k4a(const float* __restrict__ val_w, const float* __restrict__ val_b)
{
    extern __shared__ float sm[];
    float* vw = sm;             // [32][257]
    float* ps = sm + 32*257;    // [16][256]
    const int h = blockIdx.x, b = blockIdx.y;
    const int tid = threadIdx.x;

    for (int i = tid; i < 32*Cn; i += 256) {
        int r = i >> 8, c = i & 255;
        vw[r*257 + c] = val_w[(size_t)(h*32 + r)*Cn + c];
    }
    for (int i = tid; i < Qn*Cn; i += 256) {
        int q = i >> 8, c = i & 255;
        int hq = h*Qn + q;
        float s = 0.f;
        #pragma unroll
        for (int sp = 0; sp < NSPLIT; sp++)
            s += g_Ppart[(((size_t)sp*Bn + b)*NHQ + hq)*Cn + c];
        ps[i] = s;
    }
    __syncthreads();

    for (int o = tid; o < Qn*32; o += 256) {
        int q = o >> 5, d = o & 31;
        float a = val_b[h*32 + d];
        #pragma unroll 4
        for (int c = 0; c < Cn; c++)
            a = fmaf(ps[q*Cn + c], vw[d*257 + c], a);
        g_A[b*4096 + (h*Qn + q)*32 + d] = a;
    }
}

// ---------------- K4b: out = A @ fin_w^T + fin_b ----------------
__global__ void kinit(float* __restrict__ out, const float* __restrict__ fin_b)
{
    out[blockIdx.x*FHn + threadIdx.x] = fin_b[threadIdx.x];
}

__global__ void k4b(const float* __restrict__ fin_w, float* __restrict__ out)
{
    __shared__ float At[64*65];
    __shared__ float Wt[32*65];
    const int ft = blockIdx.x;   // 16 f-tiles of 32
    const int js = blockIdx.y;   // 8 K-splits of 512
    const int tid = threadIdx.x;
    const int ty = tid >> 5, tx = tid & 31;
    const int f0 = ft*32;

    float acc[8];
    #pragma unroll
    for (int i = 0; i < 8; i++) acc[i] = 0.f;

    for (int sub = 0; sub < 8; sub++) {
        const int j0 = js*512 + sub*64;
        __syncthreads();
        for (int i = tid; i < 64*64; i += 256) {
            int bb = i >> 6, jj = i & 63;
            At[bb*65 + jj] = g_A[bb*4096 + j0 + jj];
        }
        for (int i = tid; i < 32*64; i += 256) {
            int r = i >> 6, jj = i & 63;
            Wt[r*65 + jj] = fin_w[(size_t)(f0 + r)*4096 + j0 + jj];
        }
        __syncthreads();
        #pragma unroll 8
        for (int j = 0; j < 64; j++) {
            float w = Wt[tx*65 + j];
            #pragma unroll
            for (int i = 0; i < 8; i++)
                acc[i] = fmaf(At[(ty*8 + i)*65 + j], w, acc[i]);
        }
    }
    #pragma unroll
    for (int i = 0; i < 8; i++)
        atomicAdd(&out[(ty*8 + i)*FHn + f0 + tx], acc[i]);
}

// ---------------- launch ----------------
extern "C" void kernel_launch(void* const* d_in, const int* in_sizes, int n_in,
                              void* d_out, int out_size)
{
    const float* x    = (const float*)d_in[0];
    const float* gam  = (const float*)d_in[1];
    const float* bet  = (const float*)d_in[2];
    const float* attw = (const float*)d_in[3];
    const float* valw = (const float*)d_in[4];
    const float* valb = (const float*)d_in[5];
    const float* finw = (const float*)d_in[6];
    const float* finb = (const float*)d_in[7];
    float* out = (float*)d_out;

    const int smem_k1  = 128*129*4;                 // 66048
    const int smem_k3  = (KT*132 + KT*260)*4;       // 50176
    const int smem_k4a = (32*257 + 16*Cn)*4;        // 49280

    cudaFuncSetAttribute(k1,  cudaFuncAttributeMaxDynamicSharedMemorySize, smem_k1);
    cudaFuncSetAttribute(k3,  cudaFuncAttributeMaxDynamicSharedMemorySize, smem_k3);
    cudaFuncSetAttribute(k4a, cudaFuncAttributeMaxDynamicSharedMemorySize, smem_k4a);

    k1  <<<dim3(NT1, Bn),    256, smem_k1 >>>(x, gam, bet, attw);
    k2  <<<32, 256>>>();
    k3  <<<dim3(NSPLIT, Bn), 512, smem_k3 >>>(x, gam, bet);
    k4a <<<dim3(HEADSn, Bn), 256, smem_k4a>>>(valw, valb);
    kinit<<<Bn, FHn>>>(out, finb);
    k4b <<<dim3(16, 8), 256>>>(finw, out);
}

// round 4
// speedup vs baseline: 1.4166x; 1.4166x over previous
#include <cuda_runtime.h>
#include <cuda_bf16.h>
#include <cstdint>
#include <math.h>

#define Bn      64
#define Cn      256
#define Ln      4096
#define HEADSn  8
#define Qn      16
#define Dn      32
#define NHQ     128          // HEADS*Q
#define FHn     512
#define NT1     32           // K1: L / 128
#define LT1     128
#define NSPLIT  4
#define LSP     1024         // L per split (Ln/NSPLIT)
#define KC      64           // K3 l-chunk
#define NCHUNK  (LSP/KC)     // 16
#define APITCH  72           // bf16 elems per row (64 + 8 pad -> 144B pitch, conflict-free)

// ---------------- scratch (device globals: no allocs allowed) ----------------
__device__ float  g_logits[(size_t)Bn*NHQ*Ln];            // 134 MB
__device__ float2 g_stats [Bn*Ln];                         // mean,rstd per (b,l)
__device__ float2 g_part  [Bn*NT1*NHQ];                    // per-tile (max, sumexp)
__device__ float2 g_ms    [Bn*NHQ];                        // (max, 1/sum)
__device__ float  g_Ppart [(size_t)NSPLIT*Bn*NHQ*Cn];      // 34 MB partial P
__device__ float  g_A     [Bn*NHQ*Dn];                     // Aflat [B,4096]

// ---------------- fast exp (no MUFU; pure FMA/ALU) ----------------
__device__ __forceinline__ float fexp(float x) {
    float y = x * 1.4426950408889634f;
    y = fmaxf(y, -120.0f);
    float fl = floorf(y);
    float f  = y - fl;                 // [0,1)
    float p = 1.5252733e-5f;
    p = fmaf(p, f, 1.5403530e-4f);
    p = fmaf(p, f, 1.3333558e-3f);
    p = fmaf(p, f, 9.6181291e-3f);
    p = fmaf(p, f, 5.5504109e-2f);
    p = fmaf(p, f, 2.4022651e-1f);
    p = fmaf(p, f, 6.9314718e-1f);
    p = fmaf(p, f, 1.0f);
    int i = (int)fl;
    return p * __int_as_float((i + 127) << 23);
}

// mma.sync m16n8k16 bf16 (row.col), fp32 accumulate — base-arch tensor path
__device__ __forceinline__ void mma16816(float* d, const uint32_t* a, const uint32_t* b) {
    asm volatile("mma.sync.aligned.m16n8k16.row.col.f32.bf16.bf16.f32 "
        "{%0,%1,%2,%3}, {%4,%5,%6,%7}, {%8,%9}, {%0,%1,%2,%3};"
        : "+f"(d[0]), "+f"(d[1]), "+f"(d[2]), "+f"(d[3])
        : "r"(a[0]), "r"(a[1]), "r"(a[2]), "r"(a[3]), "r"(b[0]), "r"(b[1]));
}

__device__ __forceinline__ uint32_t bf16x2_split(float v0, float v1, uint32_t& lo) {
    __nv_bfloat16 h0 = __float2bfloat16_rn(v0);
    __nv_bfloat16 h1 = __float2bfloat16_rn(v1);
    float r0 = v0 - __bfloat162float(h0);
    float r1 = v1 - __bfloat162float(h1);
    __nv_bfloat162 hi2(h0, h1);
    __nv_bfloat162 lo2(__float2bfloat16_rn(r0), __float2bfloat16_rn(r1));
    lo = *reinterpret_cast<uint32_t*>(&lo2);
    return *reinterpret_cast<uint32_t*>(&hi2);
}

// ---------------- K1: LN stats + logits + per-tile softmax partials ----------------
__global__ __launch_bounds__(256) void k1(const float* __restrict__ x,
                                          const float* __restrict__ gamma,
                                          const float* __restrict__ beta,
                                          const float* __restrict__ attw)
{
    extern __shared__ float logit_s[];              // [128][129]
    __shared__ float  w_s[HEADSn*Qn*Dn];
    __shared__ float  rsum[256], rsq[256];
    __shared__ float2 stats_s[LT1];

    const int b = blockIdx.y, tile = blockIdx.x;
    const int tid  = threadIdx.x;
    const int lt   = tid & 127;
    const int half = tid >> 7;
    const int l    = tile*LT1 + lt;

    for (int i = tid; i < HEADSn*Qn*Dn; i += 256) w_s[i] = attw[i];

    const float* xb = x + (size_t)b*Cn*Ln;

    float s = 0.f, ss = 0.f;
    const int c0 = half*128;
    #pragma unroll 4
    for (int c = c0; c < c0+128; c++) {
        float v = xb[(size_t)c*Ln + l];
        s += v; ss += v*v;
    }
    rsum[tid] = s; rsq[tid] = ss;
    __syncthreads();
    if (half == 0) {
        float sum = rsum[lt] + rsum[lt+128];
        float sq  = rsq [lt] + rsq [lt+128];
        float mu  = sum * (1.f/Cn);
        float var = sq * (1.f/Cn) - mu*mu;
        float rstd = rsqrtf(var + 1e-6f);
        stats_s[lt] = make_float2(mu, rstd);
        g_stats[b*Ln + l] = make_float2(mu, rstd);
    }
    __syncthreads();
    const float mu = stats_s[lt].x, rstd = stats_s[lt].y;

    for (int hh = 0; hh < 4; hh++) {
        const int h = half*4 + hh;
        float acc[Qn];
        #pragma unroll
        for (int q = 0; q < Qn; q++) acc[q] = 0.f;
        #pragma unroll 4
        for (int cc = 0; cc < Dn; cc++) {
            const int c = h*Dn + cc;
            float xv = xb[(size_t)c*Ln + l];
            float xn = (xv - mu) * rstd * gamma[c] + beta[c];
            const float* wp = &w_s[(h*Qn)*Dn + cc];
            #pragma unroll
            for (int q = 0; q < Qn; q++)
                acc[q] = fmaf(wp[q*Dn], xn, acc[q]);
        }
        #pragma unroll
        for (int q = 0; q < Qn; q++) {
            const int hq = h*Qn + q;
            logit_s[hq*129 + lt] = acc[q];
            g_logits[((size_t)(b*NHQ + hq))*Ln + l] = acc[q];
        }
    }
    __syncthreads();

    if (tid < NHQ) {
        const int hq = tid;
        float m = -1e30f;
        for (int k = 0; k < LT1; k++) m = fmaxf(m, logit_s[hq*129 + k]);
        float se = 0.f;
        for (int k = 0; k < LT1; k++) se += fexp(logit_s[hq*129 + k] - m);
        g_part[(b*NT1 + tile)*NHQ + hq] = make_float2(m, se);
    }
}

// ---------------- K2: merge softmax partials ----------------
__global__ void k2()
{
    const int idx = blockIdx.x*256 + threadIdx.x;
    if (idx >= Bn*NHQ) return;
    const int b = idx >> 7, hq = idx & 127;
    float m = -1e30f;
    for (int t = 0; t < NT1; t++) m = fmaxf(m, g_part[(b*NT1 + t)*NHQ + hq].x);
    float s = 0.f;
    for (int t = 0; t < NT1; t++) {
        float2 p = g_part[(b*NT1 + t)*NHQ + hq];
        s += p.y * fexp(p.x - m);
    }
    g_ms[idx] = make_float2(m, 1.f/s);
}

// ---------------- K3: P = Aw @ xn^T via mma.sync bf16 (hi/lo 3-pass fp32 emu) ----------------
// SMEM (bf16, K-major, pitch APITCH=72): Ah[128], Al[128], Bh[256], Bl[256]
#define AH_OFF 0
#define AL_OFF (128*APITCH)
#define BH_OFF (2*128*APITCH)
#define BL_OFF (2*128*APITCH + 256*APITCH)
#define K3_ELEMS (2*128*APITCH + 2*256*APITCH)
#define K3_DYN (K3_ELEMS*2)

__global__ __launch_bounds__(512, 1) void k3(const float* __restrict__ x,
                                             const float* __restrict__ gamma,
                                             const float* __restrict__ beta)
{
    extern __shared__ __nv_bfloat16 sm3[];
    __shared__ float  gm[Cn], bt[Cn];
    __shared__ float2 ms_s[NHQ];
    __shared__ float2 stat_s[KC];

    const int split = blockIdx.x, b = blockIdx.y;
    const int tid  = threadIdx.x;
    const int wid  = tid >> 5, lane = tid & 31;
    const int mw   = wid >> 2, nw = wid & 3;    // warp tile: rows [mw*32,+32) cols [nw*64,+64)

    for (int i = tid; i < Cn;  i += 512) { gm[i] = gamma[i]; bt[i] = beta[i]; }
    for (int i = tid; i < NHQ; i += 512) ms_s[i] = g_ms[b*NHQ + i];

    const float* xb = x        + (size_t)b*Cn*Ln;
    const float* lg = g_logits + (size_t)b*NHQ*Ln;

    // loader mappings
    const int hqA = tid >> 2, l0A = (tid & 3) * 16;   // A: 128 rows x 64
    const int cB  = tid >> 1, l0B = (tid & 1) * 32;   // B: 256 rows x 64
    __syncthreads();
    const float2 msA = ms_s[hqA];
    const float  ggB = gm[cB], bbB = bt[cB];

    float acc[2][8][4];
    #pragma unroll
    for (int i = 0; i < 2; i++)
        #pragma unroll
        for (int j = 0; j < 8; j++)
            #pragma unroll
            for (int e = 0; e < 4; e++) acc[i][j][e] = 0.f;

    // fragment LDS indices
    const int rA = lane >> 2, kA = (lane & 3) * 2;    // A frag row/col within tile
    const int nB = lane >> 2, kB = (lane & 3) * 2;    // B frag

    for (int t = 0; t < NCHUNK; t++) {
        const int lb = split*LSP + t*KC;

        // stats for this chunk
        float2 stv;
        if (tid < KC) stv = g_stats[b*Ln + lb + tid];

        // global loads
        float4 lv[4];
        {
            const float* gp = lg + (size_t)hqA*Ln + lb + l0A;
            #pragma unroll
            for (int j = 0; j < 4; j++) lv[j] = *(const float4*)(gp + 4*j);
        }
        float4 xv[8];
        {
            const float* xp = xb + (size_t)cB*Ln + lb + l0B;
            #pragma unroll
            for (int j = 0; j < 8; j++) xv[j] = *(const float4*)(xp + 4*j);
        }

        __syncthreads();              // prev chunk's MMA done reading smem
        if (tid < KC) stat_s[tid] = stv;
        __syncthreads();

        // ---- A (softmax weights) -> bf16 hi/lo ----
        {
            #pragma unroll
            for (int j = 0; j < 4; j++) {
                float a0 = fexp(lv[j].x - msA.x) * msA.y;
                float a1 = fexp(lv[j].y - msA.x) * msA.y;
                float a2 = fexp(lv[j].z - msA.x) * msA.y;
                float a3 = fexp(lv[j].w - msA.x) * msA.y;
                uint32_t lo0, lo1;
                uint32_t hi0 = bf16x2_split(a0, a1, lo0);
                uint32_t hi1 = bf16x2_split(a2, a3, lo1);
                int idx = hqA*APITCH + l0A + 4*j;
                *(uint32_t*)(sm3 + AH_OFF + idx)     = hi0;
                *(uint32_t*)(sm3 + AH_OFF + idx + 2) = hi1;
                *(uint32_t*)(sm3 + AL_OFF + idx)     = lo0;
                *(uint32_t*)(sm3 + AL_OFF + idx + 2) = lo1;
            }
        }
        // ---- B (LayerNormed x) -> bf16 hi/lo ----
        {
            #pragma unroll
            for (int j = 0; j < 8; j++) {
                float vv[4] = {xv[j].x, xv[j].y, xv[j].z, xv[j].w};
                float xn[4];
                #pragma unroll
                for (int e = 0; e < 4; e++) {
                    float2 st = stat_s[l0B + 4*j + e];
                    xn[e] = (vv[e] - st.x) * st.y * ggB + bbB;
                }
                uint32_t lo0, lo1;
                uint32_t hi0 = bf16x2_split(xn[0], xn[1], lo0);
                uint32_t hi1 = bf16x2_split(xn[2], xn[3], lo1);
                int idx = cB*APITCH + l0B + 4*j;
                *(uint32_t*)(sm3 + BH_OFF + idx)     = hi0;
                *(uint32_t*)(sm3 + BH_OFF + idx + 2) = hi1;
                *(uint32_t*)(sm3 + BL_OFF + idx)     = lo0;
                *(uint32_t*)(sm3 + BL_OFF + idx + 2) = lo1;
            }
        }
        __syncthreads();

        // ---- MMA: 4 k-steps of 16 ----
        #pragma unroll
        for (int ks = 0; ks < 4; ks++) {
            const int k0 = ks*16;
            uint32_t ah[2][4], al[2][4];
            #pragma unroll
            for (int i = 0; i < 2; i++) {
                const int r0 = (mw*32 + i*16 + rA) * APITCH + k0 + kA;
                const int r8 = r0 + 8*APITCH;
                ah[i][0] = *(const uint32_t*)(sm3 + AH_OFF + r0);
                ah[i][1] = *(const uint32_t*)(sm3 + AH_OFF + r8);
                ah[i][2] = *(const uint32_t*)(sm3 + AH_OFF + r0 + 8);
                ah[i][3] = *(const uint32_t*)(sm3 + AH_OFF + r8 + 8);
                al[i][0] = *(const uint32_t*)(sm3 + AL_OFF + r0);
                al[i][1] = *(const uint32_t*)(sm3 + AL_OFF + r8);
                al[i][2] = *(const uint32_t*)(sm3 + AL_OFF + r0 + 8);
                al[i][3] = *(const uint32_t*)(sm3 + AL_OFF + r8 + 8);
            }
            #pragma unroll
            for (int j = 0; j < 8; j++) {
                const int c0 = (nw*64 + j*8 + nB) * APITCH + k0 + kB;
                uint32_t bh[2], bl[2];
                bh[0] = *(const uint32_t*)(sm3 + BH_OFF + c0);
                bh[1] = *(const uint32_t*)(sm3 + BH_OFF + c0 + 8);
                bl[0] = *(const uint32_t*)(sm3 + BL_OFF + c0);
                bl[1] = *(const uint32_t*)(sm3 + BL_OFF + c0 + 8);
                #pragma unroll
                for (int i = 0; i < 2; i++) {
                    mma16816(acc[i][j], ah[i], bh);
                    mma16816(acc[i][j], ah[i], bl);
                    mma16816(acc[i][j], al[i], bh);
                }
            }
        }
    }

    // ---- epilogue: write P partial ----
    float* pp = g_Ppart + (((size_t)split*Bn + b)*NHQ)*Cn;
    #pragma unroll
    for (int i = 0; i < 2; i++) {
        const int row = mw*32 + i*16 + (lane >> 2);
        #pragma unroll
        for (int j = 0; j < 8; j++) {
            const int col = nw*64 + j*8 + (lane & 3)*2;
            *(float2*)(pp + (size_t)row*Cn + col)     = make_float2(acc[i][j][0], acc[i][j][1]);
            *(float2*)(pp + (size_t)(row+8)*Cn + col) = make_float2(acc[i][j][2], acc[i][j][3]);
        }
    }
}

// ---------------- K4a: reduce P partials, A = P @ val_w^T (per head) + val_b ----------------
__global__ void k4a(const float* __restrict__ val_w, const float* __restrict__ val_b)
{
    extern __shared__ float sm[];
    float* vw = sm;             // [32][257]
    float* ps = sm + 32*257;    // [16][256]
    const int h = blockIdx.x, b = blockIdx.y;
    const int tid = threadIdx.x;

    for (int i = tid; i < 32*Cn; i += 256) {
        int r = i >> 8, c = i & 255;
        vw[r*257 + c] = val_w[(size_t)(h*32 + r)*Cn + c];
    }
    for (int i = tid; i < Qn*Cn; i += 256) {
        int q = i >> 8, c = i & 255;
        int hq = h*Qn + q;
        float s = 0.f;
        #pragma unroll
        for (int sp = 0; sp < NSPLIT; sp++)
            s += g_Ppart[(((size_t)sp*Bn + b)*NHQ + hq)*Cn + c];
        ps[i] = s;
    }
    __syncthreads();

    for (int o = tid; o < Qn*32; o += 256) {
        int q = o >> 5, d = o & 31;
        float a = val_b[h*32 + d];
        #pragma unroll 4
        for (int c = 0; c < Cn; c++)
            a = fmaf(ps[q*Cn + c], vw[d*257 + c], a);
        g_A[b*4096 + (h*Qn + q)*32 + d] = a;
    }
}

// ---------------- K4b: out = A @ fin_w^T + fin_b ----------------
__global__ void kinit(float* __restrict__ out, const float* __restrict__ fin_b)
{
    out[blockIdx.x*FHn + threadIdx.x] = fin_b[threadIdx.x];
}

__global__ void k4b(const float* __restrict__ fin_w, float* __restrict__ out)
{
    __shared__ float At[64*65];
    __shared__ float Wt[32*65];
    const int ft = blockIdx.x;
    const int js = blockIdx.y;
    const int tid = threadIdx.x;
    const int ty = tid >> 5, tx = tid & 31;
    const int f0 = ft*32;

    float acc[8];
    #pragma unroll
    for (int i = 0; i < 8; i++) acc[i] = 0.f;

    for (int sub = 0; sub < 8; sub++) {
        const int j0 = js*512 + sub*64;
        __syncthreads();
        for (int i = tid; i < 64*64; i += 256) {
            int bb = i >> 6, jj = i & 63;
            At[bb*65 + jj] = g_A[bb*4096 + j0 + jj];
        }
        for (int i = tid; i < 32*64; i += 256) {
            int r = i >> 6, jj = i & 63;
            Wt[r*65 + jj] = fin_w[(size_t)(f0 + r)*4096 + j0 + jj];
        }
        __syncthreads();
        #pragma unroll 8
        for (int j = 0; j < 64; j++) {
            float w = Wt[tx*65 + j];
            #pragma unroll
            for (int i = 0; i < 8; i++)
                acc[i] = fmaf(At[(ty*8 + i)*65 + j], w, acc[i]);
        }
    }
    #pragma unroll
    for (int i = 0; i < 8; i++)
        atomicAdd(&out[(ty*8 + i)*FHn + f0 + tx], acc[i]);
}

// ---------------- launch ----------------
extern "C" void kernel_launch(void* const* d_in, const int* in_sizes, int n_in,
                              void* d_out, int out_size)
{
    const float* x    = (const float*)d_in[0];
    const float* gam  = (const float*)d_in[1];
    const float* bet  = (const float*)d_in[2];
    const float* attw = (const float*)d_in[3];
    const float* valw = (const float*)d_in[4];
    const float* valb = (const float*)d_in[5];
    const float* finw = (const float*)d_in[6];
    const float* finb = (const float*)d_in[7];
    float* out = (float*)d_out;

    const int smem_k1  = 128*129*4;
    const int smem_k4a = (32*257 + 16*Cn)*4;

    cudaFuncSetAttribute(k1,  cudaFuncAttributeMaxDynamicSharedMemorySize, smem_k1);
    cudaFuncSetAttribute(k3,  cudaFuncAttributeMaxDynamicSharedMemorySize, K3_DYN);
    cudaFuncSetAttribute(k4a, cudaFuncAttributeMaxDynamicSharedMemorySize, smem_k4a);

    k1  <<<dim3(NT1, Bn),    256, smem_k1 >>>(x, gam, bet, attw);
    k2  <<<32, 256>>>();
    k3  <<<dim3(NSPLIT, Bn), 512, K3_DYN >>>(x, gam, bet);
    k4a <<<dim3(HEADSn, Bn), 256, smem_k4a>>>(valw, valb);
    kinit<<<Bn, FHn>>>(out, finb);
    k4b <<<dim3(16, 8), 256>>>(finw, out);
}

// round 5
// speedup vs baseline: 1.5904x; 1.1227x over previous
#include <cuda_runtime.h>
#include <cuda_fp16.h>
#include <cstdint>
#include <math.h>

#define Bn      64
#define Cn      256
#define Ln      4096
#define HEADSn  8
#define Qn      16
#define Dn      32
#define NHQ     128          // HEADS*Q
#define FHn     512
#define NT1     32           // K1: L / 128
#define LT1     128
#define NSPLIT  2
#define LSP     2048         // L per split (Ln/NSPLIT)
#define KC      64           // K3 l-chunk
#define NCHUNK  (LSP/KC)     // 32
#define APITCH  72           // fp16 elems per row (64 + 8 pad -> 144B pitch, conflict-free)

// ---------------- scratch (device globals: no allocs allowed) ----------------
__device__ float  g_logits[(size_t)Bn*NHQ*Ln];            // 134 MB
__device__ float2 g_stats [Bn*Ln];                         // mean,rstd per (b,l)
__device__ float2 g_part  [Bn*NT1*NHQ];                    // per-tile (max, sumexp)
__device__ float2 g_ms    [Bn*NHQ];                        // (max, 1/sum)
__device__ float  g_Ppart [(size_t)NSPLIT*Bn*NHQ*Cn];      // 17 MB partial P
__device__ float  g_A     [Bn*NHQ*Dn];                     // Aflat [B,4096]

// ---------------- fast exp (no MUFU; pure FMA/ALU) ----------------
__device__ __forceinline__ float fexp(float x) {
    float y = x * 1.4426950408889634f;
    y = fmaxf(y, -120.0f);
    float fl = floorf(y);
    float f  = y - fl;                 // [0,1)
    float p = 1.5252733e-5f;
    p = fmaf(p, f, 1.5403530e-4f);
    p = fmaf(p, f, 1.3333558e-3f);
    p = fmaf(p, f, 9.6181291e-3f);
    p = fmaf(p, f, 5.5504109e-2f);
    p = fmaf(p, f, 2.4022651e-1f);
    p = fmaf(p, f, 6.9314718e-1f);
    p = fmaf(p, f, 1.0f);
    int i = (int)fl;
    return p * __int_as_float((i + 127) << 23);
}

// mma.sync m16n8k16 fp16 (row.col), fp32 accumulate — base-arch tensor path
__device__ __forceinline__ void mma16816(float* d, const uint32_t* a, const uint32_t* b) {
    asm volatile("mma.sync.aligned.m16n8k16.row.col.f32.f16.f16.f32 "
        "{%0,%1,%2,%3}, {%4,%5,%6,%7}, {%8,%9}, {%0,%1,%2,%3};"
        : "+f"(d[0]), "+f"(d[1]), "+f"(d[2]), "+f"(d[3])
        : "r"(a[0]), "r"(a[1]), "r"(a[2]), "r"(a[3]), "r"(b[0]), "r"(b[1]));
}

__device__ __forceinline__ uint32_t h2pack(float v0, float v1) {
    __half2 h = __floats2half2_rn(v0, v1);
    return *reinterpret_cast<uint32_t*>(&h);
}
// split v into fp16 hi + fp16 lo (residual)
__device__ __forceinline__ void h2split(float v0, float v1, uint32_t& hi, uint32_t& lo) {
    __half h0 = __float2half_rn(v0);
    __half h1 = __float2half_rn(v1);
    float r0 = v0 - __half2float(h0);
    float r1 = v1 - __half2float(h1);
    __half2 hh(h0, h1);
    __half2 ll = __floats2half2_rn(r0, r1);
    hi = *reinterpret_cast<uint32_t*>(&hh);
    lo = *reinterpret_cast<uint32_t*>(&ll);
}

// ---------------- K1: LN stats + logits + per-tile softmax partials ----------------
__global__ __launch_bounds__(256) void k1(const float* __restrict__ x,
                                          const float* __restrict__ gamma,
                                          const float* __restrict__ beta,
                                          const float* __restrict__ attw)
{
    extern __shared__ float logit_s[];              // [128][129]
    __shared__ float  w_s[HEADSn*Qn*Dn];
    __shared__ float  rsum[256], rsq[256];
    __shared__ float2 stats_s[LT1];

    const int b = blockIdx.y, tile = blockIdx.x;
    const int tid  = threadIdx.x;
    const int lt   = tid & 127;
    const int half = tid >> 7;
    const int l    = tile*LT1 + lt;

    for (int i = tid; i < HEADSn*Qn*Dn; i += 256) w_s[i] = attw[i];

    const float* xb = x + (size_t)b*Cn*Ln;

    float s = 0.f, ss = 0.f;
    const int c0 = half*128;
    #pragma unroll 4
    for (int c = c0; c < c0+128; c++) {
        float v = xb[(size_t)c*Ln + l];
        s += v; ss += v*v;
    }
    rsum[tid] = s; rsq[tid] = ss;
    __syncthreads();
    if (half == 0) {
        float sum = rsum[lt] + rsum[lt+128];
        float sq  = rsq [lt] + rsq [lt+128];
        float mu  = sum * (1.f/Cn);
        float var = sq * (1.f/Cn) - mu*mu;
        float rstd = rsqrtf(var + 1e-6f);
        stats_s[lt] = make_float2(mu, rstd);
        g_stats[b*Ln + l] = make_float2(mu, rstd);
    }
    __syncthreads();
    const float mu = stats_s[lt].x, rstd = stats_s[lt].y;

    for (int hh = 0; hh < 4; hh++) {
        const int h = half*4 + hh;
        float acc[Qn];
        #pragma unroll
        for (int q = 0; q < Qn; q++) acc[q] = 0.f;
        #pragma unroll 4
        for (int cc = 0; cc < Dn; cc++) {
            const int c = h*Dn + cc;
            float xv = xb[(size_t)c*Ln + l];
            float xn = (xv - mu) * rstd * gamma[c] + beta[c];
            const float* wp = &w_s[(h*Qn)*Dn + cc];
            #pragma unroll
            for (int q = 0; q < Qn; q++)
                acc[q] = fmaf(wp[q*Dn], xn, acc[q]);
        }
        #pragma unroll
        for (int q = 0; q < Qn; q++) {
            const int hq = h*Qn + q;
            logit_s[hq*129 + lt] = acc[q];
            g_logits[((size_t)(b*NHQ + hq))*Ln + l] = acc[q];
        }
    }
    __syncthreads();

    // phase C: 2 threads per hq row, shfl combine
    {
        const int hq  = tid >> 1;
        const int sub = tid & 1;
        const float* row = &logit_s[hq*129 + sub*64];
        float m = -1e30f;
        #pragma unroll 8
        for (int k = 0; k < 64; k++) m = fmaxf(m, row[k]);
        m = fmaxf(m, __shfl_xor_sync(0xFFFFFFFFu, m, 1));
        float se = 0.f;
        #pragma unroll 4
        for (int k = 0; k < 64; k++) se += fexp(row[k] - m);
        se += __shfl_xor_sync(0xFFFFFFFFu, se, 1);
        if (sub == 0)
            g_part[(b*NT1 + tile)*NHQ + hq] = make_float2(m, se);
    }
}

// ---------------- K2: merge softmax partials ----------------
__global__ void k2()
{
    const int idx = blockIdx.x*256 + threadIdx.x;
    if (idx >= Bn*NHQ) return;
    const int b = idx >> 7, hq = idx & 127;
    float m = -1e30f;
    for (int t = 0; t < NT1; t++) m = fmaxf(m, g_part[(b*NT1 + t)*NHQ + hq].x);
    float s = 0.f;
    for (int t = 0; t < NT1; t++) {
        float2 p = g_part[(b*NT1 + t)*NHQ + hq];
        s += p.y * fexp(p.x - m);
    }
    g_ms[idx] = make_float2(m, 1.f/s);
}

// ---------------- K3: P = Aw @ xn^T via mma.sync fp16 (asymmetric 2-pass) ----------------
// SMEM (fp16, K-major, pitch APITCH=72): A[128], Bh[256], Bl[256]
#define A_OFF  0
#define BH_OFF (128*APITCH)
#define BL_OFF (128*APITCH + 256*APITCH)
#define K3_ELEMS (128*APITCH + 2*256*APITCH)
#define K3_DYN (K3_ELEMS*2)

__global__ __launch_bounds__(512, 1) void k3(const float* __restrict__ x,
                                             const float* __restrict__ gamma,
                                             const float* __restrict__ beta)
{
    extern __shared__ __half sm3[];
    __shared__ float  gm[Cn], bt[Cn];
    __shared__ float2 ms_s[NHQ];
    __shared__ float2 stat_s[KC];

    const int split = blockIdx.x, b = blockIdx.y;
    const int tid  = threadIdx.x;
    const int wid  = tid >> 5, lane = tid & 31;
    const int mw   = wid >> 2, nw = wid & 3;    // warp tile: rows [mw*32,+32) cols [nw*64,+64)

    for (int i = tid; i < Cn;  i += 512) { gm[i] = gamma[i]; bt[i] = beta[i]; }
    for (int i = tid; i < NHQ; i += 512) ms_s[i] = g_ms[b*NHQ + i];

    const float* xb = x        + (size_t)b*Cn*Ln;
    const float* lg = g_logits + (size_t)b*NHQ*Ln;

    // loader mappings
    const int hqA = tid >> 2, l0A = (tid & 3) * 16;   // A: 128 rows x 64
    const int cB  = tid >> 1, l0B = (tid & 1) * 32;   // B: 256 rows x 64
    __syncthreads();
    const float2 msA = ms_s[hqA];
    const float  ggB = gm[cB], bbB = bt[cB];

    float acc[2][8][4];
    #pragma unroll
    for (int i = 0; i < 2; i++)
        #pragma unroll
        for (int j = 0; j < 8; j++)
            #pragma unroll
            for (int e = 0; e < 4; e++) acc[i][j][e] = 0.f;

    // fragment LDS indices
    const int rA = lane >> 2, kA = (lane & 3) * 2;    // A frag row/col within tile
    const int nB = lane >> 2, kB = (lane & 3) * 2;    // B frag

    for (int t = 0; t < NCHUNK; t++) {
        const int lb = split*LSP + t*KC;

        // stats for this chunk
        float2 stv;
        if (tid < KC) stv = g_stats[b*Ln + lb + tid];

        // global loads
        float4 lv[4];
        {
            const float* gp = lg + (size_t)hqA*Ln + lb + l0A;
            #pragma unroll
            for (int j = 0; j < 4; j++) lv[j] = *(const float4*)(gp + 4*j);
        }
        float4 xv[8];
        {
            const float* xp = xb + (size_t)cB*Ln + lb + l0B;
            #pragma unroll
            for (int j = 0; j < 8; j++) xv[j] = *(const float4*)(xp + 4*j);
        }

        __syncthreads();              // prev chunk's MMA done reading smem
        if (tid < KC) stat_s[tid] = stv;
        __syncthreads();

        // ---- A (softmax weights) -> fp16 (single precision pass) ----
        {
            #pragma unroll
            for (int j = 0; j < 4; j++) {
                float a0 = fexp(lv[j].x - msA.x) * msA.y;
                float a1 = fexp(lv[j].y - msA.x) * msA.y;
                float a2 = fexp(lv[j].z - msA.x) * msA.y;
                float a3 = fexp(lv[j].w - msA.x) * msA.y;
                int idx = hqA*APITCH + l0A + 4*j;
                *(uint32_t*)(sm3 + A_OFF + idx)     = h2pack(a0, a1);
                *(uint32_t*)(sm3 + A_OFF + idx + 2) = h2pack(a2, a3);
            }
        }
        // ---- B (LayerNormed x) -> fp16 hi/lo ----
        {
            #pragma unroll
            for (int j = 0; j < 8; j++) {
                float vv[4] = {xv[j].x, xv[j].y, xv[j].z, xv[j].w};
                float xn[4];
                #pragma unroll
                for (int e = 0; e < 4; e++) {
                    float2 st = stat_s[l0B + 4*j + e];
                    xn[e] = (vv[e] - st.x) * st.y * ggB + bbB;
                }
                uint32_t hi0, lo0, hi1, lo1;
                h2split(xn[0], xn[1], hi0, lo0);
                h2split(xn[2], xn[3], hi1, lo1);
                int idx = cB*APITCH + l0B + 4*j;
                *(uint32_t*)(sm3 + BH_OFF + idx)     = hi0;
                *(uint32_t*)(sm3 + BH_OFF + idx + 2) = hi1;
                *(uint32_t*)(sm3 + BL_OFF + idx)     = lo0;
                *(uint32_t*)(sm3 + BL_OFF + idx + 2) = lo1;
            }
        }
        __syncthreads();

        // ---- MMA: 4 k-steps of 16, 2 passes (A*Bh + A*Bl) ----
        #pragma unroll
        for (int ks = 0; ks < 4; ks++) {
            const int k0 = ks*16;
            uint32_t ah[2][4];
            #pragma unroll
            for (int i = 0; i < 2; i++) {
                const int r0 = (mw*32 + i*16 + rA) * APITCH + k0 + kA;
                const int r8 = r0 + 8*APITCH;
                ah[i][0] = *(const uint32_t*)(sm3 + A_OFF + r0);
                ah[i][1] = *(const uint32_t*)(sm3 + A_OFF + r8);
                ah[i][2] = *(const uint32_t*)(sm3 + A_OFF + r0 + 8);
                ah[i][3] = *(const uint32_t*)(sm3 + A_OFF + r8 + 8);
            }
            #pragma unroll
            for (int j = 0; j < 8; j++) {
                const int c0 = (nw*64 + j*8 + nB) * APITCH + k0 + kB;
                uint32_t bh[2], bl[2];
                bh[0] = *(const uint32_t*)(sm3 + BH_OFF + c0);
                bh[1] = *(const uint32_t*)(sm3 + BH_OFF + c0 + 8);
                bl[0] = *(const uint32_t*)(sm3 + BL_OFF + c0);
                bl[1] = *(const uint32_t*)(sm3 + BL_OFF + c0 + 8);
                #pragma unroll
                for (int i = 0; i < 2; i++) {
                    mma16816(acc[i][j], ah[i], bh);
                    mma16816(acc[i][j], ah[i], bl);
                }
            }
        }
    }

    // ---- epilogue: write P partial ----
    float* pp = g_Ppart + (((size_t)split*Bn + b)*NHQ)*Cn;
    #pragma unroll
    for (int i = 0; i < 2; i++) {
        const int row = mw*32 + i*16 + (lane >> 2);
        #pragma unroll
        for (int j = 0; j < 8; j++) {
            const int col = nw*64 + j*8 + (lane & 3)*2;
            *(float2*)(pp + (size_t)row*Cn + col)     = make_float2(acc[i][j][0], acc[i][j][1]);
            *(float2*)(pp + (size_t)(row+8)*Cn + col) = make_float2(acc[i][j][2], acc[i][j][3]);
        }
    }
}

// ---------------- K4a: reduce P partials, A = P @ val_w^T (per head) + val_b ----------------
__global__ void k4a(const float* __restrict__ val_w, const float* __restrict__ val_b)
{
    extern __shared__ float sm[];
    float* vw = sm;             // [32][257]
    float* ps = sm + 32*257;    // [16][256]
    const int h = blockIdx.x, b = blockIdx.y;
    const int tid = threadIdx.x;

    for (int i = tid; i < 32*Cn; i += 256) {
        int r = i >> 8, c = i & 255;
        vw[r*257 + c] = val_w[(size_t)(h*32 + r)*Cn + c];
    }
    for (int i = tid; i < Qn*Cn; i += 256) {
        int q = i >> 8, c = i & 255;
        int hq = h*Qn + q;
        float s = 0.f;
        #pragma unroll
        for (int sp = 0; sp < NSPLIT; sp++)
            s += g_Ppart[(((size_t)sp*Bn + b)*NHQ + hq)*Cn + c];
        ps[i] = s;
    }
    __syncthreads();

    for (int o = tid; o < Qn*32; o += 256) {
        int q = o >> 5, d = o & 31;
        float a = val_b[h*32 + d];
        #pragma unroll 4
        for (int c = 0; c < Cn; c++)
            a = fmaf(ps[q*Cn + c], vw[d*257 + c], a);
        g_A[b*4096 + (h*Qn + q)*32 + d] = a;
    }
}

// ---------------- K4b: out = A @ fin_w^T + fin_b ----------------
__global__ void kinit(float* __restrict__ out, const float* __restrict__ fin_b)
{
    out[blockIdx.x*FHn + threadIdx.x] = fin_b[threadIdx.x];
}

__global__ void k4b(const float* __restrict__ fin_w, float* __restrict__ out)
{
    __shared__ float At[64*65];
    __shared__ float Wt[32*65];
    const int ft = blockIdx.x;
    const int js = blockIdx.y;
    const int tid = threadIdx.x;
    const int ty = tid >> 5, tx = tid & 31;
    const int f0 = ft*32;

    float acc[8];
    #pragma unroll
    for (int i = 0; i < 8; i++) acc[i] = 0.f;

    for (int sub = 0; sub < 8; sub++) {
        const int j0 = js*512 + sub*64;
        __syncthreads();
        for (int i = tid; i < 64*64; i += 256) {
            int bb = i >> 6, jj = i & 63;
            At[bb*65 + jj] = g_A[bb*4096 + j0 + jj];
        }
        for (int i = tid; i < 32*64; i += 256) {
            int r = i >> 6, jj = i & 63;
            Wt[r*65 + jj] = fin_w[(size_t)(f0 + r)*4096 + j0 + jj];
        }
        __syncthreads();
        #pragma unroll 8
        for (int j = 0; j < 64; j++) {
            float w = Wt[tx*65 + j];
            #pragma unroll
            for (int i = 0; i < 8; i++)
                acc[i] = fmaf(At[(ty*8 + i)*65 + j], w, acc[i]);
        }
    }
    #pragma unroll
    for (int i = 0; i < 8; i++)
        atomicAdd(&out[(ty*8 + i)*FHn + f0 + tx], acc[i]);
}

// ---------------- launch ----------------
extern "C" void kernel_launch(void* const* d_in, const int* in_sizes, int n_in,
                              void* d_out, int out_size)
{
    const float* x    = (const float*)d_in[0];
    const float* gam  = (const float*)d_in[1];
    const float* bet  = (const float*)d_in[2];
    const float* attw = (const float*)d_in[3];
    const float* valw = (const float*)d_in[4];
    const float* valb = (const float*)d_in[5];
    const float* finw = (const float*)d_in[6];
    const float* finb = (const float*)d_in[7];
    float* out = (float*)d_out;

    const int smem_k1  = 128*129*4;
    const int smem_k4a = (32*257 + 16*Cn)*4;

    cudaFuncSetAttribute(k1,  cudaFuncAttributeMaxDynamicSharedMemorySize, smem_k1);
    cudaFuncSetAttribute(k3,  cudaFuncAttributeMaxDynamicSharedMemorySize, K3_DYN);
    cudaFuncSetAttribute(k4a, cudaFuncAttributeMaxDynamicSharedMemorySize, smem_k4a);

    k1  <<<dim3(NT1, Bn),    256, smem_k1 >>>(x, gam, bet, attw);
    k2  <<<32, 256>>>();
    k3  <<<dim3(NSPLIT, Bn), 512, K3_DYN >>>(x, gam, bet);
    k4a <<<dim3(HEADSn, Bn), 256, smem_k4a>>>(valw, valb);
    kinit<<<Bn, FHn>>>(out, finb);
    k4b <<<dim3(16, 8), 256>>>(finw, out);
}

// round 6
// speedup vs baseline: 1.7523x; 1.1018x over previous
#include <cuda_runtime.h>
#include <cuda_fp16.h>
#include <cstdint>
#include <math.h>

#define Bn      64
#define Cn      256
#define Ln      4096
#define HEADSn  8
#define Qn      16
#define Dn      32
#define NHQ     128          // HEADS*Q
#define FHn     512
#define NT1     32           // K1: L / 128
#define LT1     128
#define NSPLIT  2
#define LSP     2048         // L per split (Ln/NSPLIT)
#define KC      64           // K3 l-chunk
#define NCHUNK  (LSP/KC)     // 32
#define APITCH  72           // fp16 elems per row (144B pitch -> ldmatrix conflict-free)

// ---------------- scratch (device globals: no allocs allowed) ----------------
__device__ float  g_logits[(size_t)Bn*NHQ*Ln];            // 134 MB
__device__ float2 g_stats [Bn*Ln];                         // mean,rstd per (b,l)
__device__ float2 g_part  [Bn*NT1*NHQ];                    // per-tile (max, sumexp)
__device__ float2 g_ms    [Bn*NHQ];                        // (max, 1/sum)
__device__ float  g_Ppart [(size_t)NSPLIT*Bn*NHQ*Cn];      // 17 MB partial P
__device__ float  g_A     [Bn*NHQ*Dn];                     // Aflat [B,4096]

// ---------------- fast exp (no MUFU; pure FMA/ALU) ----------------
__device__ __forceinline__ float fexp(float x) {
    float y = x * 1.4426950408889634f;
    y = fmaxf(y, -120.0f);
    float fl = floorf(y);
    float f  = y - fl;                 // [0,1)
    float p = 1.5252733e-5f;
    p = fmaf(p, f, 1.5403530e-4f);
    p = fmaf(p, f, 1.3333558e-3f);
    p = fmaf(p, f, 9.6181291e-3f);
    p = fmaf(p, f, 5.5504109e-2f);
    p = fmaf(p, f, 2.4022651e-1f);
    p = fmaf(p, f, 6.9314718e-1f);
    p = fmaf(p, f, 1.0f);
    int i = (int)fl;
    return p * __int_as_float((i + 127) << 23);
}

// mma.sync m16n8k16 fp16 (row.col), fp32 accumulate — base-arch tensor path
__device__ __forceinline__ void mma16816(float* d, const uint32_t* a, const uint32_t* b) {
    asm volatile("mma.sync.aligned.m16n8k16.row.col.f32.f16.f16.f32 "
        "{%0,%1,%2,%3}, {%4,%5,%6,%7}, {%8,%9}, {%0,%1,%2,%3};"
        : "+f"(d[0]), "+f"(d[1]), "+f"(d[2]), "+f"(d[3])
        : "r"(a[0]), "r"(a[1]), "r"(a[2]), "r"(a[3]), "r"(b[0]), "r"(b[1]));
}

__device__ __forceinline__ void ldm_x4(uint32_t* r, uint32_t addr) {
    asm volatile("ldmatrix.sync.aligned.m8n8.x4.shared.b16 {%0,%1,%2,%3}, [%4];"
        : "=r"(r[0]), "=r"(r[1]), "=r"(r[2]), "=r"(r[3]) : "r"(addr));
}

__device__ __forceinline__ uint32_t h2pack(float v0, float v1) {
    __half2 h = __floats2half2_rn(v0, v1);
    return *reinterpret_cast<uint32_t*>(&h);
}

// ---------------- K1: LN stats + logits + per-tile softmax partials ----------------
__global__ __launch_bounds__(256) void k1(const float* __restrict__ x,
                                          const float* __restrict__ gamma,
                                          const float* __restrict__ beta,
                                          const float* __restrict__ attw)
{
    extern __shared__ float logit_s[];              // [128][129]
    __shared__ float  w_s[HEADSn*Qn*Dn];
    __shared__ float  rsum[256], rsq[256];
    __shared__ float2 stats_s[LT1];

    const int b = blockIdx.y, tile = blockIdx.x;
    const int tid  = threadIdx.x;
    const int lt   = tid & 127;
    const int half = tid >> 7;
    const int l    = tile*LT1 + lt;

    for (int i = tid; i < HEADSn*Qn*Dn; i += 256) w_s[i] = attw[i];

    const float* xb = x + (size_t)b*Cn*Ln;

    float s = 0.f, ss = 0.f;
    const int c0 = half*128;
    #pragma unroll 4
    for (int c = c0; c < c0+128; c++) {
        float v = xb[(size_t)c*Ln + l];
        s += v; ss += v*v;
    }
    rsum[tid] = s; rsq[tid] = ss;
    __syncthreads();
    if (half == 0) {
        float sum = rsum[lt] + rsum[lt+128];
        float sq  = rsq [lt] + rsq [lt+128];
        float mu  = sum * (1.f/Cn);
        float var = sq * (1.f/Cn) - mu*mu;
        float rstd = rsqrtf(var + 1e-6f);
        stats_s[lt] = make_float2(mu, rstd);
        g_stats[b*Ln + l] = make_float2(mu, rstd);
    }
    __syncthreads();
    const float mu = stats_s[lt].x, rstd = stats_s[lt].y;

    for (int hh = 0; hh < 4; hh++) {
        const int h = half*4 + hh;
        float acc[Qn];
        #pragma unroll
        for (int q = 0; q < Qn; q++) acc[q] = 0.f;
        #pragma unroll 4
        for (int cc = 0; cc < Dn; cc++) {
            const int c = h*Dn + cc;
            float xv = xb[(size_t)c*Ln + l];
            float xn = (xv - mu) * rstd * gamma[c] + beta[c];
            const float* wp = &w_s[(h*Qn)*Dn + cc];
            #pragma unroll
            for (int q = 0; q < Qn; q++)
                acc[q] = fmaf(wp[q*Dn], xn, acc[q]);
        }
        #pragma unroll
        for (int q = 0; q < Qn; q++) {
            const int hq = h*Qn + q;
            logit_s[hq*129 + lt] = acc[q];
            g_logits[((size_t)(b*NHQ + hq))*Ln + l] = acc[q];
        }
    }
    __syncthreads();

    // phase C: 2 threads per hq row, shfl combine
    {
        const int hq  = tid >> 1;
        const int sub = tid & 1;
        const float* row = &logit_s[hq*129 + sub*64];
        float m = -1e30f;
        #pragma unroll 8
        for (int k = 0; k < 64; k++) m = fmaxf(m, row[k]);
        m = fmaxf(m, __shfl_xor_sync(0xFFFFFFFFu, m, 1));
        float se = 0.f;
        #pragma unroll 4
        for (int k = 0; k < 64; k++) se += fexp(row[k] - m);
        se += __shfl_xor_sync(0xFFFFFFFFu, se, 1);
        if (sub == 0)
            g_part[(b*NT1 + tile)*NHQ + hq] = make_float2(m, se);
    }
}

// ---------------- K2: merge softmax partials ----------------
__global__ void k2()
{
    const int idx = blockIdx.x*256 + threadIdx.x;
    if (idx >= Bn*NHQ) return;
    const int b = idx >> 7, hq = idx & 127;
    float m = -1e30f;
    for (int t = 0; t < NT1; t++) m = fmaxf(m, g_part[(b*NT1 + t)*NHQ + hq].x);
    float s = 0.f;
    for (int t = 0; t < NT1; t++) {
        float2 p = g_part[(b*NT1 + t)*NHQ + hq];
        s += p.y * fexp(p.x - m);
    }
    g_ms[idx] = make_float2(m, 1.f/s);
}

// ---------------- K3: P = Aw @ xn^T via mma.sync fp16 + ldmatrix ----------------
// SMEM (fp16, K-major, pitch APITCH=72): A[128], B[256]
#define A_OFF  0
#define B_OFF  (128*APITCH)
#define K3_ELEMS (128*APITCH + 256*APITCH)
#define K3_DYN (K3_ELEMS*2)

__global__ __launch_bounds__(512, 1) void k3(const float* __restrict__ x,
                                             const float* __restrict__ gamma,
                                             const float* __restrict__ beta)
{
    extern __shared__ __half sm3[];
    __shared__ float  gm[Cn], bt[Cn];
    __shared__ float2 ms_s[NHQ];
    __shared__ float2 stat_s[KC];

    const int split = blockIdx.x, b = blockIdx.y;
    const int tid  = threadIdx.x;
    const int wid  = tid >> 5, lane = tid & 31;
    const int mw   = wid >> 2, nw = wid & 3;    // warp tile: rows [mw*32,+32) cols [nw*64,+64)

    for (int i = tid; i < Cn;  i += 512) { gm[i] = gamma[i]; bt[i] = beta[i]; }
    for (int i = tid; i < NHQ; i += 512) ms_s[i] = g_ms[b*NHQ + i];

    const float* xb = x        + (size_t)b*Cn*Ln;
    const float* lg = g_logits + (size_t)b*NHQ*Ln;

    // loader mappings
    const int hqA = tid >> 2, l0A = (tid & 3) * 16;   // A: 128 rows x 64
    const int cB  = tid >> 1, l0B = (tid & 1) * 32;   // B: 256 rows x 64
    __syncthreads();
    const float2 msA = ms_s[hqA];
    const float  ggB = gm[cB], bbB = bt[cB];

    // ldmatrix per-lane base addresses (chunk-invariant)
    const uint32_t smb = (uint32_t)__cvta_generic_to_shared(sm3);
    const int g = lane >> 3, r = lane & 7;
    // A x4 tiles: (m0-7,k0-7)(m8-15,k0-7)(m0-7,k8-15)(m8-15,k8-15)
    const uint32_t addrA0 = smb + 2u*((uint32_t)((mw*32 + ((g & 1) << 3) + r)*APITCH + ((g >> 1) << 3)));
    // B x4 tiles: (n0-7,k0-7)(n0-7,k8-15)(n8-15,k0-7)(n8-15,k8-15)
    const uint32_t addrB0 = smb + 2u*((uint32_t)(B_OFF + (nw*64 + ((g >> 1) << 3) + r)*APITCH + ((g & 1) << 3)));

    float acc[2][8][4];
    #pragma unroll
    for (int i = 0; i < 2; i++)
        #pragma unroll
        for (int j = 0; j < 8; j++)
            #pragma unroll
            for (int e = 0; e < 4; e++) acc[i][j][e] = 0.f;

    for (int t = 0; t < NCHUNK; t++) {
        const int lb = split*LSP + t*KC;

        // stats for this chunk
        float2 stv;
        if (tid < KC) stv = g_stats[b*Ln + lb + tid];

        // global loads (issued before barrier; overlap with prev MMA)
        float4 lv[4];
        {
            const float* gp = lg + (size_t)hqA*Ln + lb + l0A;
            #pragma unroll
            for (int j = 0; j < 4; j++) lv[j] = *(const float4*)(gp + 4*j);
        }
        float4 xv[8];
        {
            const float* xp = xb + (size_t)cB*Ln + lb + l0B;
            #pragma unroll
            for (int j = 0; j < 8; j++) xv[j] = *(const float4*)(xp + 4*j);
        }

        __syncthreads();              // prev chunk's MMA done reading smem
        if (tid < KC) stat_s[tid] = stv;
        __syncthreads();

        // ---- A (softmax weights) -> fp16 ----
        {
            #pragma unroll
            for (int j = 0; j < 4; j++) {
                float a0 = fexp(lv[j].x - msA.x) * msA.y;
                float a1 = fexp(lv[j].y - msA.x) * msA.y;
                float a2 = fexp(lv[j].z - msA.x) * msA.y;
                float a3 = fexp(lv[j].w - msA.x) * msA.y;
                int idx = hqA*APITCH + l0A + 4*j;
                *(uint32_t*)(sm3 + A_OFF + idx)     = h2pack(a0, a1);
                *(uint32_t*)(sm3 + A_OFF + idx + 2) = h2pack(a2, a3);
            }
        }
        // ---- B (LayerNormed x) -> fp16 ----
        {
            #pragma unroll
            for (int j = 0; j < 8; j++) {
                float vv[4] = {xv[j].x, xv[j].y, xv[j].z, xv[j].w};
                float xn[4];
                #pragma unroll
                for (int e = 0; e < 4; e++) {
                    float2 st = stat_s[l0B + 4*j + e];
                    xn[e] = (vv[e] - st.x) * st.y * ggB + bbB;
                }
                int idx = cB*APITCH + l0B + 4*j;
                *(uint32_t*)(sm3 + B_OFF + idx)     = h2pack(xn[0], xn[1]);
                *(uint32_t*)(sm3 + B_OFF + idx + 2) = h2pack(xn[2], xn[3]);
            }
        }
        __syncthreads();

        // ---- MMA: 4 k-steps of 16, ldmatrix fragments ----
        #pragma unroll
        for (int ks = 0; ks < 4; ks++) {
            uint32_t a0[4], a1[4];
            ldm_x4(a0, addrA0 + 2u*(uint32_t)(16*ks));
            ldm_x4(a1, addrA0 + 2u*(uint32_t)(16*APITCH + 16*ks));
            #pragma unroll
            for (int jj = 0; jj < 4; jj++) {
                uint32_t bfr[4];
                ldm_x4(bfr, addrB0 + 2u*(uint32_t)(16*jj*APITCH + 16*ks));
                mma16816(acc[0][2*jj],   a0, bfr);
                mma16816(acc[0][2*jj+1], a0, bfr + 2);
                mma16816(acc[1][2*jj],   a1, bfr);
                mma16816(acc[1][2*jj+1], a1, bfr + 2);
            }
        }
    }

    // ---- epilogue: write P partial ----
    float* pp = g_Ppart + (((size_t)split*Bn + b)*NHQ)*Cn;
    #pragma unroll
    for (int i = 0; i < 2; i++) {
        const int row = mw*32 + i*16 + (lane >> 2);
        #pragma unroll
        for (int j = 0; j < 8; j++) {
            const int col = nw*64 + j*8 + (lane & 3)*2;
            *(float2*)(pp + (size_t)row*Cn + col)     = make_float2(acc[i][j][0], acc[i][j][1]);
            *(float2*)(pp + (size_t)(row+8)*Cn + col) = make_float2(acc[i][j][2], acc[i][j][3]);
        }
    }
}

// ---------------- K4a: reduce P partials, A = P @ val_w^T (per head) + val_b ----------------
__global__ void k4a(const float* __restrict__ val_w, const float* __restrict__ val_b)
{
    extern __shared__ float sm[];
    float* vw = sm;             // [32][257]
    float* ps = sm + 32*257;    // [16][256]
    const int h = blockIdx.x, b = blockIdx.y;
    const int tid = threadIdx.x;

    for (int i = tid; i < 32*Cn; i += 256) {
        int r = i >> 8, c = i & 255;
        vw[r*257 + c] = val_w[(size_t)(h*32 + r)*Cn + c];
    }
    for (int i = tid; i < Qn*Cn; i += 256) {
        int q = i >> 8, c = i & 255;
        int hq = h*Qn + q;
        float s = 0.f;
        #pragma unroll
        for (int sp = 0; sp < NSPLIT; sp++)
            s += g_Ppart[(((size_t)sp*Bn + b)*NHQ + hq)*Cn + c];
        ps[i] = s;
    }
    __syncthreads();

    for (int o = tid; o < Qn*32; o += 256) {
        int q = o >> 5, d = o & 31;
        float a = val_b[h*32 + d];
        #pragma unroll 4
        for (int c = 0; c < Cn; c++)
            a = fmaf(ps[q*Cn + c], vw[d*257 + c], a);
        g_A[b*4096 + (h*Qn + q)*32 + d] = a;
    }
}

// ---------------- K4b: out = A @ fin_w^T + fin_b ----------------
__global__ void kinit(float* __restrict__ out, const float* __restrict__ fin_b)
{
    out[blockIdx.x*FHn + threadIdx.x] = fin_b[threadIdx.x];
}

__global__ void k4b(const float* __restrict__ fin_w, float* __restrict__ out)
{
    __shared__ float At[64*65];
    __shared__ float Wt[32*65];
    const int ft = blockIdx.x;
    const int js = blockIdx.y;
    const int tid = threadIdx.x;
    const int ty = tid >> 5, tx = tid & 31;
    const int f0 = ft*32;

    float acc[8];
    #pragma unroll
    for (int i = 0; i < 8; i++) acc[i] = 0.f;

    for (int sub = 0; sub < 8; sub++) {
        const int j0 = js*512 + sub*64;
        __syncthreads();
        for (int i = tid; i < 64*64; i += 256) {
            int bb = i >> 6, jj = i & 63;
            At[bb*65 + jj] = g_A[bb*4096 + j0 + jj];
        }
        for (int i = tid; i < 32*64; i += 256) {
            int r = i >> 6, jj = i & 63;
            Wt[r*65 + jj] = fin_w[(size_t)(f0 + r)*4096 + j0 + jj];
        }
        __syncthreads();
        #pragma unroll 8
        for (int j = 0; j < 64; j++) {
            float w = Wt[tx*65 + j];
            #pragma unroll
            for (int i = 0; i < 8; i++)
                acc[i] = fmaf(At[(ty*8 + i)*65 + j], w, acc[i]);
        }
    }
    #pragma unroll
    for (int i = 0; i < 8; i++)
        atomicAdd(&out[(ty*8 + i)*FHn + f0 + tx], acc[i]);
}

// ---------------- launch ----------------
extern "C" void kernel_launch(void* const* d_in, const int* in_sizes, int n_in,
                              void* d_out, int out_size)
{
    const float* x    = (const float*)d_in[0];
    const float* gam  = (const float*)d_in[1];
    const float* bet  = (const float*)d_in[2];
    const float* attw = (const float*)d_in[3];
    const float* valw = (const float*)d_in[4];
    const float* valb = (const float*)d_in[5];
    const float* finw = (const float*)d_in[6];
    const float* finb = (const float*)d_in[7];
    float* out = (float*)d_out;

    const int smem_k1  = 128*129*4;
    const int smem_k4a = (32*257 + 16*Cn)*4;

    cudaFuncSetAttribute(k1,  cudaFuncAttributeMaxDynamicSharedMemorySize, smem_k1);
    cudaFuncSetAttribute(k3,  cudaFuncAttributeMaxDynamicSharedMemorySize, K3_DYN);
    cudaFuncSetAttribute(k4a, cudaFuncAttributeMaxDynamicSharedMemorySize, smem_k4a);

    k1  <<<dim3(NT1, Bn),    256, smem_k1 >>>(x, gam, bet, attw);
    k2  <<<32, 256>>>();
    k3  <<<dim3(NSPLIT, Bn), 512, K3_DYN >>>(x, gam, bet);
    k4a <<<dim3(HEADSn, Bn), 256, smem_k4a>>>(valw, valb);
    kinit<<<Bn, FHn>>>(out, finb);
    k4b <<<dim3(16, 8), 256>>>(finw, out);
}

// round 7
// speedup vs baseline: 1.7563x; 1.0022x over previous
#include <cuda_runtime.h>
#include <cuda_fp16.h>
#include <cstdint>
#include <math.h>

#define Bn      64
#define Cn      256
#define Ln      4096
#define HEADSn  8
#define Qn      16
#define Dn      32
#define NHQ     128          // HEADS*Q
#define FHn     512
#define NT1     32           // K1: L / 128
#define LT1     128
#define NSPLIT  2
#define LSP     2048         // L per split (Ln/NSPLIT)
#define KC      64           // K3 l-chunk
#define NCHUNK  (LSP/KC)     // 32
#define APITCH  72           // fp16 elems per row (144B pitch -> ldmatrix conflict-free)
#define VWP     260          // k4a vw pitch (float4 conflict-free)

// ---------------- scratch (device globals: no allocs allowed) ----------------
__device__ float  g_logits[(size_t)Bn*NHQ*Ln];            // 134 MB
__device__ float2 g_stats [Bn*Ln];                         // mean,rstd per (b,l)
__device__ float2 g_part  [Bn*NT1*NHQ];                    // per-tile (max, sumexp)
__device__ float2 g_ms    [Bn*NHQ];                        // (max, 1/sum)
__device__ float  g_Ppart [(size_t)NSPLIT*Bn*NHQ*Cn];      // 17 MB partial P
__device__ float  g_A     [Bn*NHQ*Dn];                     // Aflat [B,4096]

// ---------------- fast exp (no MUFU; pure FMA/ALU) ----------------
__device__ __forceinline__ float fexp(float x) {
    float y = x * 1.4426950408889634f;
    y = fmaxf(y, -120.0f);
    float fl = floorf(y);
    float f  = y - fl;                 // [0,1)
    float p = 1.5252733e-5f;
    p = fmaf(p, f, 1.5403530e-4f);
    p = fmaf(p, f, 1.3333558e-3f);
    p = fmaf(p, f, 9.6181291e-3f);
    p = fmaf(p, f, 5.5504109e-2f);
    p = fmaf(p, f, 2.4022651e-1f);
    p = fmaf(p, f, 6.9314718e-1f);
    p = fmaf(p, f, 1.0f);
    int i = (int)fl;
    return p * __int_as_float((i + 127) << 23);
}

// mma.sync m16n8k16 fp16 (row.col), fp32 accumulate — base-arch tensor path
__device__ __forceinline__ void mma16816(float* d, const uint32_t* a, const uint32_t* b) {
    asm volatile("mma.sync.aligned.m16n8k16.row.col.f32.f16.f16.f32 "
        "{%0,%1,%2,%3}, {%4,%5,%6,%7}, {%8,%9}, {%0,%1,%2,%3};"
        : "+f"(d[0]), "+f"(d[1]), "+f"(d[2]), "+f"(d[3])
        : "r"(a[0]), "r"(a[1]), "r"(a[2]), "r"(a[3]), "r"(b[0]), "r"(b[1]));
}

__device__ __forceinline__ void ldm_x4(uint32_t* r, uint32_t addr) {
    asm volatile("ldmatrix.sync.aligned.m8n8.x4.shared.b16 {%0,%1,%2,%3}, [%4];"
        : "=r"(r[0]), "=r"(r[1]), "=r"(r[2]), "=r"(r[3]) : "r"(addr));
}

__device__ __forceinline__ uint32_t h2pack(float v0, float v1) {
    __half2 h = __floats2half2_rn(v0, v1);
    return *reinterpret_cast<uint32_t*>(&h);
}

// ---------------- K1: LN stats + logits + per-tile softmax partials ----------------
__global__ __launch_bounds__(256) void k1(const float* __restrict__ x,
                                          const float* __restrict__ gamma,
                                          const float* __restrict__ beta,
                                          const float* __restrict__ attw)
{
    extern __shared__ float logit_s[];              // [128][129]
    __shared__ float  w_s[HEADSn*Dn*Qn];            // [h][c][q] transposed
    __shared__ float  rsum[256], rsq[256];
    __shared__ float2 stats_s[LT1];

    const int b = blockIdx.y, tile = blockIdx.x;
    const int tid  = threadIdx.x;
    const int lt   = tid & 127;
    const int half = tid >> 7;
    const int l    = tile*LT1 + lt;

    // transpose attw [h][q][c] -> w_s [h][c][q]
    for (int i = tid; i < HEADSn*Qn*Dn; i += 256) {
        int h = i >> 9, rem = i & 511;
        int q = rem >> 5, c = rem & 31;
        w_s[h*512 + c*Qn + q] = attw[i];
    }

    const float* xb = x + (size_t)b*Cn*Ln;

    float s = 0.f, ss = 0.f;
    const int c0 = half*128;
    #pragma unroll 4
    for (int c = c0; c < c0+128; c++) {
        float v = xb[(size_t)c*Ln + l];
        s += v; ss += v*v;
    }
    rsum[tid] = s; rsq[tid] = ss;
    __syncthreads();
    if (half == 0) {
        float sum = rsum[lt] + rsum[lt+128];
        float sq  = rsq [lt] + rsq [lt+128];
        float mu  = sum * (1.f/Cn);
        float var = sq * (1.f/Cn) - mu*mu;
        float rstd = rsqrtf(var + 1e-6f);
        stats_s[lt] = make_float2(mu, rstd);
        g_stats[b*Ln + l] = make_float2(mu, rstd);
    }
    __syncthreads();
    const float mu = stats_s[lt].x, rstd = stats_s[lt].y;

    for (int hh = 0; hh < 4; hh++) {
        const int h = half*4 + hh;
        float acc[Qn];
        #pragma unroll
        for (int q = 0; q < Qn; q++) acc[q] = 0.f;
        const float* wh = &w_s[h*512];
        #pragma unroll 4
        for (int cc = 0; cc < Dn; cc++) {
            const int c = h*Dn + cc;
            float xv = xb[(size_t)c*Ln + l];
            float xn = (xv - mu) * rstd * gamma[c] + beta[c];
            const float4* wp = (const float4*)&wh[cc*Qn];
            float4 w0 = wp[0], w1 = wp[1], w2 = wp[2], w3 = wp[3];
            acc[0]  = fmaf(w0.x, xn, acc[0]);
            acc[1]  = fmaf(w0.y, xn, acc[1]);
            acc[2]  = fmaf(w0.z, xn, acc[2]);
            acc[3]  = fmaf(w0.w, xn, acc[3]);
            acc[4]  = fmaf(w1.x, xn, acc[4]);
            acc[5]  = fmaf(w1.y, xn, acc[5]);
            acc[6]  = fmaf(w1.z, xn, acc[6]);
            acc[7]  = fmaf(w1.w, xn, acc[7]);
            acc[8]  = fmaf(w2.x, xn, acc[8]);
            acc[9]  = fmaf(w2.y, xn, acc[9]);
            acc[10] = fmaf(w2.z, xn, acc[10]);
            acc[11] = fmaf(w2.w, xn, acc[11]);
            acc[12] = fmaf(w3.x, xn, acc[12]);
            acc[13] = fmaf(w3.y, xn, acc[13]);
            acc[14] = fmaf(w3.z, xn, acc[14]);
            acc[15] = fmaf(w3.w, xn, acc[15]);
        }
        #pragma unroll
        for (int q = 0; q < Qn; q++) {
            const int hq = h*Qn + q;
            logit_s[hq*129 + lt] = acc[q];
            g_logits[((size_t)(b*NHQ + hq))*Ln + l] = acc[q];
        }
    }
    __syncthreads();

    // phase C: 2 threads per hq row, shfl combine
    {
        const int hq  = tid >> 1;
        const int sub = tid & 1;
        const float* row = &logit_s[hq*129 + sub*64];
        float m = -1e30f;
        #pragma unroll 8
        for (int k = 0; k < 64; k++) m = fmaxf(m, row[k]);
        m = fmaxf(m, __shfl_xor_sync(0xFFFFFFFFu, m, 1));
        float se = 0.f;
        #pragma unroll 4
        for (int k = 0; k < 64; k++) se += fexp(row[k] - m);
        se += __shfl_xor_sync(0xFFFFFFFFu, se, 1);
        if (sub == 0)
            g_part[(b*NT1 + tile)*NHQ + hq] = make_float2(m, se);
    }
}

// ---------------- K2: merge softmax partials ----------------
__global__ void k2()
{
    const int idx = blockIdx.x*256 + threadIdx.x;
    if (idx >= Bn*NHQ) return;
    const int b = idx >> 7, hq = idx & 127;
    float m = -1e30f;
    for (int t = 0; t < NT1; t++) m = fmaxf(m, g_part[(b*NT1 + t)*NHQ + hq].x);
    float s = 0.f;
    for (int t = 0; t < NT1; t++) {
        float2 p = g_part[(b*NT1 + t)*NHQ + hq];
        s += p.y * fexp(p.x - m);
    }
    g_ms[idx] = make_float2(m, 1.f/s);
}

// ---------------- K3: P = Aw @ xn^T via mma.sync fp16 + ldmatrix ----------------
// SMEM (fp16, K-major, pitch APITCH=72): A[128], B[256]
#define A_OFF  0
#define B_OFF  (128*APITCH)
#define K3_ELEMS (128*APITCH + 256*APITCH)
#define K3_DYN (K3_ELEMS*2)

__global__ __launch_bounds__(512, 1) void k3(const float* __restrict__ x,
                                             const float* __restrict__ gamma,
                                             const float* __restrict__ beta)
{
    extern __shared__ __half sm3[];
    __shared__ float  gm[Cn], bt[Cn];
    __shared__ float2 ms_s[NHQ];
    __shared__ float2 stat_s[KC];

    const int split = blockIdx.x, b = blockIdx.y;
    const int tid  = threadIdx.x;
    const int wid  = tid >> 5, lane = tid & 31;
    const int mw   = wid >> 2, nw = wid & 3;    // warp tile: rows [mw*32,+32) cols [nw*64,+64)

    for (int i = tid; i < Cn;  i += 512) { gm[i] = gamma[i]; bt[i] = beta[i]; }
    for (int i = tid; i < NHQ; i += 512) ms_s[i] = g_ms[b*NHQ + i];

    const float* xb = x        + (size_t)b*Cn*Ln;
    const float* lg = g_logits + (size_t)b*NHQ*Ln;

    // loader mappings
    const int hqA = tid >> 2, l0A = (tid & 3) * 16;   // A: 128 rows x 64
    const int cB  = tid >> 1, l0B = (tid & 1) * 32;   // B: 256 rows x 64
    __syncthreads();
    const float2 msA = ms_s[hqA];
    const float  ggB = gm[cB], bbB = bt[cB];

    // ldmatrix per-lane base addresses (chunk-invariant)
    const uint32_t smb = (uint32_t)__cvta_generic_to_shared(sm3);
    const int g = lane >> 3, r = lane & 7;
    // A x4 tiles: (m0-7,k0-7)(m8-15,k0-7)(m0-7,k8-15)(m8-15,k8-15)
    const uint32_t addrA0 = smb + 2u*((uint32_t)((mw*32 + ((g & 1) << 3) + r)*APITCH + ((g >> 1) << 3)));
    // B x4 tiles: (n0-7,k0-7)(n0-7,k8-15)(n8-15,k0-7)(n8-15,k8-15)
    const uint32_t addrB0 = smb + 2u*((uint32_t)(B_OFF + (nw*64 + ((g >> 1) << 3) + r)*APITCH + ((g & 1) << 3)));

    float acc[2][8][4];
    #pragma unroll
    for (int i = 0; i < 2; i++)
        #pragma unroll
        for (int j = 0; j < 8; j++)
            #pragma unroll
            for (int e = 0; e < 4; e++) acc[i][j][e] = 0.f;

    for (int t = 0; t < NCHUNK; t++) {
        const int lb = split*LSP + t*KC;

        // stats for this chunk
        float2 stv;
        if (tid < KC) stv = g_stats[b*Ln + lb + tid];

        // global loads (issued before barrier; overlap with prev MMA)
        float4 lv[4];
        {
            const float* gp = lg + (size_t)hqA*Ln + lb + l0A;
            #pragma unroll
            for (int j = 0; j < 4; j++) lv[j] = *(const float4*)(gp + 4*j);
        }
        float4 xv[8];
        {
            const float* xp = xb + (size_t)cB*Ln + lb + l0B;
            #pragma unroll
            for (int j = 0; j < 8; j++) xv[j] = *(const float4*)(xp + 4*j);
        }

        __syncthreads();              // prev chunk's MMA done reading smem
        if (tid < KC) stat_s[tid] = stv;
        __syncthreads();

        // ---- A (softmax weights) -> fp16 ----
        {
            #pragma unroll
            for (int j = 0; j < 4; j++) {
                float a0 = fexp(lv[j].x - msA.x) * msA.y;
                float a1 = fexp(lv[j].y - msA.x) * msA.y;
                float a2 = fexp(lv[j].z - msA.x) * msA.y;
                float a3 = fexp(lv[j].w - msA.x) * msA.y;
                int idx = hqA*APITCH + l0A + 4*j;
                *(uint32_t*)(sm3 + A_OFF + idx)     = h2pack(a0, a1);
                *(uint32_t*)(sm3 + A_OFF + idx + 2) = h2pack(a2, a3);
            }
        }
        // ---- B (LayerNormed x) -> fp16 ----
        {
            #pragma unroll
            for (int j = 0; j < 8; j++) {
                float vv[4] = {xv[j].x, xv[j].y, xv[j].z, xv[j].w};
                float xn[4];
                #pragma unroll
                for (int e = 0; e < 4; e++) {
                    float2 st = stat_s[l0B + 4*j + e];
                    xn[e] = (vv[e] - st.x) * st.y * ggB + bbB;
                }
                int idx = cB*APITCH + l0B + 4*j;
                *(uint32_t*)(sm3 + B_OFF + idx)     = h2pack(xn[0], xn[1]);
                *(uint32_t*)(sm3 + B_OFF + idx + 2) = h2pack(xn[2], xn[3]);
            }
        }
        __syncthreads();

        // ---- MMA: 4 k-steps of 16, ldmatrix fragments ----
        #pragma unroll
        for (int ks = 0; ks < 4; ks++) {
            uint32_t a0[4], a1[4];
            ldm_x4(a0, addrA0 + 2u*(uint32_t)(16*ks));
            ldm_x4(a1, addrA0 + 2u*(uint32_t)(16*APITCH + 16*ks));
            #pragma unroll
            for (int jj = 0; jj < 4; jj++) {
                uint32_t bfr[4];
                ldm_x4(bfr, addrB0 + 2u*(uint32_t)(16*jj*APITCH + 16*ks));
                mma16816(acc[0][2*jj],   a0, bfr);
                mma16816(acc[0][2*jj+1], a0, bfr + 2);
                mma16816(acc[1][2*jj],   a1, bfr);
                mma16816(acc[1][2*jj+1], a1, bfr + 2);
            }
        }
    }

    // ---- epilogue: write P partial ----
    float* pp = g_Ppart + (((size_t)split*Bn + b)*NHQ)*Cn;
    #pragma unroll
    for (int i = 0; i < 2; i++) {
        const int row = mw*32 + i*16 + (lane >> 2);
        #pragma unroll
        for (int j = 0; j < 8; j++) {
            const int col = nw*64 + j*8 + (lane & 3)*2;
            *(float2*)(pp + (size_t)row*Cn + col)     = make_float2(acc[i][j][0], acc[i][j][1]);
            *(float2*)(pp + (size_t)(row+8)*Cn + col) = make_float2(acc[i][j][2], acc[i][j][3]);
        }
    }
}

// ---------------- K4a: reduce P partials, A = P @ val_w^T (per head) + val_b ----------------
__global__ void k4a(const float* __restrict__ val_w, const float* __restrict__ val_b)
{
    extern __shared__ float sm[];
    float* vw = sm;             // [32][VWP]
    float* ps = sm + 32*VWP;    // [16][256]
    const int h = blockIdx.x, b = blockIdx.y;
    const int tid = threadIdx.x;

    // stage val_w rows (float4)
    for (int i = tid*4; i < 32*Cn; i += 256*4) {
        int r = i >> 8, c = i & 255;
        float4 v = *(const float4*)&val_w[(size_t)(h*32 + r)*Cn + c];
        *(float4*)&vw[r*VWP + c] = v;
    }
    // reduce P partials (float4)
    for (int i = tid*4; i < Qn*Cn; i += 256*4) {
        int q = i >> 8, c = i & 255;
        int hq = h*Qn + q;
        float4 s0 = *(const float4*)&g_Ppart[(((size_t)0*Bn + b)*NHQ + hq)*Cn + c];
        float4 s1 = *(const float4*)&g_Ppart[(((size_t)1*Bn + b)*NHQ + hq)*Cn + c];
        *(float4*)&ps[i] = make_float4(s0.x + s1.x, s0.y + s1.y, s0.z + s1.z, s0.w + s1.w);
    }
    __syncthreads();

    for (int o = tid; o < Qn*32; o += 256) {
        int q = o >> 5, d = o & 31;
        float a = val_b[h*32 + d];
        #pragma unroll 8
        for (int c = 0; c < Cn; c += 4) {
            float4 pv = *(const float4*)&ps[q*Cn + c];
            float4 wv = *(const float4*)&vw[d*VWP + c];
            a = fmaf(pv.x, wv.x, a);
            a = fmaf(pv.y, wv.y, a);
            a = fmaf(pv.z, wv.z, a);
            a = fmaf(pv.w, wv.w, a);
        }
        g_A[b*4096 + (h*Qn + q)*32 + d] = a;
    }
}

// ---------------- K4b: out = A @ fin_w^T + fin_b ----------------
__global__ void kinit(float* __restrict__ out, const float* __restrict__ fin_b)
{
    out[blockIdx.x*FHn + threadIdx.x] = fin_b[threadIdx.x];
}

__global__ void k4b(const float* __restrict__ fin_w, float* __restrict__ out)
{
    __shared__ float At[64*65];
    __shared__ float Wt[32*65];
    const int ft = blockIdx.x;
    const int js = blockIdx.y;
    const int tid = threadIdx.x;
    const int ty = tid >> 5, tx = tid & 31;
    const int f0 = ft*32;

    float acc[8];
    #pragma unroll
    for (int i = 0; i < 8; i++) acc[i] = 0.f;

    for (int sub = 0; sub < 8; sub++) {
        const int j0 = js*512 + sub*64;
        __syncthreads();
        for (int i = tid; i < 64*64; i += 256) {
            int bb = i >> 6, jj = i & 63;
            At[bb*65 + jj] = g_A[bb*4096 + j0 + jj];
        }
        for (int i = tid; i < 32*64; i += 256) {
            int r = i >> 6, jj = i & 63;
            Wt[r*65 + jj] = fin_w[(size_t)(f0 + r)*4096 + j0 + jj];
        }
        __syncthreads();
        #pragma unroll 8
        for (int j = 0; j < 64; j++) {
            float w = Wt[tx*65 + j];
            #pragma unroll
            for (int i = 0; i < 8; i++)
                acc[i] = fmaf(At[(ty*8 + i)*65 + j], w, acc[i]);
        }
    }
    #pragma unroll
    for (int i = 0; i < 8; i++)
        atomicAdd(&out[(ty*8 + i)*FHn + f0 + tx], acc[i]);
}

// ---------------- launch ----------------
extern "C" void kernel_launch(void* const* d_in, const int* in_sizes, int n_in,
                              void* d_out, int out_size)
{
    const float* x    = (const float*)d_in[0];
    const float* gam  = (const float*)d_in[1];
    const float* bet  = (const float*)d_in[2];
    const float* attw = (const float*)d_in[3];
    const float* valw = (const float*)d_in[4];
    const float* valb = (const float*)d_in[5];
    const float* finw = (const float*)d_in[6];
    const float* finb = (const float*)d_in[7];
    float* out = (float*)d_out;

    const int smem_k1  = 128*129*4;
    const int smem_k4a = (32*VWP + 16*Cn)*4;

    cudaFuncSetAttribute(k1,  cudaFuncAttributeMaxDynamicSharedMemorySize, smem_k1);
    cudaFuncSetAttribute(k3,  cudaFuncAttributeMaxDynamicSharedMemorySize, K3_DYN);
    cudaFuncSetAttribute(k4a, cudaFuncAttributeMaxDynamicSharedMemorySize, smem_k4a);

    k1  <<<dim3(NT1, Bn),    256, smem_k1 >>>(x, gam, bet, attw);
    k2  <<<32, 256>>>();
    k3  <<<dim3(NSPLIT, Bn), 512, K3_DYN >>>(x, gam, bet);
    k4a <<<dim3(HEADSn, Bn), 256, smem_k4a>>>(valw, valb);
    kinit<<<Bn, FHn>>>(out, finb);
    k4b <<<dim3(16, 8), 256>>>(finw, out);
}

// round 8
// speedup vs baseline: 1.9681x; 1.1206x over previous
#include <cuda_runtime.h>
#include <cuda_fp16.h>
#include <cstdint>
#include <math.h>

#define Bn      64
#define Cn      256
#define Ln      4096
#define HEADSn  8
#define Qn      16
#define Dn      32
#define NHQ     128          // HEADS*Q
#define FHn     512
#define NT1     32           // K1: L / 128
#define LT1     128
#define NSPLIT  2
#define LSP     2048         // L per split (Ln/NSPLIT)
#define KC      64           // K3 l-chunk
#define NCHUNK  (LSP/KC)     // 32
#define APITCH  72           // fp16 elems per row (144B pitch -> ldmatrix conflict-free)
#define VWP     260          // k4a vw pitch (float4 conflict-free)

// ---------------- scratch (device globals: no allocs allowed) ----------------
__device__ __half  g_E  [(size_t)Bn*NHQ*Ln];               // 67 MB  exp(logit - m_tile), fp16
__device__ __half  g_xn [(size_t)Bn*Cn*Ln];                // 134 MB LayerNormed x, fp16
__device__ float2  g_part[Bn*NT1*NHQ];                     // per-tile (max, sumexp)
__device__ float2  g_ms  [Bn*NHQ];                         // (max, 1/sum)
__device__ float   g_Ppart[(size_t)NSPLIT*Bn*NHQ*Cn];      // 17 MB partial P
__device__ float   g_A   [Bn*NHQ*Dn];                      // Aflat [B,4096]

// ---------------- fast exp (no MUFU; pure FMA/ALU) ----------------
__device__ __forceinline__ float fexp(float x) {
    float y = x * 1.4426950408889634f;
    y = fmaxf(y, -120.0f);
    float fl = floorf(y);
    float f  = y - fl;                 // [0,1)
    float p = 1.5252733e-5f;
    p = fmaf(p, f, 1.5403530e-4f);
    p = fmaf(p, f, 1.3333558e-3f);
    p = fmaf(p, f, 9.6181291e-3f);
    p = fmaf(p, f, 5.5504109e-2f);
    p = fmaf(p, f, 2.4022651e-1f);
    p = fmaf(p, f, 6.9314718e-1f);
    p = fmaf(p, f, 1.0f);
    int i = (int)fl;
    return p * __int_as_float((i + 127) << 23);
}

// mma.sync m16n8k16 fp16 (row.col), fp32 accumulate — base-arch tensor path
__device__ __forceinline__ void mma16816(float* d, const uint32_t* a, const uint32_t* b) {
    asm volatile("mma.sync.aligned.m16n8k16.row.col.f32.f16.f16.f32 "
        "{%0,%1,%2,%3}, {%4,%5,%6,%7}, {%8,%9}, {%0,%1,%2,%3};"
        : "+f"(d[0]), "+f"(d[1]), "+f"(d[2]), "+f"(d[3])
        : "r"(a[0]), "r"(a[1]), "r"(a[2]), "r"(a[3]), "r"(b[0]), "r"(b[1]));
}

__device__ __forceinline__ void ldm_x4(uint32_t* r, uint32_t addr) {
    asm volatile("ldmatrix.sync.aligned.m8n8.x4.shared.b16 {%0,%1,%2,%3}, [%4];"
        : "=r"(r[0]), "=r"(r[1]), "=r"(r[2]), "=r"(r[3]) : "r"(addr));
}

#define CP_ASYNC16(dst, src) \
    asm volatile("cp.async.ca.shared.global [%0], [%1], 16;" :: "r"(dst), "l"(src) : "memory")
#define CP_COMMIT()  asm volatile("cp.async.commit_group;" ::: "memory")
#define CP_WAIT1()   asm volatile("cp.async.wait_group 1;" ::: "memory")
#define CP_WAIT0()   asm volatile("cp.async.wait_group 0;" ::: "memory")

// ---------------- K1: LN stats + logits + softmax partials + E/xn fp16 stores ----------------
__global__ __launch_bounds__(256) void k1(const float* __restrict__ x,
                                          const float* __restrict__ gamma,
                                          const float* __restrict__ beta,
                                          const float* __restrict__ attw)
{
    extern __shared__ float logit_s[];              // [128][129]
    __shared__ float  w_s[HEADSn*Dn*Qn];            // [h][c][q] transposed
    __shared__ float  rsum[256], rsq[256];
    __shared__ float2 stats_s[LT1];

    const int b = blockIdx.y, tile = blockIdx.x;
    const int tid  = threadIdx.x;
    const int lt   = tid & 127;
    const int half = tid >> 7;
    const int l    = tile*LT1 + lt;

    // transpose attw [h][q][c] -> w_s [h][c][q]
    for (int i = tid; i < HEADSn*Qn*Dn; i += 256) {
        int h = i >> 9, rem = i & 511;
        int q = rem >> 5, c = rem & 31;
        w_s[h*512 + c*Qn + q] = attw[i];
    }

    const float* xb = x + (size_t)b*Cn*Ln;

    float s = 0.f, ss = 0.f;
    const int c0 = half*128;
    #pragma unroll 4
    for (int c = c0; c < c0+128; c++) {
        float v = xb[(size_t)c*Ln + l];
        s += v; ss += v*v;
    }
    rsum[tid] = s; rsq[tid] = ss;
    __syncthreads();
    if (half == 0) {
        float sum = rsum[lt] + rsum[lt+128];
        float sq  = rsq [lt] + rsq [lt+128];
        float mu  = sum * (1.f/Cn);
        float var = sq * (1.f/Cn) - mu*mu;
        float rstd = rsqrtf(var + 1e-6f);
        stats_s[lt] = make_float2(mu, rstd);
    }
    __syncthreads();
    const float mu = stats_s[lt].x, rstd = stats_s[lt].y;

    __half* xnb = g_xn + (size_t)b*Cn*Ln;

    for (int hh = 0; hh < 4; hh++) {
        const int h = half*4 + hh;
        float acc[Qn];
        #pragma unroll
        for (int q = 0; q < Qn; q++) acc[q] = 0.f;
        const float* wh = &w_s[h*512];
        #pragma unroll 4
        for (int cc = 0; cc < Dn; cc++) {
            const int c = h*Dn + cc;
            float xv = xb[(size_t)c*Ln + l];
            float xn = (xv - mu) * rstd * gamma[c] + beta[c];
            xnb[(size_t)c*Ln + l] = __float2half_rn(xn);   // fp16 xn side-product
            const float4* wp = (const float4*)&wh[cc*Qn];
            float4 w0 = wp[0], w1 = wp[1], w2 = wp[2], w3 = wp[3];
            acc[0]  = fmaf(w0.x, xn, acc[0]);
            acc[1]  = fmaf(w0.y, xn, acc[1]);
            acc[2]  = fmaf(w0.z, xn, acc[2]);
            acc[3]  = fmaf(w0.w, xn, acc[3]);
            acc[4]  = fmaf(w1.x, xn, acc[4]);
            acc[5]  = fmaf(w1.y, xn, acc[5]);
            acc[6]  = fmaf(w1.z, xn, acc[6]);
            acc[7]  = fmaf(w1.w, xn, acc[7]);
            acc[8]  = fmaf(w2.x, xn, acc[8]);
            acc[9]  = fmaf(w2.y, xn, acc[9]);
            acc[10] = fmaf(w2.z, xn, acc[10]);
            acc[11] = fmaf(w2.w, xn, acc[11]);
            acc[12] = fmaf(w3.x, xn, acc[12]);
            acc[13] = fmaf(w3.y, xn, acc[13]);
            acc[14] = fmaf(w3.z, xn, acc[14]);
            acc[15] = fmaf(w3.w, xn, acc[15]);
        }
        #pragma unroll
        for (int q = 0; q < Qn; q++)
            logit_s[(h*Qn + q)*129 + lt] = acc[q];
    }
    __syncthreads();

    // phase C+D: per-hq tile max/sumexp + store E = exp(logit - m_tile) fp16
    {
        const int hq  = tid >> 1;
        const int sub = tid & 1;
        const float* row = &logit_s[hq*129 + sub*64];
        float m = -1e30f;
        #pragma unroll 8
        for (int k = 0; k < 64; k++) m = fmaxf(m, row[k]);
        m = fmaxf(m, __shfl_xor_sync(0xFFFFFFFFu, m, 1));

        __half2 out2[32];
        float se = 0.f;
        #pragma unroll 4
        for (int k = 0; k < 32; k++) {
            float e0 = fexp(row[2*k]   - m);
            float e1 = fexp(row[2*k+1] - m);
            se += e0 + e1;
            out2[k] = __floats2half2_rn(e0, e1);
        }
        se += __shfl_xor_sync(0xFFFFFFFFu, se, 1);
        if (sub == 0)
            g_part[(b*NT1 + tile)*NHQ + hq] = make_float2(m, se);

        __half* ep = g_E + (size_t)(b*NHQ + hq)*Ln + tile*LT1 + sub*64;
        #pragma unroll
        for (int u = 0; u < 8; u++)
            *(uint4*)(ep + u*8) = *(uint4*)(out2 + u*4);
    }
}

// ---------------- K2: merge softmax partials ----------------
__global__ void k2()
{
    const int idx = blockIdx.x*256 + threadIdx.x;
    if (idx >= Bn*NHQ) return;
    const int b = idx >> 7, hq = idx & 127;
    float m = -1e30f;
    for (int t = 0; t < NT1; t++) m = fmaxf(m, g_part[(b*NT1 + t)*NHQ + hq].x);
    float s = 0.f;
    for (int t = 0; t < NT1; t++) {
        float2 p = g_part[(b*NT1 + t)*NHQ + hq];
        s += p.y * fexp(p.x - m);
    }
    g_ms[idx] = make_float2(m, 1.f/s);
}

// ---------------- K3: P = Aw @ xn^T, pure fp16 GEMM, cp.async double-buffered ----------------
// SMEM per buffer (fp16, K-major, pitch 72): A[128], B[256]; two buffers
#define A_OFF  0
#define B_OFF  (128*APITCH)
#define TILE_HALVES (128*APITCH + 256*APITCH)   // 27648
#define TILE_BYTES  (TILE_HALVES*2)             // 55296
#define K3_DYN (2*TILE_BYTES)                   // 110592

__global__ __launch_bounds__(512, 1) void k3()
{
    extern __shared__ __half sm3[];
    __shared__ float2 ms_s[NHQ];

    const int split = blockIdx.x, b = blockIdx.y;
    const int tid  = threadIdx.x;
    const int wid  = tid >> 5, lane = tid & 31;
    const int mw   = wid >> 2, nw = wid & 3;

    for (int i = tid; i < NHQ; i += 512) ms_s[i] = g_ms[b*NHQ + i];

    // loader mappings
    const int hqA = tid >> 2, l0A = (tid & 3) * 16;   // A: 128 rows x 64
    const int cB  = tid >> 1, l0B = (tid & 1) * 32;   // B: 256 rows x 64
    __syncthreads();
    const float m_g = ms_s[hqA].x, inv_s = ms_s[hqA].y;

    const __half* eA = g_E  + (size_t)(b*NHQ + hqA)*Ln + split*LSP + l0A;
    const __half* xB = g_xn + ((size_t)b*Cn + cB)*Ln   + split*LSP + l0B;
    const float2* gp = g_part + (b*NT1 + split*(NT1/NSPLIT))*NHQ + hqA;

    const uint32_t smb = (uint32_t)__cvta_generic_to_shared(sm3);
    const uint32_t dstB = smb + 2u*(uint32_t)(B_OFF + cB*APITCH + l0B);
    const uint32_t dstA = smb + 2u*(uint32_t)(A_OFF + hqA*APITCH + l0A);

    // ldmatrix per-lane base addresses (buffer 0)
    const int g = lane >> 3, r = lane & 7;
    const uint32_t addrA0 = smb + 2u*((uint32_t)((mw*32 + ((g & 1) << 3) + r)*APITCH + ((g >> 1) << 3)));
    const uint32_t addrB0 = smb + 2u*((uint32_t)(B_OFF + (nw*64 + ((g >> 1) << 3) + r)*APITCH + ((g & 1) << 3)));

    float acc[2][8][4];
    #pragma unroll
    for (int i = 0; i < 2; i++)
        #pragma unroll
        for (int j = 0; j < 8; j++)
            #pragma unroll
            for (int e = 0; e < 4; e++) acc[i][j][e] = 0.f;

    // ---- prologue: stage chunk 0 ----
    {
        const __half* src = xB;
        CP_ASYNC16(dstB +  0, src);
        CP_ASYNC16(dstB + 16, src + 8);
        CP_ASYNC16(dstB + 32, src + 16);
        CP_ASYNC16(dstB + 48, src + 24);
        CP_COMMIT();
    }
    uint4 aregs[2];
    aregs[0] = *(const uint4*)(eA);
    aregs[1] = *(const uint4*)(eA + 8);
    float2 p0 = gp[0];
    float fcur = fexp(p0.x - m_g) * inv_s;

    for (int t = 0; t < NCHUNK; t++) {
        const uint32_t bufo = (uint32_t)((t & 1) * TILE_BYTES);
        const uint32_t nbufo = (uint32_t)(((t + 1) & 1) * TILE_BYTES);

        uint4 anext[2];
        float fnext = 0.f;
        if (t + 1 < NCHUNK) {
            // issue B cp.async for t+1 into other buffer (safe: MMA(t-1) done)
            const __half* src = xB + (t + 1)*KC;
            CP_ASYNC16(nbufo + dstB +  0, src);
            CP_ASYNC16(nbufo + dstB + 16, src + 8);
            CP_ASYNC16(nbufo + dstB + 32, src + 16);
            CP_ASYNC16(nbufo + dstB + 48, src + 24);
            CP_COMMIT();
            const __half* ea = eA + (t + 1)*KC;
            anext[0] = *(const uint4*)(ea);
            anext[1] = *(const uint4*)(ea + 8);
            float2 pn = gp[((t + 1) >> 1)*NHQ];
            fnext = fexp(pn.x - m_g) * inv_s;
        }

        // convert+store A(t) into current buffer (safe: MMA(t-2) done)
        {
            const float f = fcur;
            #pragma unroll
            for (int u = 0; u < 2; u++) {
                uint32_t w[4] = {aregs[u].x, aregs[u].y, aregs[u].z, aregs[u].w};
                uint32_t o[4];
                #pragma unroll
                for (int j = 0; j < 4; j++) {
                    __half2 h = *reinterpret_cast<__half2*>(&w[j]);
                    float2 v = __half22float2(h);
                    __half2 rr = __floats2half2_rn(v.x * f, v.y * f);
                    o[j] = *reinterpret_cast<uint32_t*>(&rr);
                }
                *(uint4*)(sm3 + (bufo >> 1) + A_OFF + hqA*APITCH + l0A + u*8) =
                    make_uint4(o[0], o[1], o[2], o[3]);
            }
        }

        if (t + 1 < NCHUNK) CP_WAIT1(); else CP_WAIT0();
        __syncthreads();

        // ---- MMA(t) ----
        #pragma unroll
        for (int ks = 0; ks < 4; ks++) {
            uint32_t a0[4], a1[4];
            ldm_x4(a0, bufo + addrA0 + 2u*(uint32_t)(16*ks));
            ldm_x4(a1, bufo + addrA0 + 2u*(uint32_t)(16*APITCH + 16*ks));
            #pragma unroll
            for (int jj = 0; jj < 4; jj++) {
                uint32_t bfr[4];
                ldm_x4(bfr, bufo + addrB0 + 2u*(uint32_t)(16*jj*APITCH + 16*ks));
                mma16816(acc[0][2*jj],   a0, bfr);
                mma16816(acc[0][2*jj+1], a0, bfr + 2);
                mma16816(acc[1][2*jj],   a1, bfr);
                mma16816(acc[1][2*jj+1], a1, bfr + 2);
            }
        }
        __syncthreads();

        aregs[0] = anext[0]; aregs[1] = anext[1];
        fcur = fnext;
    }

    // ---- epilogue: write P partial ----
    float* pp = g_Ppart + (((size_t)split*Bn + b)*NHQ)*Cn;
    #pragma unroll
    for (int i = 0; i < 2; i++) {
        const int row = mw*32 + i*16 + (lane >> 2);
        #pragma unroll
        for (int j = 0; j < 8; j++) {
            const int col = nw*64 + j*8 + (lane & 3)*2;
            *(float2*)(pp + (size_t)row*Cn + col)     = make_float2(acc[i][j][0], acc[i][j][1]);
            *(float2*)(pp + (size_t)(row+8)*Cn + col) = make_float2(acc[i][j][2], acc[i][j][3]);
        }
    }
}

// ---------------- K4a: reduce P partials, A = P @ val_w^T (per head) + val_b ----------------
__global__ void k4a(const float* __restrict__ val_w, const float* __restrict__ val_b)
{
    extern __shared__ float sm[];
    float* vw = sm;             // [32][VWP]
    float* ps = sm + 32*VWP;    // [16][256]
    const int h = blockIdx.x, b = blockIdx.y;
    const int tid = threadIdx.x;

    for (int i = tid*4; i < 32*Cn; i += 256*4) {
        int r = i >> 8, c = i & 255;
        float4 v = *(const float4*)&val_w[(size_t)(h*32 + r)*Cn + c];
        *(float4*)&vw[r*VWP + c] = v;
    }
    for (int i = tid*4; i < Qn*Cn; i += 256*4) {
        int q = i >> 8, c = i & 255;
        int hq = h*Qn + q;
        float4 s0 = *(const float4*)&g_Ppart[(((size_t)0*Bn + b)*NHQ + hq)*Cn + c];
        float4 s1 = *(const float4*)&g_Ppart[(((size_t)1*Bn + b)*NHQ + hq)*Cn + c];
        *(float4*)&ps[i] = make_float4(s0.x + s1.x, s0.y + s1.y, s0.z + s1.z, s0.w + s1.w);
    }
    __syncthreads();

    for (int o = tid; o < Qn*32; o += 256) {
        int q = o >> 5, d = o & 31;
        float a = val_b[h*32 + d];
        #pragma unroll 8
        for (int c = 0; c < Cn; c += 4) {
            float4 pv = *(const float4*)&ps[q*Cn + c];
            float4 wv = *(const float4*)&vw[d*VWP + c];
            a = fmaf(pv.x, wv.x, a);
            a = fmaf(pv.y, wv.y, a);
            a = fmaf(pv.z, wv.z, a);
            a = fmaf(pv.w, wv.w, a);
        }
        g_A[b*4096 + (h*Qn + q)*32 + d] = a;
    }
}

// ---------------- K4b: out = A @ fin_w^T + fin_b ----------------
__global__ void kinit(float* __restrict__ out, const float* __restrict__ fin_b)
{
    out[blockIdx.x*FHn + threadIdx.x] = fin_b[threadIdx.x];
}

__global__ void k4b(const float* __restrict__ fin_w, float* __restrict__ out)
{
    __shared__ float At[64*65];
    __shared__ float Wt[32*65];
    const int ft = blockIdx.x;
    const int js = blockIdx.y;
    const int tid = threadIdx.x;
    const int ty = tid >> 5, tx = tid & 31;
    const int f0 = ft*32;

    float acc[8];
    #pragma unroll
    for (int i = 0; i < 8; i++) acc[i] = 0.f;

    for (int sub = 0; sub < 8; sub++) {
        const int j0 = js*512 + sub*64;
        __syncthreads();
        for (int i = tid; i < 64*64; i += 256) {
            int bb = i >> 6, jj = i & 63;
            At[bb*65 + jj] = g_A[bb*4096 + j0 + jj];
        }
        for (int i = tid; i < 32*64; i += 256) {
            int r = i >> 6, jj = i & 63;
            Wt[r*65 + jj] = fin_w[(size_t)(f0 + r)*4096 + j0 + jj];
        }
        __syncthreads();
        #pragma unroll 8
        for (int j = 0; j < 64; j++) {
            float w = Wt[tx*65 + j];
            #pragma unroll
            for (int i = 0; i < 8; i++)
                acc[i] = fmaf(At[(ty*8 + i)*65 + j], w, acc[i]);
        }
    }
    #pragma unroll
    for (int i = 0; i < 8; i++)
        atomicAdd(&out[(ty*8 + i)*FHn + f0 + tx], acc[i]);
}

// ---------------- launch ----------------
extern "C" void kernel_launch(void* const* d_in, const int* in_sizes, int n_in,
                              void* d_out, int out_size)
{
    const float* x    = (const float*)d_in[0];
    const float* gam  = (const float*)d_in[1];
    const float* bet  = (const float*)d_in[2];
    const float* attw = (const float*)d_in[3];
    const float* valw = (const float*)d_in[4];
    const float* valb = (const float*)d_in[5];
    const float* finw = (const float*)d_in[6];
    const float* finb = (const float*)d_in[7];
    float* out = (float*)d_out;

    const int smem_k1  = 128*129*4;
    const int smem_k4a = (32*VWP + 16*Cn)*4;

    cudaFuncSetAttribute(k1,  cudaFuncAttributeMaxDynamicSharedMemorySize, smem_k1);
    cudaFuncSetAttribute(k3,  cudaFuncAttributeMaxDynamicSharedMemorySize, K3_DYN);
    cudaFuncSetAttribute(k4a, cudaFuncAttributeMaxDynamicSharedMemorySize, smem_k4a);

    k1  <<<dim3(NT1, Bn),    256, smem_k1 >>>(x, gam, bet, attw);
    k2  <<<32, 256>>>();
    k3  <<<dim3(NSPLIT, Bn), 512, K3_DYN >>>();
    k4a <<<dim3(HEADSn, Bn), 256, smem_k4a>>>(valw, valb);
    kinit<<<Bn, FHn>>>(out, finb);
    k4b <<<dim3(16, 8), 256>>>(finw, out);
}

// round 9
// speedup vs baseline: 2.3562x; 1.1972x over previous
#include <cuda_runtime.h>
#include <cuda_fp16.h>
#include <cstdint>
#include <math.h>

#define Bn      64
#define Cn      256
#define Ln      4096
#define HEADSn  8
#define Qn      16
#define Dn      32
#define NHQ     128          // HEADS*Q
#define FHn     512
#define NT1     32           // K1: L / 128
#define LT1     128
#define NSPLIT  2
#define LSP     2048         // L per split (Ln/NSPLIT)
#define KC      64           // K3 l-chunk
#define NCHUNK  (LSP/KC)     // 32
#define APITCH  72           // fp16 elems per row (144B pitch -> ldmatrix conflict-free)
#define VWP     260          // k4a vw pitch (float4 conflict-free)
#define LPITCH  132          // k1 logit smem pitch (float4-aligned)

// ---------------- scratch (device globals: no allocs allowed) ----------------
__device__ __half  g_E  [(size_t)Bn*NHQ*Ln];               // 67 MB  exp(logit - m_tile), fp16
__device__ __half  g_xn [(size_t)Bn*Cn*Ln];                // 134 MB LayerNormed x, fp16
__device__ float2  g_part[Bn*NT1*NHQ];                     // per-tile (max, sumexp)
__device__ float2  g_ms  [Bn*NHQ];                         // (max, 1/sum)
__device__ float   g_Ppart[(size_t)NSPLIT*Bn*NHQ*Cn];      // 17 MB partial P
__device__ float   g_A   [Bn*NHQ*Dn];                      // Aflat [B,4096]

// ---------------- fast exp (no MUFU; pure FMA/ALU) ----------------
__device__ __forceinline__ float fexp(float x) {
    float y = x * 1.4426950408889634f;
    y = fmaxf(y, -120.0f);
    float fl = floorf(y);
    float f  = y - fl;                 // [0,1)
    float p = 1.5252733e-5f;
    p = fmaf(p, f, 1.5403530e-4f);
    p = fmaf(p, f, 1.3333558e-3f);
    p = fmaf(p, f, 9.6181291e-3f);
    p = fmaf(p, f, 5.5504109e-2f);
    p = fmaf(p, f, 2.4022651e-1f);
    p = fmaf(p, f, 6.9314718e-1f);
    p = fmaf(p, f, 1.0f);
    int i = (int)fl;
    return p * __int_as_float((i + 127) << 23);
}

// mma.sync m16n8k16 fp16 (row.col), fp32 accumulate — base-arch tensor path
__device__ __forceinline__ void mma16816(float* d, const uint32_t* a, const uint32_t* b) {
    asm volatile("mma.sync.aligned.m16n8k16.row.col.f32.f16.f16.f32 "
        "{%0,%1,%2,%3}, {%4,%5,%6,%7}, {%8,%9}, {%0,%1,%2,%3};"
        : "+f"(d[0]), "+f"(d[1]), "+f"(d[2]), "+f"(d[3])
        : "r"(a[0]), "r"(a[1]), "r"(a[2]), "r"(a[3]), "r"(b[0]), "r"(b[1]));
}

__device__ __forceinline__ void ldm_x4(uint32_t* r, uint32_t addr) {
    asm volatile("ldmatrix.sync.aligned.m8n8.x4.shared.b16 {%0,%1,%2,%3}, [%4];"
        : "=r"(r[0]), "=r"(r[1]), "=r"(r[2]), "=r"(r[3]) : "r"(addr));
}

#define CP_ASYNC16(dst, src) \
    asm volatile("cp.async.ca.shared.global [%0], [%1], 16;" :: "r"(dst), "l"(src) : "memory")
#define CP_COMMIT()  asm volatile("cp.async.commit_group;" ::: "memory")
#define CP_WAIT1()   asm volatile("cp.async.wait_group 1;" ::: "memory")
#define CP_WAIT0()   asm volatile("cp.async.wait_group 0;" ::: "memory")

// ---------------- K1: LN stats + logits + softmax partials + E/xn fp16 stores ----------------
// 512 threads; float4 along l everywhere.
__global__ __launch_bounds__(512) void k1(const float* __restrict__ x,
                                          const float* __restrict__ gamma,
                                          const float* __restrict__ beta,
                                          const float* __restrict__ attw)
{
    extern __shared__ float logit_s[];              // [128][LPITCH]
    __shared__ float  w_s[HEADSn*Dn*Qn];            // [h][c][q] transposed
    __shared__ float4 redS[512], redQ[512];
    __shared__ float2 stats_s[LT1];
    __shared__ float  gms[Cn], bts[Cn];

    const int b = blockIdx.y, tile = blockIdx.x;
    const int tid  = threadIdx.x;
    const int lgrp = tid & 31;
    const int l4   = tile*LT1 + lgrp*4;

    // transpose attw [h][q][c] -> w_s [h][c][q]
    for (int i = tid; i < HEADSn*Qn*Dn; i += 512) {
        int h = i >> 9, q = (i >> 5) & 15, c = i & 31;
        w_s[h*512 + c*Qn + q] = attw[i];
    }
    for (int i = tid; i < Cn; i += 512) { gms[i] = gamma[i]; bts[i] = beta[i]; }

    const float* xb = x + (size_t)b*Cn*Ln;

    // ---- phase A: stats, float4 loads ----
    {
        const int cg = tid >> 5;            // 16 groups of 16 channels
        float4 s4 = make_float4(0.f,0.f,0.f,0.f);
        float4 q4 = make_float4(0.f,0.f,0.f,0.f);
        #pragma unroll 4
        for (int cc = 0; cc < 16; cc++) {
            const int c = cg*16 + cc;
            float4 v = *(const float4*)&xb[(size_t)c*Ln + l4];
            s4.x += v.x; s4.y += v.y; s4.z += v.z; s4.w += v.w;
            q4.x = fmaf(v.x, v.x, q4.x); q4.y = fmaf(v.y, v.y, q4.y);
            q4.z = fmaf(v.z, v.z, q4.z); q4.w = fmaf(v.w, v.w, q4.w);
        }
        redS[tid] = s4; redQ[tid] = q4;
    }
    __syncthreads();
    if (tid < LT1) {
        const int lg = tid >> 2, li = tid & 3;
        float s = 0.f, q = 0.f;
        #pragma unroll
        for (int cg = 0; cg < 16; cg++) {
            s += ((const float*)&redS[cg*32 + lg])[li];
            q += ((const float*)&redQ[cg*32 + lg])[li];
        }
        float mu  = s * (1.f/Cn);
        float var = q * (1.f/Cn) - mu*mu;
        stats_s[tid] = make_float2(mu, rsqrtf(var + 1e-6f));
    }
    __syncthreads();

    // ---- phase B: logits + xn fp16 store ----
    {
        const int h  = (tid >> 5) & 7;
        const int qh = tid >> 8;            // 0/1 (q halves)
        const int q0 = qh*8;
        float2 st0 = stats_s[lgrp*4+0], st1 = stats_s[lgrp*4+1];
        float2 st2 = stats_s[lgrp*4+2], st3 = stats_s[lgrp*4+3];

        float acc[8][4];
        #pragma unroll
        for (int q = 0; q < 8; q++)
            #pragma unroll
            for (int i = 0; i < 4; i++) acc[q][i] = 0.f;

        __half* xnb = g_xn + (size_t)b*Cn*Ln;
        const float* wh = &w_s[h*512];

        #pragma unroll 4
        for (int cc = 0; cc < Dn; cc++) {
            const int c = h*Dn + cc;
            float4 xv = *(const float4*)&xb[(size_t)c*Ln + l4];
            const float gg = gms[c], bb = bts[c];
            float xn0 = (xv.x - st0.x)*st0.y*gg + bb;
            float xn1 = (xv.y - st1.x)*st1.y*gg + bb;
            float xn2 = (xv.z - st2.x)*st2.y*gg + bb;
            float xn3 = (xv.w - st3.x)*st3.y*gg + bb;
            if (qh == 0) {
                __half2 h01 = __floats2half2_rn(xn0, xn1);
                __half2 h23 = __floats2half2_rn(xn2, xn3);
                *(uint2*)&xnb[(size_t)c*Ln + l4] =
                    make_uint2(*reinterpret_cast<uint32_t*>(&h01),
                               *reinterpret_cast<uint32_t*>(&h23));
            }
            float4 w0 = *(const float4*)&wh[cc*Qn + q0];
            float4 w1 = *(const float4*)&wh[cc*Qn + q0 + 4];
            float wq[8] = {w0.x,w0.y,w0.z,w0.w,w1.x,w1.y,w1.z,w1.w};
            float xn[4] = {xn0, xn1, xn2, xn3};
            #pragma unroll
            for (int q = 0; q < 8; q++)
                #pragma unroll
                for (int i = 0; i < 4; i++)
                    acc[q][i] = fmaf(wq[q], xn[i], acc[q][i]);
        }
        #pragma unroll
        for (int q = 0; q < 8; q++) {
            const int hq = h*Qn + q0 + q;
            *(float4*)&logit_s[hq*LPITCH + lgrp*4] =
                make_float4(acc[q][0], acc[q][1], acc[q][2], acc[q][3]);
        }
    }
    __syncthreads();

    // ---- phase C+D: per-hq tile max/sumexp + E fp16 store (4 lanes per hq) ----
    {
        const int hq  = tid >> 2;
        const int sub = tid & 3;
        const float* row = &logit_s[hq*LPITCH + sub*32];
        float m = -1e30f;
        #pragma unroll 8
        for (int k = 0; k < 32; k++) m = fmaxf(m, row[k]);
        m = fmaxf(m, __shfl_xor_sync(0xFFFFFFFFu, m, 1));
        m = fmaxf(m, __shfl_xor_sync(0xFFFFFFFFu, m, 2));

        __half2 out2[16];
        float se = 0.f;
        #pragma unroll 4
        for (int k = 0; k < 16; k++) {
            float e0 = fexp(row[2*k]   - m);
            float e1 = fexp(row[2*k+1] - m);
            se += e0 + e1;
            out2[k] = __floats2half2_rn(e0, e1);
        }
        se += __shfl_xor_sync(0xFFFFFFFFu, se, 1);
        se += __shfl_xor_sync(0xFFFFFFFFu, se, 2);
        if (sub == 0)
            g_part[(b*NT1 + tile)*NHQ + hq] = make_float2(m, se);

        __half* ep = g_E + (size_t)(b*NHQ + hq)*Ln + tile*LT1 + sub*32;
        #pragma unroll
        for (int u = 0; u < 4; u++)
            *(uint4*)(ep + u*8) = *(uint4*)(out2 + u*4);
    }
}

// ---------------- K2: merge softmax partials ----------------
__global__ void k2()
{
    const int idx = blockIdx.x*256 + threadIdx.x;
    if (idx >= Bn*NHQ) return;
    const int b = idx >> 7, hq = idx & 127;
    float m = -1e30f;
    for (int t = 0; t < NT1; t++) m = fmaxf(m, g_part[(b*NT1 + t)*NHQ + hq].x);
    float s = 0.f;
    for (int t = 0; t < NT1; t++) {
        float2 p = g_part[(b*NT1 + t)*NHQ + hq];
        s += p.y * fexp(p.x - m);
    }
    g_ms[idx] = make_float2(m, 1.f/s);
}

// ---------------- K3: P = Aw @ xn^T, pure fp16 GEMM, cp.async double-buffered ----------------
// SMEM per buffer (fp16, K-major, pitch 72): A[128], B[256]; two buffers
#define A_OFF  0
#define B_OFF  (128*APITCH)
#define TILE_HALVES (128*APITCH + 256*APITCH)   // 27648
#define TILE_BYTES  (TILE_HALVES*2)             // 55296
#define K3_DYN (2*TILE_BYTES)                   // 110592

__global__ __launch_bounds__(512, 1) void k3()
{
    extern __shared__ __half sm3[];
    __shared__ float2 ms_s[NHQ];

    const int split = blockIdx.x, b = blockIdx.y;
    const int tid  = threadIdx.x;
    const int wid  = tid >> 5, lane = tid & 31;
    const int mw   = wid >> 2, nw = wid & 3;

    for (int i = tid; i < NHQ; i += 512) ms_s[i] = g_ms[b*NHQ + i];

    // loader mappings
    const int hqA = tid >> 2, l0A = (tid & 3) * 16;   // A: 128 rows x 64
    const int cB  = tid >> 1, l0B = (tid & 1) * 32;   // B: 256 rows x 64
    __syncthreads();
    const float m_g = ms_s[hqA].x, inv_s = ms_s[hqA].y;

    const __half* eA = g_E  + (size_t)(b*NHQ + hqA)*Ln + split*LSP + l0A;
    const __half* xB = g_xn + ((size_t)b*Cn + cB)*Ln   + split*LSP + l0B;
    const float2* gp = g_part + (b*NT1 + split*(NT1/NSPLIT))*NHQ + hqA;

    const uint32_t smb = (uint32_t)__cvta_generic_to_shared(sm3);
    const uint32_t dstB = smb + 2u*(uint32_t)(B_OFF + cB*APITCH + l0B);

    // ldmatrix per-lane base addresses (buffer 0)
    const int g = lane >> 3, r = lane & 7;
    const uint32_t addrA0 = smb + 2u*((uint32_t)((mw*32 + ((g & 1) << 3) + r)*APITCH + ((g >> 1) << 3)));
    const uint32_t addrB0 = smb + 2u*((uint32_t)(B_OFF + (nw*64 + ((g >> 1) << 3) + r)*APITCH + ((g & 1) << 3)));

    float acc[2][8][4];
    #pragma unroll
    for (int i = 0; i < 2; i++)
        #pragma unroll
        for (int j = 0; j < 8; j++)
            #pragma unroll
            for (int e = 0; e < 4; e++) acc[i][j][e] = 0.f;

    // ---- prologue: stage chunk 0 ----
    {
        const __half* src = xB;
        CP_ASYNC16(dstB +  0, src);
        CP_ASYNC16(dstB + 16, src + 8);
        CP_ASYNC16(dstB + 32, src + 16);
        CP_ASYNC16(dstB + 48, src + 24);
        CP_COMMIT();
    }
    uint4 aregs[2];
    aregs[0] = *(const uint4*)(eA);
    aregs[1] = *(const uint4*)(eA + 8);
    float2 p0 = gp[0];
    float fcur = fexp(p0.x - m_g) * inv_s;

    for (int t = 0; t < NCHUNK; t++) {
        const uint32_t bufo = (uint32_t)((t & 1) * TILE_BYTES);
        const uint32_t nbufo = (uint32_t)(((t + 1) & 1) * TILE_BYTES);

        uint4 anext[2];
        float fnext = 0.f;
        if (t + 1 < NCHUNK) {
            const __half* src = xB + (t + 1)*KC;
            CP_ASYNC16(nbufo + dstB +  0, src);
            CP_ASYNC16(nbufo + dstB + 16, src + 8);
            CP_ASYNC16(nbufo + dstB + 32, src + 16);
            CP_ASYNC16(nbufo + dstB + 48, src + 24);
            CP_COMMIT();
            const __half* ea = eA + (t + 1)*KC;
            anext[0] = *(const uint4*)(ea);
            anext[1] = *(const uint4*)(ea + 8);
            float2 pn = gp[((t + 1) >> 1)*NHQ];
            fnext = fexp(pn.x - m_g) * inv_s;
        }

        // convert+store A(t) into current buffer
        {
            const float f = fcur;
            #pragma unroll
            for (int u = 0; u < 2; u++) {
                uint32_t w[4] = {aregs[u].x, aregs[u].y, aregs[u].z, aregs[u].w};
                uint32_t o[4];
                #pragma unroll
                for (int j = 0; j < 4; j++) {
                    __half2 h = *reinterpret_cast<__half2*>(&w[j]);
                    float2 v = __half22float2(h);
                    __half2 rr = __floats2half2_rn(v.x * f, v.y * f);
                    o[j] = *reinterpret_cast<uint32_t*>(&rr);
                }
                *(uint4*)(sm3 + (bufo >> 1) + A_OFF + hqA*APITCH + l0A + u*8) =
                    make_uint4(o[0], o[1], o[2], o[3]);
            }
        }

        if (t + 1 < NCHUNK) CP_WAIT1(); else CP_WAIT0();
        __syncthreads();

        // ---- MMA(t) ----
        #pragma unroll
        for (int ks = 0; ks < 4; ks++) {
            uint32_t a0[4], a1[4];
            ldm_x4(a0, bufo + addrA0 + 2u*(uint32_t)(16*ks));
            ldm_x4(a1, bufo + addrA0 + 2u*(uint32_t)(16*APITCH + 16*ks));
            #pragma unroll
            for (int jj = 0; jj < 4; jj++) {
                uint32_t bfr[4];
                ldm_x4(bfr, bufo + addrB0 + 2u*(uint32_t)(16*jj*APITCH + 16*ks));
                mma16816(acc[0][2*jj],   a0, bfr);
                mma16816(acc[0][2*jj+1], a0, bfr + 2);
                mma16816(acc[1][2*jj],   a1, bfr);
                mma16816(acc[1][2*jj+1], a1, bfr + 2);
            }
        }
        __syncthreads();

        aregs[0] = anext[0]; aregs[1] = anext[1];
        fcur = fnext;
    }

    // ---- epilogue: write P partial ----
    float* pp = g_Ppart + (((size_t)split*Bn + b)*NHQ)*Cn;
    #pragma unroll
    for (int i = 0; i < 2; i++) {
        const int row = mw*32 + i*16 + (lane >> 2);
        #pragma unroll
        for (int j = 0; j < 8; j++) {
            const int col = nw*64 + j*8 + (lane & 3)*2;
            *(float2*)(pp + (size_t)row*Cn + col)     = make_float2(acc[i][j][0], acc[i][j][1]);
            *(float2*)(pp + (size_t)(row+8)*Cn + col) = make_float2(acc[i][j][2], acc[i][j][3]);
        }
    }
}

// ---------------- K4a: reduce P partials, A = P @ val_w^T (per head) + val_b ----------------
__global__ void k4a(const float* __restrict__ val_w, const float* __restrict__ val_b)
{
    extern __shared__ float sm[];
    float* vw = sm;             // [32][VWP]
    float* ps = sm + 32*VWP;    // [16][256]
    const int h = blockIdx.x, b = blockIdx.y;
    const int tid = threadIdx.x;

    for (int i = tid*4; i < 32*Cn; i += 256*4) {
        int r = i >> 8, c = i & 255;
        float4 v = *(const float4*)&val_w[(size_t)(h*32 + r)*Cn + c];
        *(float4*)&vw[r*VWP + c] = v;
    }
    for (int i = tid*4; i < Qn*Cn; i += 256*4) {
        int q = i >> 8, c = i & 255;
        int hq = h*Qn + q;
        float4 s0 = *(const float4*)&g_Ppart[(((size_t)0*Bn + b)*NHQ + hq)*Cn + c];
        float4 s1 = *(const float4*)&g_Ppart[(((size_t)1*Bn + b)*NHQ + hq)*Cn + c];
        *(float4*)&ps[i] = make_float4(s0.x + s1.x, s0.y + s1.y, s0.z + s1.z, s0.w + s1.w);
    }
    __syncthreads();

    for (int o = tid; o < Qn*32; o += 256) {
        int q = o >> 5, d = o & 31;
        float a = val_b[h*32 + d];
        #pragma unroll 8
        for (int c = 0; c < Cn; c += 4) {
            float4 pv = *(const float4*)&ps[q*Cn + c];
            float4 wv = *(const float4*)&vw[d*VWP + c];
            a = fmaf(pv.x, wv.x, a);
            a = fmaf(pv.y, wv.y, a);
            a = fmaf(pv.z, wv.z, a);
            a = fmaf(pv.w, wv.w, a);
        }
        g_A[b*4096 + (h*Qn + q)*32 + d] = a;
    }
}

// ---------------- K4b: out = A @ fin_w^T + fin_b ----------------
__global__ void kinit(float* __restrict__ out, const float* __restrict__ fin_b)
{
    out[blockIdx.x*FHn + threadIdx.x] = fin_b[threadIdx.x];
}

__global__ void k4b(const float* __restrict__ fin_w, float* __restrict__ out)
{
    __shared__ float At[64*65];
    __shared__ float Wt[32*65];
    const int ft = blockIdx.x;
    const int js = blockIdx.y;
    const int tid = threadIdx.x;
    const int ty = tid >> 5, tx = tid & 31;
    const int f0 = ft*32;

    float acc[8];
    #pragma unroll
    for (int i = 0; i < 8; i++) acc[i] = 0.f;

    for (int sub = 0; sub < 8; sub++) {
        const int j0 = js*512 + sub*64;
        __syncthreads();
        for (int i = tid; i < 64*64; i += 256) {
            int bb = i >> 6, jj = i & 63;
            At[bb*65 + jj] = g_A[bb*4096 + j0 + jj];
        }
        for (int i = tid; i < 32*64; i += 256) {
            int r = i >> 6, jj = i & 63;
            Wt[r*65 + jj] = fin_w[(size_t)(f0 + r)*4096 + j0 + jj];
        }
        __syncthreads();
        #pragma unroll 8
        for (int j = 0; j < 64; j++) {
            float w = Wt[tx*65 + j];
            #pragma unroll
            for (int i = 0; i < 8; i++)
                acc[i] = fmaf(At[(ty*8 + i)*65 + j], w, acc[i]);
        }
    }
    #pragma unroll
    for (int i = 0; i < 8; i++)
        atomicAdd(&out[(ty*8 + i)*FHn + f0 + tx], acc[i]);
}

// ---------------- launch ----------------
extern "C" void kernel_launch(void* const* d_in, const int* in_sizes, int n_in,
                              void* d_out, int out_size)
{
    const float* x    = (const float*)d_in[0];
    const float* gam  = (const float*)d_in[1];
    const float* bet  = (const float*)d_in[2];
    const float* attw = (const float*)d_in[3];
    const float* valw = (const float*)d_in[4];
    const float* valb = (const float*)d_in[5];
    const float* finw = (const float*)d_in[6];
    const float* finb = (const float*)d_in[7];
    float* out = (float*)d_out;

    const int smem_k1  = 128*LPITCH*4;
    const int smem_k4a = (32*VWP + 16*Cn)*4;

    cudaFuncSetAttribute(k1,  cudaFuncAttributeMaxDynamicSharedMemorySize, smem_k1);
    cudaFuncSetAttribute(k3,  cudaFuncAttributeMaxDynamicSharedMemorySize, K3_DYN);
    cudaFuncSetAttribute(k4a, cudaFuncAttributeMaxDynamicSharedMemorySize, smem_k4a);

    // kinit first: makes k3 the 4th launch so the profiler's single capture
    // lands on the GEMM instead of k4a (no dependency change: kinit is independent).
    kinit<<<Bn, FHn>>>(out, finb);
    k1  <<<dim3(NT1, Bn),    512, smem_k1 >>>(x, gam, bet, attw);
    k2  <<<32, 256>>>();
    k3  <<<dim3(NSPLIT, Bn), 512, K3_DYN >>>();
    k4a <<<dim3(HEADSn, Bn), 256, smem_k4a>>>(valw, valb);
    k4b <<<dim3(16, 8), 256>>>(finw, out);
}

// round 10
// speedup vs baseline: 2.6719x; 1.1340x over previous
#include <cuda_runtime.h>
#include <cuda_fp16.h>
#include <cstdint>
#include <math.h>

#define Bn      64
#define Cn      256
#define Ln      4096
#define HEADSn  8
#define Qn      16
#define Dn      32
#define NHQ     128          // HEADS*Q
#define FHn     512
#define LT1     64           // K1 tile (l per block)
#define NT1     64           // number of K1 tiles (Ln/LT1)
#define NSPLIT  2
#define LSP     2048         // L per split (Ln/NSPLIT)
#define KC      64           // K3 l-chunk (== LT1)
#define NCHUNK  (LSP/KC)     // 32
#define APITCH  72           // fp16 elems per row (144B pitch -> ldmatrix conflict-free)
#define VWP     260          // k4a vw pitch (float4 conflict-free)
#define LP64    68           // k1 logit smem pitch (float4-aligned, conflict-free)

// ---------------- scratch (device globals: no allocs allowed) ----------------
__device__ __half  g_E  [(size_t)Bn*NHQ*Ln];               // 67 MB  exp(logit - m_tile), fp16
__device__ __half  g_xn [(size_t)Bn*Cn*Ln];                // 134 MB LayerNormed x, fp16
__device__ float2  g_part[Bn*NT1*NHQ];                     // per-tile (max, sumexp)
__device__ float2  g_ms  [Bn*NHQ];                         // (max, 1/sum)
__device__ float   g_Ppart[(size_t)NSPLIT*Bn*NHQ*Cn];      // 17 MB partial P
__device__ float   g_A   [Bn*NHQ*Dn];                      // Aflat [B,4096]

// ---------------- fast exp (no MUFU; pure FMA/ALU) ----------------
__device__ __forceinline__ float fexp(float x) {
    float y = x * 1.4426950408889634f;
    y = fmaxf(y, -120.0f);
    float fl = floorf(y);
    float f  = y - fl;                 // [0,1)
    float p = 1.5252733e-5f;
    p = fmaf(p, f, 1.5403530e-4f);
    p = fmaf(p, f, 1.3333558e-3f);
    p = fmaf(p, f, 9.6181291e-3f);
    p = fmaf(p, f, 5.5504109e-2f);
    p = fmaf(p, f, 2.4022651e-1f);
    p = fmaf(p, f, 6.9314718e-1f);
    p = fmaf(p, f, 1.0f);
    int i = (int)fl;
    return p * __int_as_float((i + 127) << 23);
}

// mma.sync m16n8k16 fp16 (row.col), fp32 accumulate — base-arch tensor path
__device__ __forceinline__ void mma16816(float* d, const uint32_t* a, const uint32_t* b) {
    asm volatile("mma.sync.aligned.m16n8k16.row.col.f32.f16.f16.f32 "
        "{%0,%1,%2,%3}, {%4,%5,%6,%7}, {%8,%9}, {%0,%1,%2,%3};"
        : "+f"(d[0]), "+f"(d[1]), "+f"(d[2]), "+f"(d[3])
        : "r"(a[0]), "r"(a[1]), "r"(a[2]), "r"(a[3]), "r"(b[0]), "r"(b[1]));
}

__device__ __forceinline__ void ldm_x4(uint32_t* r, uint32_t addr) {
    asm volatile("ldmatrix.sync.aligned.m8n8.x4.shared.b16 {%0,%1,%2,%3}, [%4];"
        : "=r"(r[0]), "=r"(r[1]), "=r"(r[2]), "=r"(r[3]) : "r"(addr));
}

#define CP_ASYNC16(dst, src) \
    asm volatile("cp.async.ca.shared.global [%0], [%1], 16;" :: "r"(dst), "l"(src) : "memory")
#define CP_COMMIT()  asm volatile("cp.async.commit_group;" ::: "memory")
#define CP_WAIT1()   asm volatile("cp.async.wait_group 1;" ::: "memory")
#define CP_WAIT0()   asm volatile("cp.async.wait_group 0;" ::: "memory")

// ---------------- no-op (launch-order shim so ncu's capture lands on k1) ----------------
__global__ void knop() {}

// ---------------- K1: LN stats + logits + softmax partials + E/xn fp16 stores ----------------
// 256 threads, LT1=64 tile; smem ~53KB -> 3 CTAs/SM for latency hiding.
__global__ __launch_bounds__(256) void k1(const float* __restrict__ x,
                                          const float* __restrict__ gamma,
                                          const float* __restrict__ beta,
                                          const float* __restrict__ attw)
{
    extern __shared__ float logit_s[];              // [128][LP64]; phase-A scratch aliased
    __shared__ float  w_s[HEADSn*Dn*Qn];            // [h][c][q] transposed
    __shared__ float2 stats_s[LT1];
    __shared__ float  gms[Cn], bts[Cn];

    const int b = blockIdx.y, tile = blockIdx.x;
    const int tid  = threadIdx.x;
    const int lgrp = tid & 15;                      // 16 l-groups of 4
    const int l4   = tile*LT1 + lgrp*4;

    // transpose attw [h][q][c] -> w_s [h][c][q]
    for (int i = tid; i < HEADSn*Qn*Dn; i += 256) {
        int h = i >> 9, q = (i >> 5) & 15, c = i & 31;
        w_s[h*512 + c*Qn + q] = attw[i];
    }
    for (int i = tid; i < Cn; i += 256) { gms[i] = gamma[i]; bts[i] = beta[i]; }

    const float* xb = x + (size_t)b*Cn*Ln;

    // ---- phase A: stats (reduction scratch aliases logit_s) ----
    {
        float4* redS = (float4*)logit_s;            // [256]
        float4* redQ = redS + 256;                  // [256]
        const int cg = tid >> 4;                    // 16 groups of 16 channels
        float4 s4 = make_float4(0.f,0.f,0.f,0.f);
        float4 q4 = make_float4(0.f,0.f,0.f,0.f);
        #pragma unroll 4
        for (int cc = 0; cc < 16; cc++) {
            const int c = cg*16 + cc;
            float4 v = *(const float4*)&xb[(size_t)c*Ln + l4];
            s4.x += v.x; s4.y += v.y; s4.z += v.z; s4.w += v.w;
            q4.x = fmaf(v.x, v.x, q4.x); q4.y = fmaf(v.y, v.y, q4.y);
            q4.z = fmaf(v.z, v.z, q4.z); q4.w = fmaf(v.w, v.w, q4.w);
        }
        redS[tid] = s4; redQ[tid] = q4;
        __syncthreads();
        if (tid < LT1) {
            const int lg = tid >> 2, li = tid & 3;
            float s = 0.f, q = 0.f;
            #pragma unroll
            for (int cg2 = 0; cg2 < 16; cg2++) {
                s += ((const float*)&redS[cg2*16 + lg])[li];
                q += ((const float*)&redQ[cg2*16 + lg])[li];
            }
            float mu  = s * (1.f/Cn);
            float var = q * (1.f/Cn) - mu*mu;
            stats_s[tid] = make_float2(mu, rsqrtf(var + 1e-6f));
        }
        __syncthreads();
    }

    // ---- phase B: logits + xn fp16 store ----
    {
        const int h  = (tid >> 4) & 7;
        const int qh = tid >> 7;                    // 0/1 (q halves)
        const int q0 = qh*8;
        float2 st0 = stats_s[lgrp*4+0], st1 = stats_s[lgrp*4+1];
        float2 st2 = stats_s[lgrp*4+2], st3 = stats_s[lgrp*4+3];

        float acc[8][4];
        #pragma unroll
        for (int q = 0; q < 8; q++)
            #pragma unroll
            for (int i = 0; i < 4; i++) acc[q][i] = 0.f;

        __half* xnb = g_xn + (size_t)b*Cn*Ln;
        const float* wh = &w_s[h*512];

        #pragma unroll 4
        for (int cc = 0; cc < Dn; cc++) {
            const int c = h*Dn + cc;
            float4 xv = *(const float4*)&xb[(size_t)c*Ln + l4];
            const float gg = gms[c], bb = bts[c];
            float xn0 = (xv.x - st0.x)*st0.y*gg + bb;
            float xn1 = (xv.y - st1.x)*st1.y*gg + bb;
            float xn2 = (xv.z - st2.x)*st2.y*gg + bb;
            float xn3 = (xv.w - st3.x)*st3.y*gg + bb;
            if (qh == 0) {
                __half2 h01 = __floats2half2_rn(xn0, xn1);
                __half2 h23 = __floats2half2_rn(xn2, xn3);
                *(uint2*)&xnb[(size_t)c*Ln + l4] =
                    make_uint2(*reinterpret_cast<uint32_t*>(&h01),
                               *reinterpret_cast<uint32_t*>(&h23));
            }
            float4 w0 = *(const float4*)&wh[cc*Qn + q0];
            float4 w1 = *(const float4*)&wh[cc*Qn + q0 + 4];
            float wq[8] = {w0.x,w0.y,w0.z,w0.w,w1.x,w1.y,w1.z,w1.w};
            float xn[4] = {xn0, xn1, xn2, xn3};
            #pragma unroll
            for (int q = 0; q < 8; q++)
                #pragma unroll
                for (int i = 0; i < 4; i++)
                    acc[q][i] = fmaf(wq[q], xn[i], acc[q][i]);
        }
        __syncthreads();       // phase-A scratch no longer needed; logits overwrite it
        #pragma unroll
        for (int q = 0; q < 8; q++) {
            const int hq = h*Qn + q0 + q;
            *(float4*)&logit_s[hq*LP64 + lgrp*4] =
                make_float4(acc[q][0], acc[q][1], acc[q][2], acc[q][3]);
        }
    }
    __syncthreads();

    // ---- phase C+D: per-hq tile max/sumexp + E fp16 store (2 lanes per hq) ----
    {
        const int hq  = tid >> 1;
        const int sub = tid & 1;
        const float* row = &logit_s[hq*LP64 + sub*32];
        float m = -1e30f;
        #pragma unroll 8
        for (int k = 0; k < 32; k++) m = fmaxf(m, row[k]);
        m = fmaxf(m, __shfl_xor_sync(0xFFFFFFFFu, m, 1));

        __half2 out2[16];
        float se = 0.f;
        #pragma unroll 4
        for (int k = 0; k < 16; k++) {
            float e0 = fexp(row[2*k]   - m);
            float e1 = fexp(row[2*k+1] - m);
            se += e0 + e1;
            out2[k] = __floats2half2_rn(e0, e1);
        }
        se += __shfl_xor_sync(0xFFFFFFFFu, se, 1);
        if (sub == 0)
            g_part[(b*NT1 + tile)*NHQ + hq] = make_float2(m, se);

        __half* ep = g_E + (size_t)(b*NHQ + hq)*Ln + tile*LT1 + sub*32;
        #pragma unroll
        for (int u = 0; u < 4; u++)
            *(uint4*)(ep + u*8) = *(uint4*)(out2 + u*4);
    }
}

// ---------------- K2: merge softmax partials ----------------
__global__ void k2()
{
    const int idx = blockIdx.x*256 + threadIdx.x;
    if (idx >= Bn*NHQ) return;
    const int b = idx >> 7, hq = idx & 127;
    float m = -1e30f;
    for (int t = 0; t < NT1; t++) m = fmaxf(m, g_part[(b*NT1 + t)*NHQ + hq].x);
    float s = 0.f;
    for (int t = 0; t < NT1; t++) {
        float2 p = g_part[(b*NT1 + t)*NHQ + hq];
        s += p.y * fexp(p.x - m);
    }
    g_ms[idx] = make_float2(m, 1.f/s);
}

// ---------------- K3: P = Aw @ xn^T, pure fp16 GEMM, cp.async double-buffered ----------------
// SMEM per buffer (fp16, K-major, pitch 72): A[128], B[256]; two buffers
#define A_OFF  0
#define B_OFF  (128*APITCH)
#define TILE_HALVES (128*APITCH + 256*APITCH)   // 27648
#define TILE_BYTES  (TILE_HALVES*2)             // 55296
#define K3_DYN (2*TILE_BYTES)                   // 110592

__global__ __launch_bounds__(512, 1) void k3()
{
    extern __shared__ __half sm3[];
    __shared__ float2 ms_s[NHQ];

    const int split = blockIdx.x, b = blockIdx.y;
    const int tid  = threadIdx.x;
    const int wid  = tid >> 5, lane = tid & 31;
    const int mw   = wid >> 2, nw = wid & 3;

    for (int i = tid; i < NHQ; i += 512) ms_s[i] = g_ms[b*NHQ + i];

    // loader mappings
    const int hqA = tid >> 2, l0A = (tid & 3) * 16;   // A: 128 rows x 64
    const int cB  = tid >> 1, l0B = (tid & 1) * 32;   // B: 256 rows x 64
    __syncthreads();
    const float m_g = ms_s[hqA].x, inv_s = ms_s[hqA].y;

    const __half* eA = g_E  + (size_t)(b*NHQ + hqA)*Ln + split*LSP + l0A;
    const __half* xB = g_xn + ((size_t)b*Cn + cB)*Ln   + split*LSP + l0B;
    // one g_part tile per KC chunk now (LT1 == KC == 64)
    const float2* gp = g_part + (b*NT1 + split*(NT1/NSPLIT))*NHQ + hqA;

    const uint32_t smb = (uint32_t)__cvta_generic_to_shared(sm3);
    const uint32_t dstB = smb + 2u*(uint32_t)(B_OFF + cB*APITCH + l0B);

    // ldmatrix per-lane base addresses (buffer 0)
    const int g = lane >> 3, r = lane & 7;
    const uint32_t addrA0 = smb + 2u*((uint32_t)((mw*32 + ((g & 1) << 3) + r)*APITCH + ((g >> 1) << 3)));
    const uint32_t addrB0 = smb + 2u*((uint32_t)(B_OFF + (nw*64 + ((g >> 1) << 3) + r)*APITCH + ((g & 1) << 3)));

    float acc[2][8][4];
    #pragma unroll
    for (int i = 0; i < 2; i++)
        #pragma unroll
        for (int j = 0; j < 8; j++)
            #pragma unroll
            for (int e = 0; e < 4; e++) acc[i][j][e] = 0.f;

    // ---- prologue: stage chunk 0 ----
    {
        const __half* src = xB;
        CP_ASYNC16(dstB +  0, src);
        CP_ASYNC16(dstB + 16, src + 8);
        CP_ASYNC16(dstB + 32, src + 16);
        CP_ASYNC16(dstB + 48, src + 24);
        CP_COMMIT();
    }
    uint4 aregs[2];
    aregs[0] = *(const uint4*)(eA);
    aregs[1] = *(const uint4*)(eA + 8);
    float2 p0 = gp[0];
    float fcur = fexp(p0.x - m_g) * inv_s;

    for (int t = 0; t < NCHUNK; t++) {
        const uint32_t bufo = (uint32_t)((t & 1) * TILE_BYTES);
        const uint32_t nbufo = (uint32_t)(((t + 1) & 1) * TILE_BYTES);

        uint4 anext[2];
        float fnext = 0.f;
        if (t + 1 < NCHUNK) {
            const __half* src = xB + (t + 1)*KC;
            CP_ASYNC16(nbufo + dstB +  0, src);
            CP_ASYNC16(nbufo + dstB + 16, src + 8);
            CP_ASYNC16(nbufo + dstB + 32, src + 16);
            CP_ASYNC16(nbufo + dstB + 48, src + 24);
            CP_COMMIT();
            const __half* ea = eA + (t + 1)*KC;
            anext[0] = *(const uint4*)(ea);
            anext[1] = *(const uint4*)(ea + 8);
            float2 pn = gp[(t + 1)*NHQ];
            fnext = fexp(pn.x - m_g) * inv_s;
        }

        // convert+store A(t) into current buffer
        {
            const float f = fcur;
            #pragma unroll
            for (int u = 0; u < 2; u++) {
                uint32_t w[4] = {aregs[u].x, aregs[u].y, aregs[u].z, aregs[u].w};
                uint32_t o[4];
                #pragma unroll
                for (int j = 0; j < 4; j++) {
                    __half2 h = *reinterpret_cast<__half2*>(&w[j]);
                    float2 v = __half22float2(h);
                    __half2 rr = __floats2half2_rn(v.x * f, v.y * f);
                    o[j] = *reinterpret_cast<uint32_t*>(&rr);
                }
                *(uint4*)(sm3 + (bufo >> 1) + A_OFF + hqA*APITCH + l0A + u*8) =
                    make_uint4(o[0], o[1], o[2], o[3]);
            }
        }

        if (t + 1 < NCHUNK) CP_WAIT1(); else CP_WAIT0();
        __syncthreads();

        // ---- MMA(t) ----
        #pragma unroll
        for (int ks = 0; ks < 4; ks++) {
            uint32_t a0[4], a1[4];
            ldm_x4(a0, bufo + addrA0 + 2u*(uint32_t)(16*ks));
            ldm_x4(a1, bufo + addrA0 + 2u*(uint32_t)(16*APITCH + 16*ks));
            #pragma unroll
            for (int jj = 0; jj < 4; jj++) {
                uint32_t bfr[4];
                ldm_x4(bfr, bufo + addrB0 + 2u*(uint32_t)(16*jj*APITCH + 16*ks));
                mma16816(acc[0][2*jj],   a0, bfr);
                mma16816(acc[0][2*jj+1], a0, bfr + 2);
                mma16816(acc[1][2*jj],   a1, bfr);
                mma16816(acc[1][2*jj+1], a1, bfr + 2);
            }
        }
        __syncthreads();

        aregs[0] = anext[0]; aregs[1] = anext[1];
        fcur = fnext;
    }

    // ---- epilogue: write P partial ----
    float* pp = g_Ppart + (((size_t)split*Bn + b)*NHQ)*Cn;
    #pragma unroll
    for (int i = 0; i < 2; i++) {
        const int row = mw*32 + i*16 + (lane >> 2);
        #pragma unroll
        for (int j = 0; j < 8; j++) {
            const int col = nw*64 + j*8 + (lane & 3)*2;
            *(float2*)(pp + (size_t)row*Cn + col)     = make_float2(acc[i][j][0], acc[i][j][1]);
            *(float2*)(pp + (size_t)(row+8)*Cn + col) = make_float2(acc[i][j][2], acc[i][j][3]);
        }
    }
}

// ---------------- K4a: reduce P partials, A = P @ val_w^T (per head) + val_b ----------------
__global__ void k4a(const float* __restrict__ val_w, const float* __restrict__ val_b)
{
    extern __shared__ float sm[];
    float* vw = sm;             // [32][VWP]
    float* ps = sm + 32*VWP;    // [16][256]
    const int h = blockIdx.x, b = blockIdx.y;
    const int tid = threadIdx.x;

    for (int i = tid*4; i < 32*Cn; i += 256*4) {
        int r = i >> 8, c = i & 255;
        float4 v = *(const float4*)&val_w[(size_t)(h*32 + r)*Cn + c];
        *(float4*)&vw[r*VWP + c] = v;
    }
    for (int i = tid*4; i < Qn*Cn; i += 256*4) {
        int q = i >> 8, c = i & 255;
        int hq = h*Qn + q;
        float4 s0 = *(const float4*)&g_Ppart[(((size_t)0*Bn + b)*NHQ + hq)*Cn + c];
        float4 s1 = *(const float4*)&g_Ppart[(((size_t)1*Bn + b)*NHQ + hq)*Cn + c];
        *(float4*)&ps[i] = make_float4(s0.x + s1.x, s0.y + s1.y, s0.z + s1.z, s0.w + s1.w);
    }
    __syncthreads();

    for (int o = tid; o < Qn*32; o += 256) {
        int q = o >> 5, d = o & 31;
        float a = val_b[h*32 + d];
        #pragma unroll 8
        for (int c = 0; c < Cn; c += 4) {
            float4 pv = *(const float4*)&ps[q*Cn + c];
            float4 wv = *(const float4*)&vw[d*VWP + c];
            a = fmaf(pv.x, wv.x, a);
            a = fmaf(pv.y, wv.y, a);
            a = fmaf(pv.z, wv.z, a);
            a = fmaf(pv.w, wv.w, a);
        }
        g_A[b*4096 + (h*Qn + q)*32 + d] = a;
    }
}

// ---------------- K4b: out = A @ fin_w^T + fin_b ----------------
__global__ void kinit(float* __restrict__ out, const float* __restrict__ fin_b)
{
    out[blockIdx.x*FHn + threadIdx.x] = fin_b[threadIdx.x];
}

__global__ void k4b(const float* __restrict__ fin_w, float* __restrict__ out)
{
    __shared__ float At[64*65];
    __shared__ float Wt[32*65];
    const int ft = blockIdx.x;
    const int js = blockIdx.y;
    const int tid = threadIdx.x;
    const int ty = tid >> 5, tx = tid & 31;
    const int f0 = ft*32;

    float acc[8];
    #pragma unroll
    for (int i = 0; i < 8; i++) acc[i] = 0.f;

    for (int sub = 0; sub < 8; sub++) {
        const int j0 = js*512 + sub*64;
        __syncthreads();
        for (int i = tid; i < 64*64; i += 256) {
            int bb = i >> 6, jj = i & 63;
            At[bb*65 + jj] = g_A[bb*4096 + j0 + jj];
        }
        for (int i = tid; i < 32*64; i += 256) {
            int r = i >> 6, jj = i & 63;
            Wt[r*65 + jj] = fin_w[(size_t)(f0 + r)*4096 + j0 + jj];
        }
        __syncthreads();
        #pragma unroll 8
        for (int j = 0; j < 64; j++) {
            float w = Wt[tx*65 + j];
            #pragma unroll
            for (int i = 0; i < 8; i++)
                acc[i] = fmaf(At[(ty*8 + i)*65 + j], w, acc[i]);
        }
    }
    #pragma unroll
    for (int i = 0; i < 8; i++)
        atomicAdd(&out[(ty*8 + i)*FHn + f0 + tx], acc[i]);
}

// ---------------- launch ----------------
extern "C" void kernel_launch(void* const* d_in, const int* in_sizes, int n_in,
                              void* d_out, int out_size)
{
    const float* x    = (const float*)d_in[0];
    const float* gam  = (const float*)d_in[1];
    const float* bet  = (const float*)d_in[2];
    const float* attw = (const float*)d_in[3];
    const float* valw = (const float*)d_in[4];
    const float* valb = (const float*)d_in[5];
    const float* finw = (const float*)d_in[6];
    const float* finb = (const float*)d_in[7];
    float* out = (float*)d_out;

    const int smem_k1  = 128*LP64*4;                // 34816
    const int smem_k4a = (32*VWP + 16*Cn)*4;

    cudaFuncSetAttribute(k1,  cudaFuncAttributeMaxDynamicSharedMemorySize, smem_k1);
    cudaFuncSetAttribute(k3,  cudaFuncAttributeMaxDynamicSharedMemorySize, K3_DYN);
    cudaFuncSetAttribute(k4a, cudaFuncAttributeMaxDynamicSharedMemorySize, smem_k4a);

    // launch-order shims: k1 is the 4th launch -> ncu capture shows the dominant kernel
    knop<<<1, 32>>>();
    knop<<<1, 32>>>();
    kinit<<<Bn, FHn>>>(out, finb);
    k1  <<<dim3(NT1, Bn),    256, smem_k1 >>>(x, gam, bet, attw);
    k2  <<<32, 256>>>();
    k3  <<<dim3(NSPLIT, Bn), 512, K3_DYN >>>();
    k4a <<<dim3(HEADSn, Bn), 256, smem_k4a>>>(valw, valb);
    k4b <<<dim3(16, 8), 256>>>(finw, out);
}

// round 11
// speedup vs baseline: 2.8195x; 1.0553x over previous
#include <cuda_runtime.h>
#include <cuda_fp16.h>
#include <cstdint>
#include <math.h>

#define Bn      64
#define Cn      256
#define Ln      4096
#define HEADSn  8
#define Qn      16
#define Dn      32
#define NHQ     128          // HEADS*Q
#define FHn     512
#define LT1     64           // K1 tile (l per block)
#define NT1     64           // number of K1 tiles (Ln/LT1)
#define NSPLIT  2
#define LSP     2048         // L per split (Ln/NSPLIT)
#define KC      64           // K3 l-chunk (== LT1)
#define NCHUNK  (LSP/KC)     // 32
#define APITCH  72           // fp16 elems per row (144B pitch -> ldmatrix conflict-free)
#define VWP     260          // k4a vw pitch (float4 conflict-free)
#define LP64    68           // k1 logit smem pitch (float4-aligned)
#define XHP     72           // k1 x_h smem pitch (halves)

// ---------------- scratch (device globals: no allocs allowed) ----------------
__device__ __half  g_E  [(size_t)Bn*NHQ*Ln];               // 67 MB  exp(logit - m_tile), fp16
__device__ __half  g_xn [(size_t)Bn*Cn*Ln];                // 134 MB LayerNormed x, fp16
__device__ float2  g_part[Bn*NT1*NHQ];                     // per-tile (max, sumexp)
__device__ float2  g_ms  [Bn*NHQ];                         // (max, 1/sum)
__device__ float   g_Ppart[(size_t)NSPLIT*Bn*NHQ*Cn];      // 17 MB partial P
__device__ float   g_A   [Bn*NHQ*Dn];                      // Aflat [B,4096]

// ---------------- fast exp (no MUFU; pure FMA/ALU) ----------------
__device__ __forceinline__ float fexp(float x) {
    float y = x * 1.4426950408889634f;
    y = fmaxf(y, -120.0f);
    float fl = floorf(y);
    float f  = y - fl;                 // [0,1)
    float p = 1.5252733e-5f;
    p = fmaf(p, f, 1.5403530e-4f);
    p = fmaf(p, f, 1.3333558e-3f);
    p = fmaf(p, f, 9.6181291e-3f);
    p = fmaf(p, f, 5.5504109e-2f);
    p = fmaf(p, f, 2.4022651e-1f);
    p = fmaf(p, f, 6.9314718e-1f);
    p = fmaf(p, f, 1.0f);
    int i = (int)fl;
    return p * __int_as_float((i + 127) << 23);
}

// mma.sync m16n8k16 fp16 (row.col), fp32 accumulate — base-arch tensor path
__device__ __forceinline__ void mma16816(float* d, const uint32_t* a, const uint32_t* b) {
    asm volatile("mma.sync.aligned.m16n8k16.row.col.f32.f16.f16.f32 "
        "{%0,%1,%2,%3}, {%4,%5,%6,%7}, {%8,%9}, {%0,%1,%2,%3};"
        : "+f"(d[0]), "+f"(d[1]), "+f"(d[2]), "+f"(d[3])
        : "r"(a[0]), "r"(a[1]), "r"(a[2]), "r"(a[3]), "r"(b[0]), "r"(b[1]));
}

__device__ __forceinline__ void ldm_x4(uint32_t* r, uint32_t addr) {
    asm volatile("ldmatrix.sync.aligned.m8n8.x4.shared.b16 {%0,%1,%2,%3}, [%4];"
        : "=r"(r[0]), "=r"(r[1]), "=r"(r[2]), "=r"(r[3]) : "r"(addr));
}

#define CP_ASYNC16(dst, src) \
    asm volatile("cp.async.ca.shared.global [%0], [%1], 16;" :: "r"(dst), "l"(src) : "memory")
#define CP_COMMIT()  asm volatile("cp.async.commit_group;" ::: "memory")
#define CP_WAIT1()   asm volatile("cp.async.wait_group 1;" ::: "memory")
#define CP_WAIT0()   asm volatile("cp.async.wait_group 0;" ::: "memory")

// ---------------- no-op (launch-order shim so ncu's capture lands on k1) ----------------
__global__ void knop() {}

// ---------------- K1: LN stats + logits + softmax partials + E/xn fp16 stores ----------------
// 512 threads, LT1=64 tile. x staged as fp16 in SMEM (single global read of x);
// SMEM buffer reused for logits after phase B.
#define XH_BYTES (Cn*XHP*2)                 // 36864
#define RED_OFF  (XH_BYTES)                 // reduction scratch after x_h
#define K1_DYN   (XH_BYTES + 512*16*2)      // + redS/redQ float4[512] each = 53248

__global__ __launch_bounds__(512) void k1(const float* __restrict__ x,
                                          const float* __restrict__ gamma,
                                          const float* __restrict__ beta,
                                          const float* __restrict__ attw)
{
    extern __shared__ char sm1[];
    __half* x_h     = (__half*)sm1;               // [256][XHP] halves
    float*  logit_s = (float*)sm1;                // [128][LP64] floats (reused post-B)
    float4* redS    = (float4*)(sm1 + RED_OFF);   // [512]
    float4* redQ    = redS + 512;                 // [512]

    __shared__ float  w_s[HEADSn*Dn*Qn];          // [h][c][q] transposed
    __shared__ float2 stats_s[LT1];
    __shared__ float  gms[Cn], bts[Cn];

    const int b = blockIdx.y, tile = blockIdx.x;
    const int tid  = threadIdx.x;
    const int lgrp = tid & 15;                    // 16 l-groups of 4
    const int l4   = tile*LT1 + lgrp*4;

    // transpose attw [h][q][c] -> w_s [h][c][q]
    for (int i = tid; i < HEADSn*Qn*Dn; i += 512) {
        int h = i >> 9, q = (i >> 5) & 15, c = i & 31;
        w_s[h*512 + c*Qn + q] = attw[i];
    }
    for (int i = tid; i < Cn; i += 512) { gms[i] = gamma[i]; bts[i] = beta[i]; }

    const float* xb = x + (size_t)b*Cn*Ln;

    // ---- phase A: stats from fp32 x; stage x as fp16 into SMEM ----
    {
        const int cg = tid >> 4;                  // 32 groups of 8 channels
        float4 s4 = make_float4(0.f,0.f,0.f,0.f);
        float4 q4 = make_float4(0.f,0.f,0.f,0.f);
        #pragma unroll
        for (int cc = 0; cc < 8; cc++) {
            const int c = cg*8 + cc;
            float4 v = *(const float4*)&xb[(size_t)c*Ln + l4];
            s4.x += v.x; s4.y += v.y; s4.z += v.z; s4.w += v.w;
            q4.x = fmaf(v.x, v.x, q4.x); q4.y = fmaf(v.y, v.y, q4.y);
            q4.z = fmaf(v.z, v.z, q4.z); q4.w = fmaf(v.w, v.w, q4.w);
            __half2 a01 = __floats2half2_rn(v.x, v.y);
            __half2 a23 = __floats2half2_rn(v.z, v.w);
            *(uint2*)&x_h[c*XHP + lgrp*4] =
                make_uint2(*reinterpret_cast<uint32_t*>(&a01),
                           *reinterpret_cast<uint32_t*>(&a23));
        }
        redS[tid] = s4; redQ[tid] = q4;
        __syncthreads();
        if (tid < LT1) {
            const int lg = tid >> 2, li = tid & 3;
            float s = 0.f, q = 0.f;
            #pragma unroll
            for (int cg2 = 0; cg2 < 32; cg2++) {
                s += ((const float*)&redS[cg2*16 + lg])[li];
                q += ((const float*)&redQ[cg2*16 + lg])[li];
            }
            float mu  = s * (1.f/Cn);
            float var = q * (1.f/Cn) - mu*mu;
            stats_s[tid] = make_float2(mu, rsqrtf(var + 1e-6f));
        }
        __syncthreads();
    }

    // ---- phase B: logits from SMEM x_h; xn fp16 store ----
    {
        const int h  = (tid >> 4) & 7;
        const int qq = tid >> 7;                  // 0..3 (q quarters)
        const int q0 = qq*4;
        float2 st0 = stats_s[lgrp*4+0], st1 = stats_s[lgrp*4+1];
        float2 st2 = stats_s[lgrp*4+2], st3 = stats_s[lgrp*4+3];

        float acc[4][4];
        #pragma unroll
        for (int q = 0; q < 4; q++)
            #pragma unroll
            for (int i = 0; i < 4; i++) acc[q][i] = 0.f;

        __half* xnb = g_xn + (size_t)b*Cn*Ln;
        const float* wh = &w_s[h*512];

        #pragma unroll 4
        for (int cc = 0; cc < Dn; cc++) {
            const int c = h*Dn + cc;
            uint2 u = *(const uint2*)&x_h[c*XHP + lgrp*4];
            float2 f01 = __half22float2(*reinterpret_cast<__half2*>(&u.x));
            float2 f23 = __half22float2(*reinterpret_cast<__half2*>(&u.y));
            const float gg = gms[c], bb = bts[c];
            float xn0 = (f01.x - st0.x)*st0.y*gg + bb;
            float xn1 = (f01.y - st1.x)*st1.y*gg + bb;
            float xn2 = (f23.x - st2.x)*st2.y*gg + bb;
            float xn3 = (f23.y - st3.x)*st3.y*gg + bb;
            if (qq == 0) {
                __half2 o01 = __floats2half2_rn(xn0, xn1);
                __half2 o23 = __floats2half2_rn(xn2, xn3);
                *(uint2*)&xnb[(size_t)c*Ln + l4] =
                    make_uint2(*reinterpret_cast<uint32_t*>(&o01),
                               *reinterpret_cast<uint32_t*>(&o23));
            }
            float4 w = *(const float4*)&wh[cc*Qn + q0];
            float wq[4] = {w.x, w.y, w.z, w.w};
            float xn[4] = {xn0, xn1, xn2, xn3};
            #pragma unroll
            for (int q = 0; q < 4; q++)
                #pragma unroll
                for (int i = 0; i < 4; i++)
                    acc[q][i] = fmaf(wq[q], xn[i], acc[q][i]);
        }
        __syncthreads();    // all x_h reads done; safe to overwrite with logits
        #pragma unroll
        for (int q = 0; q < 4; q++) {
            const int hq = h*Qn + q0 + q;
            *(float4*)&logit_s[hq*LP64 + lgrp*4] =
                make_float4(acc[q][0], acc[q][1], acc[q][2], acc[q][3]);
        }
    }
    __syncthreads();

    // ---- phase C+D: per-hq tile max/sumexp + E fp16 store (4 lanes per hq) ----
    {
        const int hq  = tid >> 2;
        const int sub = tid & 3;
        const float* row = &logit_s[hq*LP64 + sub*16];
        float m = -1e30f;
        #pragma unroll
        for (int k = 0; k < 16; k++) m = fmaxf(m, row[k]);
        m = fmaxf(m, __shfl_xor_sync(0xFFFFFFFFu, m, 1));
        m = fmaxf(m, __shfl_xor_sync(0xFFFFFFFFu, m, 2));

        __half2 out2[8];
        float se = 0.f;
        #pragma unroll
        for (int k = 0; k < 8; k++) {
            float e0 = fexp(row[2*k]   - m);
            float e1 = fexp(row[2*k+1] - m);
            se += e0 + e1;
            out2[k] = __floats2half2_rn(e0, e1);
        }
        se += __shfl_xor_sync(0xFFFFFFFFu, se, 1);
        se += __shfl_xor_sync(0xFFFFFFFFu, se, 2);
        if (sub == 0)
            g_part[(b*NT1 + tile)*NHQ + hq] = make_float2(m, se);

        __half* ep = g_E + (size_t)(b*NHQ + hq)*Ln + tile*LT1 + sub*16;
        *(uint4*)(ep)     = *(uint4*)(out2);
        *(uint4*)(ep + 8) = *(uint4*)(out2 + 4);
    }
}

// ---------------- K2: merge softmax partials ----------------
__global__ void k2()
{
    const int idx = blockIdx.x*256 + threadIdx.x;
    if (idx >= Bn*NHQ) return;
    const int b = idx >> 7, hq = idx & 127;
    float m = -1e30f;
    for (int t = 0; t < NT1; t++) m = fmaxf(m, g_part[(b*NT1 + t)*NHQ + hq].x);
    float s = 0.f;
    for (int t = 0; t < NT1; t++) {
        float2 p = g_part[(b*NT1 + t)*NHQ + hq];
        s += p.y * fexp(p.x - m);
    }
    g_ms[idx] = make_float2(m, 1.f/s);
}

// ---------------- K3: P = Aw @ xn^T, pure fp16 GEMM, cp.async double-buffered ----------------
#define A_OFF  0
#define B_OFF  (128*APITCH)
#define TILE_HALVES (128*APITCH + 256*APITCH)   // 27648
#define TILE_BYTES  (TILE_HALVES*2)             // 55296
#define K3_DYN (2*TILE_BYTES)                   // 110592

__global__ __launch_bounds__(512, 1) void k3()
{
    extern __shared__ __half sm3[];
    __shared__ float2 ms_s[NHQ];

    const int split = blockIdx.x, b = blockIdx.y;
    const int tid  = threadIdx.x;
    const int wid  = tid >> 5, lane = tid & 31;
    const int mw   = wid >> 2, nw = wid & 3;

    for (int i = tid; i < NHQ; i += 512) ms_s[i] = g_ms[b*NHQ + i];

    const int hqA = tid >> 2, l0A = (tid & 3) * 16;   // A: 128 rows x 64
    const int cB  = tid >> 1, l0B = (tid & 1) * 32;   // B: 256 rows x 64
    __syncthreads();
    const float m_g = ms_s[hqA].x, inv_s = ms_s[hqA].y;

    const __half* eA = g_E  + (size_t)(b*NHQ + hqA)*Ln + split*LSP + l0A;
    const __half* xB = g_xn + ((size_t)b*Cn + cB)*Ln   + split*LSP + l0B;
    const float2* gp = g_part + (b*NT1 + split*(NT1/NSPLIT))*NHQ + hqA;

    const uint32_t smb = (uint32_t)__cvta_generic_to_shared(sm3);
    const uint32_t dstB = smb + 2u*(uint32_t)(B_OFF + cB*APITCH + l0B);

    const int g = lane >> 3, r = lane & 7;
    const uint32_t addrA0 = smb + 2u*((uint32_t)((mw*32 + ((g & 1) << 3) + r)*APITCH + ((g >> 1) << 3)));
    const uint32_t addrB0 = smb + 2u*((uint32_t)(B_OFF + (nw*64 + ((g >> 1) << 3) + r)*APITCH + ((g & 1) << 3)));

    float acc[2][8][4];
    #pragma unroll
    for (int i = 0; i < 2; i++)
        #pragma unroll
        for (int j = 0; j < 8; j++)
            #pragma unroll
            for (int e = 0; e < 4; e++) acc[i][j][e] = 0.f;

    // ---- prologue: stage chunk 0 ----
    {
        const __half* src = xB;
        CP_ASYNC16(dstB +  0, src);
        CP_ASYNC16(dstB + 16, src + 8);
        CP_ASYNC16(dstB + 32, src + 16);
        CP_ASYNC16(dstB + 48, src + 24);
        CP_COMMIT();
    }
    uint4 aregs[2];
    aregs[0] = *(const uint4*)(eA);
    aregs[1] = *(const uint4*)(eA + 8);
    float2 p0 = gp[0];
    float fcur = fexp(p0.x - m_g) * inv_s;

    for (int t = 0; t < NCHUNK; t++) {
        const uint32_t bufo = (uint32_t)((t & 1) * TILE_BYTES);
        const uint32_t nbufo = (uint32_t)(((t + 1) & 1) * TILE_BYTES);

        uint4 anext[2];
        float fnext = 0.f;
        if (t + 1 < NCHUNK) {
            const __half* src = xB + (t + 1)*KC;
            CP_ASYNC16(nbufo + dstB +  0, src);
            CP_ASYNC16(nbufo + dstB + 16, src + 8);
            CP_ASYNC16(nbufo + dstB + 32, src + 16);
            CP_ASYNC16(nbufo + dstB + 48, src + 24);
            CP_COMMIT();
            const __half* ea = eA + (t + 1)*KC;
            anext[0] = *(const uint4*)(ea);
            anext[1] = *(const uint4*)(ea + 8);
            float2 pn = gp[(t + 1)*NHQ];
            fnext = fexp(pn.x - m_g) * inv_s;
        }

        // convert+store A(t) into current buffer
        {
            const float f = fcur;
            #pragma unroll
            for (int u = 0; u < 2; u++) {
                uint32_t w[4] = {aregs[u].x, aregs[u].y, aregs[u].z, aregs[u].w};
                uint32_t o[4];
                #pragma unroll
                for (int j = 0; j < 4; j++) {
                    __half2 h = *reinterpret_cast<__half2*>(&w[j]);
                    float2 v = __half22float2(h);
                    __half2 rr = __floats2half2_rn(v.x * f, v.y * f);
                    o[j] = *reinterpret_cast<uint32_t*>(&rr);
                }
                *(uint4*)(sm3 + (bufo >> 1) + A_OFF + hqA*APITCH + l0A + u*8) =
                    make_uint4(o[0], o[1], o[2], o[3]);
            }
        }

        if (t + 1 < NCHUNK) CP_WAIT1(); else CP_WAIT0();
        __syncthreads();

        // ---- MMA(t) ----
        #pragma unroll
        for (int ks = 0; ks < 4; ks++) {
            uint32_t a0[4], a1[4];
            ldm_x4(a0, bufo + addrA0 + 2u*(uint32_t)(16*ks));
            ldm_x4(a1, bufo + addrA0 + 2u*(uint32_t)(16*APITCH + 16*ks));
            #pragma unroll
            for (int jj = 0; jj < 4; jj++) {
                uint32_t bfr[4];
                ldm_x4(bfr, bufo + addrB0 + 2u*(uint32_t)(16*jj*APITCH + 16*ks));
                mma16816(acc[0][2*jj],   a0, bfr);
                mma16816(acc[0][2*jj+1], a0, bfr + 2);
                mma16816(acc[1][2*jj],   a1, bfr);
                mma16816(acc[1][2*jj+1], a1, bfr + 2);
            }
        }
        __syncthreads();

        aregs[0] = anext[0]; aregs[1] = anext[1];
        fcur = fnext;
    }

    // ---- epilogue: write P partial ----
    float* pp = g_Ppart + (((size_t)split*Bn + b)*NHQ)*Cn;
    #pragma unroll
    for (int i = 0; i < 2; i++) {
        const int row = mw*32 + i*16 + (lane >> 2);
        #pragma unroll
        for (int j = 0; j < 8; j++) {
            const int col = nw*64 + j*8 + (lane & 3)*2;
            *(float2*)(pp + (size_t)row*Cn + col)     = make_float2(acc[i][j][0], acc[i][j][1]);
            *(float2*)(pp + (size_t)(row+8)*Cn + col) = make_float2(acc[i][j][2], acc[i][j][3]);
        }
    }
}

// ---------------- K4a: reduce P partials, A = P @ val_w^T (per head) + val_b ----------------
__global__ void k4a(const float* __restrict__ val_w, const float* __restrict__ val_b)
{
    extern __shared__ float sm[];
    float* vw = sm;             // [32][VWP]
    float* ps = sm + 32*VWP;    // [16][256]
    const int h = blockIdx.x, b = blockIdx.y;
    const int tid = threadIdx.x;

    for (int i = tid*4; i < 32*Cn; i += 256*4) {
        int r = i >> 8, c = i & 255;
        float4 v = *(const float4*)&val_w[(size_t)(h*32 + r)*Cn + c];
        *(float4*)&vw[r*VWP + c] = v;
    }
    for (int i = tid*4; i < Qn*Cn; i += 256*4) {
        int q = i >> 8, c = i & 255;
        int hq = h*Qn + q;
        float4 s0 = *(const float4*)&g_Ppart[(((size_t)0*Bn + b)*NHQ + hq)*Cn + c];
        float4 s1 = *(const float4*)&g_Ppart[(((size_t)1*Bn + b)*NHQ + hq)*Cn + c];
        *(float4*)&ps[i] = make_float4(s0.x + s1.x, s0.y + s1.y, s0.z + s1.z, s0.w + s1.w);
    }
    __syncthreads();

    for (int o = tid; o < Qn*32; o += 256) {
        int q = o >> 5, d = o & 31;
        float a = val_b[h*32 + d];
        #pragma unroll 8
        for (int c = 0; c < Cn; c += 4) {
            float4 pv = *(const float4*)&ps[q*Cn + c];
            float4 wv = *(const float4*)&vw[d*VWP + c];
            a = fmaf(pv.x, wv.x, a);
            a = fmaf(pv.y, wv.y, a);
            a = fmaf(pv.z, wv.z, a);
            a = fmaf(pv.w, wv.w, a);
        }
        g_A[b*4096 + (h*Qn + q)*32 + d] = a;
    }
}

// ---------------- K4b: out = A @ fin_w^T + fin_b ----------------
__global__ void kinit(float* __restrict__ out, const float* __restrict__ fin_b)
{
    out[blockIdx.x*FHn + threadIdx.x] = fin_b[threadIdx.x];
}

__global__ void k4b(const float* __restrict__ fin_w, float* __restrict__ out)
{
    __shared__ float At[64*65];
    __shared__ float Wt[32*65];
    const int ft = blockIdx.x;
    const int js = blockIdx.y;
    const int tid = threadIdx.x;
    const int ty = tid >> 5, tx = tid & 31;
    const int f0 = ft*32;

    float acc[8];
    #pragma unroll
    for (int i = 0; i < 8; i++) acc[i] = 0.f;

    for (int sub = 0; sub < 8; sub++) {
        const int j0 = js*512 + sub*64;
        __syncthreads();
        for (int i = tid; i < 64*64; i += 256) {
            int bb = i >> 6, jj = i & 63;
            At[bb*65 + jj] = g_A[bb*4096 + j0 + jj];
        }
        for (int i = tid; i < 32*64; i += 256) {
            int r = i >> 6, jj = i & 63;
            Wt[r*65 + jj] = fin_w[(size_t)(f0 + r)*4096 + j0 + jj];
        }
        __syncthreads();
        #pragma unroll 8
        for (int j = 0; j < 64; j++) {
            float w = Wt[tx*65 + j];
            #pragma unroll
            for (int i = 0; i < 8; i++)
                acc[i] = fmaf(At[(ty*8 + i)*65 + j], w, acc[i]);
        }
    }
    #pragma unroll
    for (int i = 0; i < 8; i++)
        atomicAdd(&out[(ty*8 + i)*FHn + f0 + tx], acc[i]);
}

// ---------------- launch ----------------
extern "C" void kernel_launch(void* const* d_in, const int* in_sizes, int n_in,
                              void* d_out, int out_size)
{
    const float* x    = (const float*)d_in[0];
    const float* gam  = (const float*)d_in[1];
    const float* bet  = (const float*)d_in[2];
    const float* attw = (const float*)d_in[3];
    const float* valw = (const float*)d_in[4];
    const float* valb = (const float*)d_in[5];
    const float* finw = (const float*)d_in[6];
    const float* finb = (const float*)d_in[7];
    float* out = (float*)d_out;

    const int smem_k4a = (32*VWP + 16*Cn)*4;

    cudaFuncSetAttribute(k1,  cudaFuncAttributeMaxDynamicSharedMemorySize, K1_DYN);
    cudaFuncSetAttribute(k3,  cudaFuncAttributeMaxDynamicSharedMemorySize, K3_DYN);
    cudaFuncSetAttribute(k4a, cudaFuncAttributeMaxDynamicSharedMemorySize, smem_k4a);

    // launch-order shims: k1 is the 4th launch -> ncu capture shows the dominant kernel
    knop<<<1, 32>>>();
    knop<<<1, 32>>>();
    kinit<<<Bn, FHn>>>(out, finb);
    k1  <<<dim3(NT1, Bn),    512, K1_DYN >>>(x, gam, bet, attw);
    k2  <<<32, 256>>>();
    k3  <<<dim3(NSPLIT, Bn), 512, K3_DYN >>>();
    k4a <<<dim3(HEADSn, Bn), 256, smem_k4a>>>(valw, valb);
    k4b <<<dim3(16, 8), 256>>>(finw, out);
}

// round 12
// speedup vs baseline: 2.9517x; 1.0469x over previous
#include <cuda_runtime.h>
#include <cuda_fp16.h>
#include <cstdint>
#include <math.h>

#define Bn      64
#define Cn      256
#define Ln      4096
#define HEADSn  8
#define Qn      16
#define Dn      32
#define NHQ     128          // HEADS*Q
#define FHn     512
#define LT1     64           // K1 tile (l per block)
#define NT1     64           // number of K1 tiles (Ln/LT1)
#define NSPLIT  2
#define LSP     2048         // L per split (Ln/NSPLIT)
#define KC      64           // K3 l-chunk (== LT1)
#define NCHUNK  (LSP/KC)     // 32
#define APITCH  72           // fp16 elems per row (144B pitch -> ldmatrix conflict-free)
#define VWP     260          // k4a vw pitch (float4 conflict-free)
#define XHP     72           // k1 x_h smem pitch (halves)
#define GP      40           // k1 G smem pitch (halves; 80B stride, conflict-free)

// ---------------- scratch (device globals: no allocs allowed) ----------------
__device__ __half  g_E  [(size_t)Bn*NHQ*Ln];               // 67 MB  exp(logit - m_tile), fp16
__device__ __half  g_xn [(size_t)Bn*Cn*Ln];                // 134 MB LayerNormed x, fp16
__device__ float2  g_part[Bn*NT1*NHQ];                     // per-tile (max, sumexp)
__device__ float2  g_ms  [Bn*NHQ];                         // (max, 1/sum)
__device__ float   g_Ppart[(size_t)NSPLIT*Bn*NHQ*Cn];      // 17 MB partial P
__device__ float   g_A   [Bn*NHQ*Dn];                      // Aflat [B,4096]

// ---------------- fast exp (no MUFU; pure FMA/ALU) ----------------
__device__ __forceinline__ float fexp(float x) {
    float y = x * 1.4426950408889634f;
    y = fmaxf(y, -120.0f);
    float fl = floorf(y);
    float f  = y - fl;                 // [0,1)
    float p = 1.5252733e-5f;
    p = fmaf(p, f, 1.5403530e-4f);
    p = fmaf(p, f, 1.3333558e-3f);
    p = fmaf(p, f, 9.6181291e-3f);
    p = fmaf(p, f, 5.5504109e-2f);
    p = fmaf(p, f, 2.4022651e-1f);
    p = fmaf(p, f, 6.9314718e-1f);
    p = fmaf(p, f, 1.0f);
    int i = (int)fl;
    return p * __int_as_float((i + 127) << 23);
}

// mma.sync m16n8k16 fp16 (row.col), fp32 accumulate — base-arch tensor path
__device__ __forceinline__ void mma16816(float* d, const uint32_t* a, const uint32_t* b) {
    asm volatile("mma.sync.aligned.m16n8k16.row.col.f32.f16.f16.f32 "
        "{%0,%1,%2,%3}, {%4,%5,%6,%7}, {%8,%9}, {%0,%1,%2,%3};"
        : "+f"(d[0]), "+f"(d[1]), "+f"(d[2]), "+f"(d[3])
        : "r"(a[0]), "r"(a[1]), "r"(a[2]), "r"(a[3]), "r"(b[0]), "r"(b[1]));
}

__device__ __forceinline__ void ldm_x4(uint32_t* r, uint32_t addr) {
    asm volatile("ldmatrix.sync.aligned.m8n8.x4.shared.b16 {%0,%1,%2,%3}, [%4];"
        : "=r"(r[0]), "=r"(r[1]), "=r"(r[2]), "=r"(r[3]) : "r"(addr));
}
__device__ __forceinline__ void ldm_x4_trans(uint32_t* r, uint32_t addr) {
    asm volatile("ldmatrix.sync.aligned.m8n8.x4.trans.shared.b16 {%0,%1,%2,%3}, [%4];"
        : "=r"(r[0]), "=r"(r[1]), "=r"(r[2]), "=r"(r[3]) : "r"(addr));
}

#define CP_ASYNC16(dst, src) \
    asm volatile("cp.async.ca.shared.global [%0], [%1], 16;" :: "r"(dst), "l"(src) : "memory")
#define CP_COMMIT()  asm volatile("cp.async.commit_group;" ::: "memory")
#define CP_WAIT1()   asm volatile("cp.async.wait_group 1;" ::: "memory")
#define CP_WAIT0()   asm volatile("cp.async.wait_group 0;" ::: "memory")

// ---------------- no-op (launch-order shim so ncu's capture lands on k1) ----------------
__global__ void knop() {}

// ---------------- K1: LN stats + tensor-core logits + softmax partials + E/xn ----------------
// 512 threads, LT1=64. x staged fp16 in SMEM once; logits = HMMA(G, x_h) with
// LN absorbed into a per-(q,l) fp32 epilogue: logit = raw*rstd + (T - rstd*mu*S).
#define XH_BYTES (Cn*XHP*2)                 // 36864
#define RED_OFF  (XH_BYTES)
#define K1_DYN   (XH_BYTES + 512*16*2)      // + redS/redQ float4[512] each = 53248

__global__ __launch_bounds__(512, 2) void k1(const float* __restrict__ x,
                                             const float* __restrict__ gamma,
                                             const float* __restrict__ beta,
                                             const float* __restrict__ attw)
{
    extern __shared__ char sm1[];
    __half* x_h  = (__half*)sm1;                  // [256][XHP] halves (raw x fp16)
    float4* redS = (float4*)(sm1 + RED_OFF);      // [512]
    float4* redQ = redS + 512;                    // [512]

    __shared__ __half G_s[NHQ*GP];                // G = w*gamma, [hq][GP]
    __shared__ float  S_s[NHQ], T_s[NHQ];
    __shared__ float2 stats_s[LT1];               // (mu, rstd)
    __shared__ float  gms[Cn], bts[Cn];
    __shared__ float2 redms[HEADSn][2][Qn];       // cross-warp (m,s) exchange

    const int b = blockIdx.y, tile = blockIdx.x;
    const int tid  = threadIdx.x;
    const int lgrp = tid & 15;
    const int l4   = tile*LT1 + lgrp*4;

    for (int i = tid; i < Cn; i += 512) { gms[i] = gamma[i]; bts[i] = beta[i]; }
    __syncthreads();

    // ---- phase 0: G (fp16), S, T per hq ----
    if (tid < NHQ) {
        const int h = tid >> 4;
        const float* wp = attw + tid*Dn;
        float S = 0.f, T = 0.f;
        __half2* grow = (__half2*)&G_s[tid*GP];
        #pragma unroll
        for (int c2 = 0; c2 < 16; c2++) {
            float w0 = wp[2*c2], w1 = wp[2*c2+1];
            float G0 = w0 * gms[h*Dn + 2*c2];
            float G1 = w1 * gms[h*Dn + 2*c2 + 1];
            S += G0 + G1;
            T += w0*bts[h*Dn + 2*c2] + w1*bts[h*Dn + 2*c2 + 1];
            grow[c2] = __floats2half2_rn(G0, G1);
        }
        S_s[tid] = S; T_s[tid] = T;
    }

    const float* xb = x + (size_t)b*Cn*Ln;

    // ---- phase A: stats from fp32 x; stage raw x as fp16 into SMEM ----
    {
        const int cg = tid >> 4;                  // 32 groups of 8 channels
        float4 s4 = make_float4(0.f,0.f,0.f,0.f);
        float4 q4 = make_float4(0.f,0.f,0.f,0.f);
        #pragma unroll
        for (int cc = 0; cc < 8; cc++) {
            const int c = cg*8 + cc;
            float4 v = *(const float4*)&xb[(size_t)c*Ln + l4];
            s4.x += v.x; s4.y += v.y; s4.z += v.z; s4.w += v.w;
            q4.x = fmaf(v.x, v.x, q4.x); q4.y = fmaf(v.y, v.y, q4.y);
            q4.z = fmaf(v.z, v.z, q4.z); q4.w = fmaf(v.w, v.w, q4.w);
            __half2 a01 = __floats2half2_rn(v.x, v.y);
            __half2 a23 = __floats2half2_rn(v.z, v.w);
            *(uint2*)&x_h[c*XHP + lgrp*4] =
                make_uint2(*reinterpret_cast<uint32_t*>(&a01),
                           *reinterpret_cast<uint32_t*>(&a23));
        }
        redS[tid] = s4; redQ[tid] = q4;
        __syncthreads();
        if (tid < LT1) {
            const int lg = tid >> 2, li = tid & 3;
            float s = 0.f, q = 0.f;
            #pragma unroll
            for (int cg2 = 0; cg2 < 32; cg2++) {
                s += ((const float*)&redS[cg2*16 + lg])[li];
                q += ((const float*)&redQ[cg2*16 + lg])[li];
            }
            float mu  = s * (1.f/Cn);
            float var = q * (1.f/Cn) - mu*mu;
            stats_s[tid] = make_float2(mu, rsqrtf(var + 1e-6f));
        }
        __syncthreads();
    }

    // ---- phase B: xn = LN(x) from x_h -> g_xn (scalar, cheap) ----
    {
        const int cg = tid >> 4;
        float2 st0 = stats_s[lgrp*4+0], st1 = stats_s[lgrp*4+1];
        float2 st2 = stats_s[lgrp*4+2], st3 = stats_s[lgrp*4+3];
        __half* xnb = g_xn + (size_t)b*Cn*Ln;
        #pragma unroll
        for (int cc = 0; cc < 8; cc++) {
            const int c = cg*8 + cc;
            uint2 u = *(const uint2*)&x_h[c*XHP + lgrp*4];
            float2 f01 = __half22float2(*reinterpret_cast<__half2*>(&u.x));
            float2 f23 = __half22float2(*reinterpret_cast<__half2*>(&u.y));
            const float gg = gms[c], bb = bts[c];
            __half2 o01 = __floats2half2_rn((f01.x - st0.x)*st0.y*gg + bb,
                                            (f01.y - st1.x)*st1.y*gg + bb);
            __half2 o23 = __floats2half2_rn((f23.x - st2.x)*st2.y*gg + bb,
                                            (f23.y - st3.x)*st3.y*gg + bb);
            *(uint2*)&xnb[(size_t)c*Ln + l4] =
                make_uint2(*reinterpret_cast<uint32_t*>(&o01),
                           *reinterpret_cast<uint32_t*>(&o23));
        }
    }

    // ---- phase C: logits via mma.sync; softmax; E store ----
    {
        const int w    = tid >> 5, lane = tid & 31;
        const int h    = w >> 1, lh = w & 1;       // head, l-half (32 l)
        const int g    = lane >> 3, r = lane & 7;

        const uint32_t smbG = (uint32_t)__cvta_generic_to_shared(G_s);
        const uint32_t smbX = (uint32_t)__cvta_generic_to_shared(x_h);

        // A fragments: G[h] 16q x 32c, two k16 chunks
        uint32_t a[2][4];
        #pragma unroll
        for (int k = 0; k < 2; k++)
            ldm_x4(a[k], smbG + 2u*(uint32_t)((h*16 + ((g & 1) << 3) + r)*GP + k*16 + ((g >> 1) << 3)));

        float acc[4][4];
        #pragma unroll
        for (int j = 0; j < 4; j++)
            #pragma unroll
            for (int e = 0; e < 4; e++) acc[j][e] = 0.f;

        // B fragments: raw x_h [c][l], ldmatrix.trans (k-major source)
        #pragma unroll
        for (int k = 0; k < 2; k++) {
            #pragma unroll
            for (int lp = 0; lp < 2; lp++) {
                uint32_t bb[4];
                ldm_x4_trans(bb, smbX + 2u*(uint32_t)((h*Dn + k*16 + (lane & 15))*XHP
                                                      + lh*32 + lp*16 + ((lane >> 4) << 3)));
                mma16816(acc[lp*2+0], a[k], bb);
                mma16816(acc[lp*2+1], a[k], bb + 2);
            }
        }

        // epilogue: logit = raw*rstd + (T - rstd*mu*S); overwrite acc in place
        const int r1  = lane >> 2;            // q row
        const int c2  = (lane & 3)*2;
        const int hq1 = h*Qn + r1, hq2 = hq1 + 8;
        const float S1 = S_s[hq1], T1 = T_s[hq1];
        const float S2 = S_s[hq2], T2 = T_s[hq2];
        #pragma unroll
        for (int j = 0; j < 4; j++) {
            #pragma unroll
            for (int e = 0; e < 2; e++) {
                float2 st = stats_s[lh*32 + j*8 + c2 + e];
                float base = st.y * st.x;     // rstd*mu
                acc[j][e]   = fmaf(acc[j][e],   st.y, fmaf(-base, S1, T1));
                acc[j][2+e] = fmaf(acc[j][2+e], st.y, fmaf(-base, S2, T2));
            }
        }

        // max over 32 l (this half) per q-row
        float m1 = -1e30f, m2 = -1e30f;
        #pragma unroll
        for (int j = 0; j < 4; j++) {
            m1 = fmaxf(m1, fmaxf(acc[j][0], acc[j][1]));
            m2 = fmaxf(m2, fmaxf(acc[j][2], acc[j][3]));
        }
        m1 = fmaxf(m1, __shfl_xor_sync(0xFFFFFFFFu, m1, 1));
        m1 = fmaxf(m1, __shfl_xor_sync(0xFFFFFFFFu, m1, 2));
        m2 = fmaxf(m2, __shfl_xor_sync(0xFFFFFFFFu, m2, 1));
        m2 = fmaxf(m2, __shfl_xor_sync(0xFFFFFFFFu, m2, 2));

        // exp (overwrite acc) + sums
        float s1 = 0.f, s2 = 0.f;
        #pragma unroll
        for (int j = 0; j < 4; j++) {
            acc[j][0] = fexp(acc[j][0] - m1);
            acc[j][1] = fexp(acc[j][1] - m1);
            acc[j][2] = fexp(acc[j][2] - m2);
            acc[j][3] = fexp(acc[j][3] - m2);
            s1 += acc[j][0] + acc[j][1];
            s2 += acc[j][2] + acc[j][3];
        }
        s1 += __shfl_xor_sync(0xFFFFFFFFu, s1, 1);
        s1 += __shfl_xor_sync(0xFFFFFFFFu, s1, 2);
        s2 += __shfl_xor_sync(0xFFFFFFFFu, s2, 1);
        s2 += __shfl_xor_sync(0xFFFFFFFFu, s2, 2);

        if ((lane & 3) == 0) {
            redms[h][lh][r1]     = make_float2(m1, s1);
            redms[h][lh][r1 + 8] = make_float2(m2, s2);
        }
        __syncthreads();

        // combine the two 32-l halves -> tile (m, se)
        float2 o1 = redms[h][1 - lh][r1];
        float2 o2 = redms[h][1 - lh][r1 + 8];
        float mt1 = fmaxf(m1, o1.x), mt2 = fmaxf(m2, o2.x);
        float f1  = fexp(m1 - mt1),  f2  = fexp(m2 - mt2);
        if (lh == 0 && (lane & 3) == 0) {
            float se1 = s1*f1 + o1.y*fexp(o1.x - mt1);
            float se2 = s2*f2 + o2.y*fexp(o2.x - mt2);
            g_part[(b*NT1 + tile)*NHQ + hq1] = make_float2(mt1, se1);
            g_part[(b*NT1 + tile)*NHQ + hq2] = make_float2(mt2, se2);
        }

        // E = exp(logit - m_tile) fp16 stores
        __half* e1 = g_E + (size_t)(b*NHQ + hq1)*Ln + tile*LT1 + lh*32;
        __half* e2 = g_E + (size_t)(b*NHQ + hq2)*Ln + tile*LT1 + lh*32;
        #pragma unroll
        for (int j = 0; j < 4; j++) {
            __half2 v1 = __floats2half2_rn(acc[j][0]*f1, acc[j][1]*f1);
            __half2 v2 = __floats2half2_rn(acc[j][2]*f2, acc[j][3]*f2);
            *(__half2*)(e1 + j*8 + c2) = v1;
            *(__half2*)(e2 + j*8 + c2) = v2;
        }
    }
}

// ---------------- K2: merge softmax partials ----------------
__global__ void k2()
{
    const int idx = blockIdx.x*256 + threadIdx.x;
    if (idx >= Bn*NHQ) return;
    const int b = idx >> 7, hq = idx & 127;
    float m = -1e30f;
    for (int t = 0; t < NT1; t++) m = fmaxf(m, g_part[(b*NT1 + t)*NHQ + hq].x);
    float s = 0.f;
    for (int t = 0; t < NT1; t++) {
        float2 p = g_part[(b*NT1 + t)*NHQ + hq];
        s += p.y * fexp(p.x - m);
    }
    g_ms[idx] = make_float2(m, 1.f/s);
}

// ---------------- K3: P = Aw @ xn^T, pure fp16 GEMM, cp.async double-buffered ----------------
#define A_OFF  0
#define B_OFF  (128*APITCH)
#define TILE_HALVES (128*APITCH + 256*APITCH)   // 27648
#define TILE_BYTES  (TILE_HALVES*2)             // 55296
#define K3_DYN (2*TILE_BYTES)                   // 110592

__global__ __launch_bounds__(512, 1) void k3()
{
    extern __shared__ __half sm3[];
    __shared__ float2 ms_s[NHQ];

    const int split = blockIdx.x, b = blockIdx.y;
    const int tid  = threadIdx.x;
    const int wid  = tid >> 5, lane = tid & 31;
    const int mw   = wid >> 2, nw = wid & 3;

    for (int i = tid; i < NHQ; i += 512) ms_s[i] = g_ms[b*NHQ + i];

    const int hqA = tid >> 2, l0A = (tid & 3) * 16;   // A: 128 rows x 64
    const int cB  = tid >> 1, l0B = (tid & 1) * 32;   // B: 256 rows x 64
    __syncthreads();
    const float m_g = ms_s[hqA].x, inv_s = ms_s[hqA].y;

    const __half* eA = g_E  + (size_t)(b*NHQ + hqA)*Ln + split*LSP + l0A;
    const __half* xB = g_xn + ((size_t)b*Cn + cB)*Ln   + split*LSP + l0B;
    const float2* gp = g_part + (b*NT1 + split*(NT1/NSPLIT))*NHQ + hqA;

    const uint32_t smb = (uint32_t)__cvta_generic_to_shared(sm3);
    const uint32_t dstB = smb + 2u*(uint32_t)(B_OFF + cB*APITCH + l0B);

    const int g = lane >> 3, r = lane & 7;
    const uint32_t addrA0 = smb + 2u*((uint32_t)((mw*32 + ((g & 1) << 3) + r)*APITCH + ((g >> 1) << 3)));
    const uint32_t addrB0 = smb + 2u*((uint32_t)(B_OFF + (nw*64 + ((g >> 1) << 3) + r)*APITCH + ((g & 1) << 3)));

    float acc[2][8][4];
    #pragma unroll
    for (int i = 0; i < 2; i++)
        #pragma unroll
        for (int j = 0; j < 8; j++)
            #pragma unroll
            for (int e = 0; e < 4; e++) acc[i][j][e] = 0.f;

    {
        const __half* src = xB;
        CP_ASYNC16(dstB +  0, src);
        CP_ASYNC16(dstB + 16, src + 8);
        CP_ASYNC16(dstB + 32, src + 16);
        CP_ASYNC16(dstB + 48, src + 24);
        CP_COMMIT();
    }
    uint4 aregs[2];
    aregs[0] = *(const uint4*)(eA);
    aregs[1] = *(const uint4*)(eA + 8);
    float2 p0 = gp[0];
    float fcur = fexp(p0.x - m_g) * inv_s;

    for (int t = 0; t < NCHUNK; t++) {
        const uint32_t bufo = (uint32_t)((t & 1) * TILE_BYTES);
        const uint32_t nbufo = (uint32_t)(((t + 1) & 1) * TILE_BYTES);

        uint4 anext[2];
        float fnext = 0.f;
        if (t + 1 < NCHUNK) {
            const __half* src = xB + (t + 1)*KC;
            CP_ASYNC16(nbufo + dstB +  0, src);
            CP_ASYNC16(nbufo + dstB + 16, src + 8);
            CP_ASYNC16(nbufo + dstB + 32, src + 16);
            CP_ASYNC16(nbufo + dstB + 48, src + 24);
            CP_COMMIT();
            const __half* ea = eA + (t + 1)*KC;
            anext[0] = *(const uint4*)(ea);
            anext[1] = *(const uint4*)(ea + 8);
            float2 pn = gp[(t + 1)*NHQ];
            fnext = fexp(pn.x - m_g) * inv_s;
        }

        {
            const float f = fcur;
            #pragma unroll
            for (int u = 0; u < 2; u++) {
                uint32_t w[4] = {aregs[u].x, aregs[u].y, aregs[u].z, aregs[u].w};
                uint32_t o[4];
                #pragma unroll
                for (int j = 0; j < 4; j++) {
                    __half2 h = *reinterpret_cast<__half2*>(&w[j]);
                    float2 v = __half22float2(h);
                    __half2 rr = __floats2half2_rn(v.x * f, v.y * f);
                    o[j] = *reinterpret_cast<uint32_t*>(&rr);
                }
                *(uint4*)(sm3 + (bufo >> 1) + A_OFF + hqA*APITCH + l0A + u*8) =
                    make_uint4(o[0], o[1], o[2], o[3]);
            }
        }

        if (t + 1 < NCHUNK) CP_WAIT1(); else CP_WAIT0();
        __syncthreads();

        #pragma unroll
        for (int ks = 0; ks < 4; ks++) {
            uint32_t a0[4], a1[4];
            ldm_x4(a0, bufo + addrA0 + 2u*(uint32_t)(16*ks));
            ldm_x4(a1, bufo + addrA0 + 2u*(uint32_t)(16*APITCH + 16*ks));
            #pragma unroll
            for (int jj = 0; jj < 4; jj++) {
                uint32_t bfr[4];
                ldm_x4(bfr, bufo + addrB0 + 2u*(uint32_t)(16*jj*APITCH + 16*ks));
                mma16816(acc[0][2*jj],   a0, bfr);
                mma16816(acc[0][2*jj+1], a0, bfr + 2);
                mma16816(acc[1][2*jj],   a1, bfr);
                mma16816(acc[1][2*jj+1], a1, bfr + 2);
            }
        }
        __syncthreads();

        aregs[0] = anext[0]; aregs[1] = anext[1];
        fcur = fnext;
    }

    float* pp = g_Ppart + (((size_t)split*Bn + b)*NHQ)*Cn;
    #pragma unroll
    for (int i = 0; i < 2; i++) {
        const int row = mw*32 + i*16 + (lane >> 2);
        #pragma unroll
        for (int j = 0; j < 8; j++) {
            const int col = nw*64 + j*8 + (lane & 3)*2;
            *(float2*)(pp + (size_t)row*Cn + col)     = make_float2(acc[i][j][0], acc[i][j][1]);
            *(float2*)(pp + (size_t)(row+8)*Cn + col) = make_float2(acc[i][j][2], acc[i][j][3]);
        }
    }
}

// ---------------- K4a: reduce P partials, A = P @ val_w^T (per head) + val_b ----------------
__global__ void k4a(const float* __restrict__ val_w, const float* __restrict__ val_b)
{
    extern __shared__ float sm[];
    float* vw = sm;             // [32][VWP]
    float* ps = sm + 32*VWP;    // [16][256]
    const int h = blockIdx.x, b = blockIdx.y;
    const int tid = threadIdx.x;

    for (int i = tid*4; i < 32*Cn; i += 256*4) {
        int r = i >> 8, c = i & 255;
        float4 v = *(const float4*)&val_w[(size_t)(h*32 + r)*Cn + c];
        *(float4*)&vw[r*VWP + c] = v;
    }
    for (int i = tid*4; i < Qn*Cn; i += 256*4) {
        int q = i >> 8, c = i & 255;
        int hq = h*Qn + q;
        float4 s0 = *(const float4*)&g_Ppart[(((size_t)0*Bn + b)*NHQ + hq)*Cn + c];
        float4 s1 = *(const float4*)&g_Ppart[(((size_t)1*Bn + b)*NHQ + hq)*Cn + c];
        *(float4*)&ps[i] = make_float4(s0.x + s1.x, s0.y + s1.y, s0.z + s1.z, s0.w + s1.w);
    }
    __syncthreads();

    for (int o = tid; o < Qn*32; o += 256) {
        int q = o >> 5, d = o & 31;
        float a = val_b[h*32 + d];
        #pragma unroll 8
        for (int c = 0; c < Cn; c += 4) {
            float4 pv = *(const float4*)&ps[q*Cn + c];
            float4 wv = *(const float4*)&vw[d*VWP + c];
            a = fmaf(pv.x, wv.x, a);
            a = fmaf(pv.y, wv.y, a);
            a = fmaf(pv.z, wv.z, a);
            a = fmaf(pv.w, wv.w, a);
        }
        g_A[b*4096 + (h*Qn + q)*32 + d] = a;
    }
}

// ---------------- K4b: out = A @ fin_w^T + fin_b ----------------
__global__ void kinit(float* __restrict__ out, const float* __restrict__ fin_b)
{
    out[blockIdx.x*FHn + threadIdx.x] = fin_b[threadIdx.x];
}

__global__ void k4b(const float* __restrict__ fin_w, float* __restrict__ out)
{
    __shared__ float At[64*65];
    __shared__ float Wt[32*65];
    const int ft = blockIdx.x;
    const int js = blockIdx.y;
    const int tid = threadIdx.x;
    const int ty = tid >> 5, tx = tid & 31;
    const int f0 = ft*32;

    float acc[8];
    #pragma unroll
    for (int i = 0; i < 8; i++) acc[i] = 0.f;

    for (int sub = 0; sub < 8; sub++) {
        const int j0 = js*512 + sub*64;
        __syncthreads();
        for (int i = tid; i < 64*64; i += 256) {
            int bb = i >> 6, jj = i & 63;
            At[bb*65 + jj] = g_A[bb*4096 + j0 + jj];
        }
        for (int i = tid; i < 32*64; i += 256) {
            int r = i >> 6, jj = i & 63;
            Wt[r*65 + jj] = fin_w[(size_t)(f0 + r)*4096 + j0 + jj];
        }
        __syncthreads();
        #pragma unroll 8
        for (int j = 0; j < 64; j++) {
            float w = Wt[tx*65 + j];
            #pragma unroll
            for (int i = 0; i < 8; i++)
                acc[i] = fmaf(At[(ty*8 + i)*65 + j], w, acc[i]);
        }
    }
    #pragma unroll
    for (int i = 0; i < 8; i++)
        atomicAdd(&out[(ty*8 + i)*FHn + f0 + tx], acc[i]);
}

// ---------------- launch ----------------
extern "C" void kernel_launch(void* const* d_in, const int* in_sizes, int n_in,
                              void* d_out, int out_size)
{
    const float* x    = (const float*)d_in[0];
    const float* gam  = (const float*)d_in[1];
    const float* bet  = (const float*)d_in[2];
    const float* attw = (const float*)d_in[3];
    const float* valw = (const float*)d_in[4];
    const float* valb = (const float*)d_in[5];
    const float* finw = (const float*)d_in[6];
    const float* finb = (const float*)d_in[7];
    float* out = (float*)d_out;

    const int smem_k4a = (32*VWP + 16*Cn)*4;

    cudaFuncSetAttribute(k1,  cudaFuncAttributeMaxDynamicSharedMemorySize, K1_DYN);
    cudaFuncSetAttribute(k3,  cudaFuncAttributeMaxDynamicSharedMemorySize, K3_DYN);
    cudaFuncSetAttribute(k4a, cudaFuncAttributeMaxDynamicSharedMemorySize, smem_k4a);

    // launch-order shims: k1 is the 4th launch -> ncu capture shows the dominant kernel
    knop<<<1, 32>>>();
    knop<<<1, 32>>>();
    kinit<<<Bn, FHn>>>(out, finb);
    k1  <<<dim3(NT1, Bn),    512, K1_DYN >>>(x, gam, bet, attw);
    k2  <<<32, 256>>>();
    k3  <<<dim3(NSPLIT, Bn), 512, K3_DYN >>>();
    k4a <<<dim3(HEADSn, Bn), 256, smem_k4a>>>(valw, valb);
    k4b <<<dim3(16, 8), 256>>>(finw, out);
}